// round 4
// baseline (speedup 1.0000x reference)
#include <cuda_runtime.h>
#include <cuda_bf16.h>
#include <math.h>

// ---------------- problem constants ----------------
#define B_  128
#define L_  196
#define T_  32
#define TD  31          // T_dec
#define F_  512
#define H_  512
#define A_  512
#define E_  512
#define V_  10000

#define LOGITS_SZ (B_*TD*V_)   // 39,680,000
#define ALPHA_SZ  (B_*TD*L_)   // 777,728

// ---------------- scratch (device globals, no allocation) ----------------
__device__ float g_mean [B_*F_];
__device__ float g_h    [B_*H_];
__device__ float g_c    [B_*H_];
__device__ float g_hnew [B_*H_];
__device__ float g_emb  [B_*E_];
__device__ float g_hp   [B_*A_];
__device__ float g_gpre [B_*F_];
__device__ float g_gctx [B_*F_];
__device__ float g_gates[B_*4*H_];
__device__ float g_pre  [B_*E_];
__device__ float g_annproj[(size_t)B_*L_*A_];   // ~51 MB, loop-invariant

__device__ __forceinline__ float sigf(float x){ return 1.f/(1.f+expf(-x)); }

// ---------------- tiled fp32 GEMM core: C[128 x N] = A[128 x K] * W[N x K]^T ----
#define BM 128
#define BN 64
#define BK 16

struct Seg { const float* A; int lda; const float* W; int ldw; float* C; };

__device__ __forceinline__ void gemm_acc(
    const float* __restrict__ A, int lda,
    const float* __restrict__ W, int ldw, int nmax,
    int m0, int n0, int kstart, int kcount,
    float (&acc)[8][4], float* As, float* Ws)
{
    const int tid = threadIdx.x;
    for (int kt = 0; kt < kcount; kt += BK) {
        // load A tile: 128 x 16 (transposed into As[k][m])
        int f = tid;
        #pragma unroll
        for (int r = 0; r < 2; r++, f += 256) {
            int m  = f >> 2;
            int kk = (f & 3) << 2;
            float4 v = *reinterpret_cast<const float4*>(
                &A[(size_t)(m0 + m) * lda + kstart + kt + kk]);
            As[(kk+0)*BM + m] = v.x; As[(kk+1)*BM + m] = v.y;
            As[(kk+2)*BM + m] = v.z; As[(kk+3)*BM + m] = v.w;
        }
        // load W tile: 64 x 16 (transposed into Ws[k][n]); clamp row for ragged N
        {
            int n  = tid >> 2;
            int kk = (tid & 3) << 2;
            int nr = n0 + n; if (nr >= nmax) nr = nmax - 1;
            float4 w = *reinterpret_cast<const float4*>(
                &W[(size_t)nr * ldw + kstart + kt + kk]);
            Ws[(kk+0)*BN + n] = w.x; Ws[(kk+1)*BN + n] = w.y;
            Ws[(kk+2)*BN + n] = w.z; Ws[(kk+3)*BN + n] = w.w;
        }
        __syncthreads();
        const int tx = tid & 15, ty = tid >> 4;
        #pragma unroll
        for (int k = 0; k < BK; k++) {
            float a[8], bv[4];
            #pragma unroll
            for (int i = 0; i < 8; i++) a[i]  = As[k*BM + ty*8 + i];
            #pragma unroll
            for (int j = 0; j < 4; j++) bv[j] = Ws[k*BN + tx*4 + j];
            #pragma unroll
            for (int i = 0; i < 8; i++)
                #pragma unroll
                for (int j = 0; j < 4; j++)
                    acc[i][j] = fmaf(a[i], bv[j], acc[i][j]);
        }
        __syncthreads();
    }
}

// Multi-segment split-K GEMM, accumulating with atomics into bias-initialized C.
// grid: (N/BN, 1, nseg * (K/kchunk)); all segments share N, K, kchunk.
__global__ void __launch_bounds__(256) gemm_ms_atomic(
    Seg s0, Seg s1, Seg s2, int N, int K, int kchunk)
{
    __shared__ float As[BK*BM];
    __shared__ float Ws[BK*BN];
    const int zper = K / kchunk;
    const int z = blockIdx.z;
    const int si = z / zper;
    Seg s = (si == 0) ? s0 : ((si == 1) ? s1 : s2);
    const int kstart = (z % zper) * kchunk;
    const int n0 = blockIdx.x * BN;

    float acc[8][4];
    #pragma unroll
    for (int i = 0; i < 8; i++)
        #pragma unroll
        for (int j = 0; j < 4; j++) acc[i][j] = 0.f;

    gemm_acc(s.A, s.lda, s.W, s.ldw, N, 0, n0, kstart, kchunk, acc, As, Ws);

    const int tx = threadIdx.x & 15, ty = threadIdx.x >> 4;
    #pragma unroll
    for (int i = 0; i < 8; i++) {
        float* row = s.C + (size_t)(ty*8 + i) * N + n0 + tx*4;
        #pragma unroll
        for (int j = 0; j < 4; j++) atomicAdd(&row[j], acc[i][j]);
    }
}

// Direct-store GEMM with bias (used for the big one-time ann_proj).
// grid: (N/BN, M/BM)
__global__ void __launch_bounds__(256) gemm_store(
    const float* __restrict__ A, int lda,
    const float* __restrict__ W, int ldw,
    const float* __restrict__ bias,
    float* __restrict__ C, int ldc, int N, int K)
{
    __shared__ float As[BK*BM];
    __shared__ float Ws[BK*BN];
    const int n0 = blockIdx.x * BN;
    const int m0 = blockIdx.y * BM;

    float acc[8][4];
    #pragma unroll
    for (int i = 0; i < 8; i++)
        #pragma unroll
        for (int j = 0; j < 4; j++) acc[i][j] = 0.f;

    gemm_acc(A, lda, W, ldw, N, m0, n0, 0, K, acc, As, Ws);

    const int tx = threadIdx.x & 15, ty = threadIdx.x >> 4;
    #pragma unroll
    for (int i = 0; i < 8; i++) {
        int n = n0 + tx*4;
        float4 v;
        v.x = acc[i][0] + bias[n+0];
        v.y = acc[i][1] + bias[n+1];
        v.z = acc[i][2] + bias[n+2];
        v.w = acc[i][3] + bias[n+3];
        *reinterpret_cast<float4*>(&C[(size_t)(m0 + ty*8 + i)*ldc + n]) = v;
    }
}

// Logits GEMM: out[(b*TD+t)*V + n] = act ? pre@W_out^T + b_out : 0
// grid: (ceil(V/BN))
__global__ void __launch_bounds__(256) klogits(
    const float* __restrict__ pre,
    const float* __restrict__ Wout,
    const float* __restrict__ bout,
    const int*   __restrict__ lengths,
    int t, float* __restrict__ out)
{
    __shared__ float As[BK*BM];
    __shared__ float Ws[BK*BN];
    const int n0 = blockIdx.x * BN;

    float acc[8][4];
    #pragma unroll
    for (int i = 0; i < 8; i++)
        #pragma unroll
        for (int j = 0; j < 4; j++) acc[i][j] = 0.f;

    gemm_acc(pre, E_, Wout, E_, V_, 0, n0, 0, E_, acc, As, Ws);

    const int tx = threadIdx.x & 15, ty = threadIdx.x >> 4;
    #pragma unroll
    for (int i = 0; i < 8; i++) {
        const int b = ty*8 + i;
        int dl = lengths[b] - 1; if (dl < 1) dl = 1;
        const bool act = dl > t;
        float* row = out + ((size_t)b*TD + t) * V_;
        #pragma unroll
        for (int j = 0; j < 4; j++) {
            int n = n0 + tx*4 + j;
            if (n < V_) row[n] = act ? (acc[i][j] + bout[n]) : 0.f;
        }
    }
}

// ---------------- small kernels ----------------

// mean over L + bias-init of h0/c0 buffers
__global__ void kmean(const float* __restrict__ ann,
                      const float* __restrict__ b_init_h,
                      const float* __restrict__ b_init_c)
{
    const int b = blockIdx.x;
    for (int f = threadIdx.x; f < F_; f += blockDim.x) {
        const float* p = ann + (size_t)b*L_*F_ + f;
        float s = 0.f;
        #pragma unroll 4
        for (int l = 0; l < L_; l++) s += p[(size_t)l*F_];
        g_mean[b*F_ + f] = s * (1.f/196.f);
        g_h[b*H_ + f] = b_init_h[f];
        g_c[b*H_ + f] = b_init_c[f];
    }
}

__global__ void ktanh(float* __restrict__ p, int n) {
    for (int i = blockIdx.x*blockDim.x + threadIdx.x; i < n; i += gridDim.x*blockDim.x)
        p[i] = tanhf(p[i]);
}

// per-step prep: embedding gather + bias-init of accumulation buffers
__global__ void kprep(const int* __restrict__ captions,
                      const float* __restrict__ E_emb,
                      const float* __restrict__ b_att_h,
                      const float* __restrict__ b_beta,
                      const float* __restrict__ b_ih,
                      const float* __restrict__ b_hh, int t)
{
    const int b = blockIdx.x, j = threadIdx.x;   // 512 threads
    const int tok = captions[b*T_ + t];
    g_emb [b*E_ + j] = E_emb[(size_t)tok*E_ + j];
    g_hp  [b*A_ + j] = b_att_h[j];
    g_gpre[b*F_ + j] = b_beta[j];
    g_pre [b*E_ + j] = 0.f;
    #pragma unroll
    for (int q = 0; q < 4; q++)
        g_gates[b*2048 + q*512 + j] = b_ih[q*512 + j] + b_hh[q*512 + j];
}

// fused attention: scores -> softmax -> context -> gated context; block per b
__global__ void __launch_bounds__(256) kattn(
    const float* __restrict__ ann,
    const float* __restrict__ w_att_v,
    const float* __restrict__ b_att_v,
    const int*   __restrict__ lengths,
    int t, float* __restrict__ alphas_out)
{
    __shared__ float hp_s[A_];
    __shared__ float wv_s[A_];
    __shared__ float sc[L_];
    __shared__ float red[8];
    __shared__ float sval[2];

    const int b = blockIdx.x;
    const int tid = threadIdx.x;
    const int w = tid >> 5, lane = tid & 31;

    for (int i = tid; i < A_; i += 256) {
        hp_s[i] = g_hp[b*A_ + i];
        wv_s[i] = w_att_v[i];
    }
    __syncthreads();

    const float bv = b_att_v[0];
    const float* ap = g_annproj + (size_t)b*L_*A_;

    // scores: warp per l
    for (int l = w; l < L_; l += 8) {
        const float* row = ap + (size_t)l*A_;
        float s = 0.f;
        #pragma unroll 4
        for (int a = lane; a < A_; a += 32)
            s += fmaxf(row[a] + hp_s[a], 0.f) * wv_s[a];
        #pragma unroll
        for (int o = 16; o; o >>= 1) s += __shfl_down_sync(0xffffffffu, s, o);
        if (lane == 0) sc[l] = s + bv;
    }
    __syncthreads();

    // softmax over 196
    float mx = -1e30f;
    for (int i = tid; i < L_; i += 256) mx = fmaxf(mx, sc[i]);
    #pragma unroll
    for (int o = 16; o; o >>= 1) mx = fmaxf(mx, __shfl_xor_sync(0xffffffffu, mx, o));
    if (lane == 0) red[w] = mx;
    __syncthreads();
    if (tid == 0) {
        float m = red[0];
        #pragma unroll
        for (int i = 1; i < 8; i++) m = fmaxf(m, red[i]);
        sval[0] = m;
    }
    __syncthreads();
    mx = sval[0];

    float ss = 0.f;
    for (int i = tid; i < L_; i += 256) {
        float e = expf(sc[i] - mx);
        sc[i] = e;
        ss += e;
    }
    #pragma unroll
    for (int o = 16; o; o >>= 1) ss += __shfl_xor_sync(0xffffffffu, ss, o);
    if (lane == 0) red[w] = ss;
    __syncthreads();
    if (tid == 0) {
        float s2 = 0.f;
        #pragma unroll
        for (int i = 0; i < 8; i++) s2 += red[i];
        sval[1] = s2;
    }
    __syncthreads();
    const float inv = 1.f / sval[1];

    int dl = lengths[b] - 1; if (dl < 1) dl = 1;
    const bool act = dl > t;
    for (int i = tid; i < L_; i += 256) {
        float a = sc[i] * inv;
        sc[i] = a;
        alphas_out[((size_t)b*TD + t)*L_ + i] = act ? a : 0.f;
    }
    __syncthreads();

    // context + gated context
    const float* an = ann + (size_t)b*L_*F_;
    for (int f = tid; f < F_; f += 256) {
        float acc = 0.f;
        #pragma unroll 4
        for (int l = 0; l < L_; l++)
            acc = fmaf(sc[l], an[(size_t)l*F_ + f], acc);
        const float gate = sigf(g_gpre[b*F_ + f]);
        g_gctx[b*F_ + f] = gate * acc;
    }
}

// LSTM pointwise + masked carry commit
__global__ void klstm(const int* __restrict__ lengths, int t) {
    const int b = blockIdx.x, j = threadIdx.x;   // 512 threads
    const float* g = g_gates + b*2048;
    const float i_ = g[j], f_ = g[512 + j], gg = g[1024 + j], o_ = g[1536 + j];
    const float c_old = g_c[b*H_ + j];
    const float cn = sigf(f_) * c_old + sigf(i_) * tanhf(gg);
    const float hn = sigf(o_) * tanhf(cn);
    g_hnew[b*H_ + j] = hn;
    int dl = lengths[b] - 1; if (dl < 1) dl = 1;
    if (dl > t) {
        g_c[b*H_ + j] = cn;
        g_h[b*H_ + j] = hn;
    }
}

__global__ void kdeclen(const int* __restrict__ lengths, float* __restrict__ out) {
    const int b = threadIdx.x;
    if (b < B_) {
        int dl = lengths[b] - 1; if (dl < 1) dl = 1;
        out[(size_t)LOGITS_SZ + ALPHA_SZ + b] = (float)dl;
    }
}

// ---------------- host launcher ----------------
static float* symaddr(const void* s) {
    void* p = nullptr;
    cudaGetSymbolAddress(&p, s);
    return (float*)p;
}

extern "C" void kernel_launch(void* const* d_in, const int* in_sizes, int n_in,
                              void* d_out, int out_size)
{
    const float* ann      = (const float*)d_in[0];
    const int*   captions = (const int*)  d_in[1];
    const int*   lengths  = (const int*)  d_in[2];
    const float* E_emb    = (const float*)d_in[3];
    const float* W_init_h = (const float*)d_in[4];
    const float* b_init_h = (const float*)d_in[5];
    const float* W_init_c = (const float*)d_in[6];
    const float* b_init_c = (const float*)d_in[7];
    const float* W_att_f  = (const float*)d_in[8];
    const float* b_att_f  = (const float*)d_in[9];
    const float* W_att_h  = (const float*)d_in[10];
    const float* b_att_h  = (const float*)d_in[11];
    const float* w_att_v  = (const float*)d_in[12];
    const float* b_att_v  = (const float*)d_in[13];
    const float* W_beta   = (const float*)d_in[14];
    const float* b_beta   = (const float*)d_in[15];
    const float* W_ih     = (const float*)d_in[16];
    const float* W_hh     = (const float*)d_in[17];
    const float* b_ih     = (const float*)d_in[18];
    const float* b_hh     = (const float*)d_in[19];
    const float* W_y      = (const float*)d_in[20];
    const float* W_h      = (const float*)d_in[21];
    const float* W_z      = (const float*)d_in[22];
    const float* W_out    = (const float*)d_in[23];
    const float* b_out    = (const float*)d_in[24];

    float* out = (float*)d_out;

    float* p_mean    = symaddr(g_mean);
    float* p_h       = symaddr(g_h);
    float* p_c       = symaddr(g_c);
    float* p_hnew    = symaddr(g_hnew);
    float* p_emb     = symaddr(g_emb);
    float* p_hp      = symaddr(g_hp);
    float* p_gpre    = symaddr(g_gpre);
    float* p_gctx    = symaddr(g_gctx);
    float* p_gates   = symaddr(g_gates);
    float* p_pre     = symaddr(g_pre);
    float* p_annproj = symaddr(g_annproj);

    // ---- prologue: mean, h0/c0, ann_proj (loop-invariant) ----
    kmean<<<B_, 256>>>(ann, b_init_h, b_init_c);

    {
        Seg s0 = { p_mean, F_, W_init_h, F_, p_h };
        Seg s1 = { p_mean, F_, W_init_c, F_, p_c };
        gemm_ms_atomic<<<dim3(H_/BN, 1, 2*4), 256>>>(s0, s1, s1, H_, F_, 128);
    }
    ktanh<<<64, 256>>>(p_h, B_*H_);
    ktanh<<<64, 256>>>(p_c, B_*H_);

    gemm_store<<<dim3(A_/BN, (B_*L_)/BM), 256>>>(
        ann, F_, W_att_f, F_, b_att_f, p_annproj, A_, A_, F_);

    // ---- decode loop ----
    for (int t = 0; t < TD; t++) {
        kprep<<<B_, 512>>>(captions, E_emb, b_att_h, b_beta, b_ih, b_hh, t);

        {   // hp = h @ W_att_h^T ; gatepre = h @ W_beta^T
            Seg s0 = { p_h, H_, W_att_h, H_, p_hp   };
            Seg s1 = { p_h, H_, W_beta,  H_, p_gpre };
            gemm_ms_atomic<<<dim3(A_/BN, 1, 2*4), 256>>>(s0, s1, s1, A_, H_, 128);
        }

        kattn<<<B_, 256>>>(ann, w_att_v, b_att_v, lengths, t, out + LOGITS_SZ);

        {   // gates = emb@W_ih[:, :512]^T + gctx@W_ih[:, 512:]^T + h@W_hh^T
            Seg s0 = { p_emb,  E_, W_ih,       1024, p_gates };
            Seg s1 = { p_gctx, F_, W_ih + 512, 1024, p_gates };
            Seg s2 = { p_h,    H_, W_hh,       H_,   p_gates };
            gemm_ms_atomic<<<dim3(2048/BN, 1, 3*4), 256>>>(s0, s1, s2, 2048, 512, 128);
        }

        klstm<<<B_, 512>>>(lengths, t);

        {   // pre = emb@W_y^T + h_new@W_h^T + gctx@W_z^T
            Seg s0 = { p_emb,  E_, W_y, E_, p_pre };
            Seg s1 = { p_hnew, H_, W_h, H_, p_pre };
            Seg s2 = { p_gctx, F_, W_z, F_, p_pre };
            gemm_ms_atomic<<<dim3(E_/BN, 1, 3*4), 256>>>(s0, s1, s2, E_, 512, 128);
        }
        ktanh<<<64, 256>>>(p_pre, B_*E_);

        klogits<<<(V_ + BN - 1)/BN, 256>>>(p_pre, W_out, b_out, lengths, t, out);
    }

    kdeclen<<<1, 128>>>(lengths, out);
}

// round 5
// speedup vs baseline: 1.1825x; 1.1825x over previous
#include <cuda_runtime.h>
#include <cuda_bf16.h>
#include <math.h>

typedef unsigned long long ull;

// ---------------- problem constants ----------------
#define B_  128
#define L_  196
#define T_  32
#define TD  31          // T_dec
#define F_  512
#define H_  512
#define A_  512
#define E_  512
#define V_  10000

#define LOGITS_SZ (B_*TD*V_)   // 39,680,000
#define ALPHA_SZ  (B_*TD*L_)   // 777,728

// ---------------- scratch (device globals) ----------------
__device__ float g_mean [B_*F_];
__device__ float g_h    [B_*H_];
__device__ float g_c    [B_*H_];
__device__ float g_hp   [B_*A_];
__device__ float g_gpre [B_*F_];
__device__ float g_gates[B_*4*H_];
// double-buffered (software pipeline, pre/logits shifted by one step)
__device__ float g_emb [2][B_*E_];
__device__ float g_gctx[2][B_*F_];
__device__ float g_hnew[2][B_*H_];
__device__ float g_pre [2][B_*E_];
__device__ float g_annproj[(size_t)B_*L_*A_];   // ~51 MB, loop-invariant

__device__ __forceinline__ float sigf(float x){ return 1.f/(1.f+expf(-x)); }
__device__ __forceinline__ float lo32(ull v){ return __uint_as_float((unsigned)v); }
__device__ __forceinline__ float hi32(ull v){ return __uint_as_float((unsigned)(v>>32)); }

// packed fp32x2 FMA (sm_100+; doubles fp32 FMA throughput vs scalar FFMA)
#define FMA2(acc,a,b) asm("fma.rn.f32x2 %0, %1, %2, %0;" : "+l"(acc) : "l"(a), "l"(b))
#define PACK2(d,s)    asm("mov.b64 %0, {%1, %1};"        : "=l"(d)   : "r"(s))

// ---------------- GEMM core: C[128 x N] = A[128 x K] * W[N x K]^T --------
// acc[p][j] holds packed rows {ty*8+2p, ty*8+2p+1} at column n0+tx*4+j.
#define BM 128
#define BN 64
#define BK 16

__device__ __forceinline__ void dev_gemm(
    const float* __restrict__ A, int lda,
    const float* __restrict__ W, int ldw, int nmax,
    int m0, int n0, int kstart, int kcount,
    ull (&acc)[4][4], float* As, float* Ws)
{
    const int tid = threadIdx.x;
    for (int kt = 0; kt < kcount; kt += BK) {
        // A tile 128x16 -> As[k][m]
        int f = tid;
        #pragma unroll
        for (int r = 0; r < 2; r++, f += 256) {
            int m  = f >> 2;
            int kk = (f & 3) << 2;
            float4 v = *reinterpret_cast<const float4*>(
                &A[(size_t)(m0 + m) * lda + kstart + kt + kk]);
            As[(kk+0)*BM + m] = v.x; As[(kk+1)*BM + m] = v.y;
            As[(kk+2)*BM + m] = v.z; As[(kk+3)*BM + m] = v.w;
        }
        // W tile 64x16 -> Ws[k][n] (row clamp for ragged N)
        {
            int n  = tid >> 2;
            int kk = (tid & 3) << 2;
            int nr = n0 + n; if (nr >= nmax) nr = nmax - 1;
            float4 w = *reinterpret_cast<const float4*>(
                &W[(size_t)nr * ldw + kstart + kt + kk]);
            Ws[(kk+0)*BN + n] = w.x; Ws[(kk+1)*BN + n] = w.y;
            Ws[(kk+2)*BN + n] = w.z; Ws[(kk+3)*BN + n] = w.w;
        }
        __syncthreads();
        const int tx = tid & 15, ty = tid >> 4;
        #pragma unroll
        for (int k = 0; k < BK; k++) {
            const ull* a64 = reinterpret_cast<const ull*>(As + k*BM + ty*8);
            ull a0 = a64[0], a1 = a64[1], a2 = a64[2], a3 = a64[3];
            const unsigned* bw = reinterpret_cast<const unsigned*>(Ws + k*BN + tx*4);
            unsigned u0 = bw[0], u1 = bw[1], u2 = bw[2], u3 = bw[3];
            ull b0, b1, b2, b3;
            PACK2(b0,u0); PACK2(b1,u1); PACK2(b2,u2); PACK2(b3,u3);
            FMA2(acc[0][0],a0,b0); FMA2(acc[0][1],a0,b1); FMA2(acc[0][2],a0,b2); FMA2(acc[0][3],a0,b3);
            FMA2(acc[1][0],a1,b0); FMA2(acc[1][1],a1,b1); FMA2(acc[1][2],a1,b2); FMA2(acc[1][3],a1,b3);
            FMA2(acc[2][0],a2,b0); FMA2(acc[2][1],a2,b1); FMA2(acc[2][2],a2,b2); FMA2(acc[2][3],a2,b3);
            FMA2(acc[3][0],a3,b0); FMA2(acc[3][1],a3,b1); FMA2(acc[3][2],a3,b2); FMA2(acc[3][3],a3,b3);
        }
        __syncthreads();
    }
}

__device__ __forceinline__ void atomic_epilogue(
    ull (&acc)[4][4], float* __restrict__ C, int N, int n0)
{
    const int tx = threadIdx.x & 15, ty = threadIdx.x >> 4;
    #pragma unroll
    for (int p = 0; p < 4; p++) {
        float* R0 = C + (size_t)(ty*8 + 2*p) * N + n0 + tx*4;
        float* R1 = R0 + N;
        #pragma unroll
        for (int j = 0; j < 4; j++) {
            atomicAdd(&R0[j], lo32(acc[p][j]));
            atomicAdd(&R1[j], hi32(acc[p][j]));
        }
    }
}

// ---------------- prologue kernels ----------------

// mean over L + bias-init h0/c0
__global__ void __launch_bounds__(256) kmean(const float* __restrict__ ann,
                      const float* __restrict__ b_init_h,
                      const float* __restrict__ b_init_c)
{
    const int b = blockIdx.x;
    for (int f = threadIdx.x; f < F_; f += blockDim.x) {
        const float* p = ann + (size_t)b*L_*F_ + f;
        float s = 0.f;
        #pragma unroll 4
        for (int l = 0; l < L_; l++) s += p[(size_t)l*F_];
        g_mean[b*F_ + f] = s * (1.f/196.f);
        g_h[b*H_ + f] = b_init_h[f];
        g_c[b*H_ + f] = b_init_c[f];
    }
}

// h0/c0 GEMMs (split-K atomic): grid 64
__global__ void __launch_bounds__(256) kInit(const float* __restrict__ W_init_h,
                                             const float* __restrict__ W_init_c)
{
    __shared__ __align__(16) float As[BK*BM];
    __shared__ __align__(16) float Ws[BK*BN];
    const int z = blockIdx.x >> 3;          // 0..7
    const int seg = z >> 2;
    const int kstart = (z & 3) * 128;
    const int n0 = (blockIdx.x & 7) * BN;
    const float* W = seg ? W_init_c : W_init_h;
    float* C = seg ? g_c : g_h;
    ull acc[4][4];
    #pragma unroll
    for (int p = 0; p < 4; p++)
        #pragma unroll
        for (int j = 0; j < 4; j++) acc[p][j] = 0ull;
    dev_gemm(g_mean, F_, W, F_, H_, 0, n0, kstart, 128, acc, As, Ws);
    atomic_epilogue(acc, C, H_, n0);
}

__global__ void __launch_bounds__(256) kTanhHC() {
    for (int i = blockIdx.x*256 + threadIdx.x; i < B_*H_; i += 64*256) {
        g_h[i] = tanhf(g_h[i]);
        g_c[i] = tanhf(g_c[i]);
    }
}

// ann_proj = ann @ W_att_f^T + b_att_f, grid (8, 196)
__global__ void __launch_bounds__(256) kAnnProj(
    const float* __restrict__ ann,
    const float* __restrict__ W_att_f,
    const float* __restrict__ b_att_f)
{
    __shared__ __align__(16) float As[BK*BM];
    __shared__ __align__(16) float Ws[BK*BN];
    const int n0 = blockIdx.x * BN;
    const int m0 = blockIdx.y * BM;
    ull acc[4][4];
    #pragma unroll
    for (int p = 0; p < 4; p++)
        #pragma unroll
        for (int j = 0; j < 4; j++) acc[p][j] = 0ull;
    dev_gemm(ann, F_, W_att_f, F_, A_, m0, n0, 0, F_, acc, As, Ws);
    const int tx = threadIdx.x & 15, ty = threadIdx.x >> 4;
    const int n = n0 + tx*4;
    float4 bb = *reinterpret_cast<const float4*>(&b_att_f[n]);
    #pragma unroll
    for (int p = 0; p < 4; p++) {
        float* R0 = g_annproj + (size_t)(m0 + ty*8 + 2*p) * A_ + n;
        float* R1 = R0 + A_;
        float4 v0, v1;
        v0.x = lo32(acc[p][0]) + bb.x; v0.y = lo32(acc[p][1]) + bb.y;
        v0.z = lo32(acc[p][2]) + bb.z; v0.w = lo32(acc[p][3]) + bb.w;
        v1.x = hi32(acc[p][0]) + bb.x; v1.y = hi32(acc[p][1]) + bb.y;
        v1.z = hi32(acc[p][2]) + bb.z; v1.w = hi32(acc[p][3]) + bb.w;
        *reinterpret_cast<float4*>(R0) = v0;
        *reinterpret_cast<float4*>(R1) = v1;
    }
}

// ---------------- pipelined step kernels ----------------

// kA: pre-gemm(t-1)  [blocks 0..95]  ∪  prep(t) [blocks 96..223]
__global__ void __launch_bounds__(256) kA(int t,
    const int* __restrict__ captions, const float* __restrict__ E_emb,
    const float* __restrict__ b_att_h, const float* __restrict__ b_beta,
    const float* __restrict__ b_ih, const float* __restrict__ b_hh,
    const float* __restrict__ W_y, const float* __restrict__ W_h,
    const float* __restrict__ W_z)
{
    __shared__ __align__(16) float As[BK*BM];
    __shared__ __align__(16) float Ws[BK*BN];
    if (blockIdx.x < 96) {
        if (t == 0) return;
        const int s = (t-1) & 1;
        const int z = blockIdx.x >> 3;       // 0..11
        const int seg = z >> 2;
        const int kstart = (z & 3) * 128;
        const int n0 = (blockIdx.x & 7) * BN;
        const float *A, *W;
        if      (seg == 0) { A = g_emb[s];  W = W_y; }
        else if (seg == 1) { A = g_hnew[s]; W = W_h; }
        else               { A = g_gctx[s]; W = W_z; }
        ull acc[4][4];
        #pragma unroll
        for (int p = 0; p < 4; p++)
            #pragma unroll
            for (int j = 0; j < 4; j++) acc[p][j] = 0ull;
        dev_gemm(A, 512, W, 512, E_, 0, n0, kstart, 128, acc, As, Ws);
        atomic_epilogue(acc, g_pre[s], E_, n0);
    } else {
        if (t > 30) return;
        const int b = blockIdx.x - 96;
        const int s = t & 1;
        const int tok = captions[b*T_ + t];
        for (int j = threadIdx.x; j < 512; j += 256) {
            g_emb[s][b*512 + j] = E_emb[(size_t)tok*512 + j];
            g_hp  [b*512 + j] = b_att_h[j];
            g_gpre[b*512 + j] = b_beta[j];
            g_pre[s][b*512 + j] = 0.f;
            #pragma unroll
            for (int q = 0; q < 4; q++)
                g_gates[b*2048 + q*512 + j] = b_ih[q*512 + j] + b_hh[q*512 + j];
        }
    }
}

// kB: hp/gpre GEMMs(t) [blocks 0..127]  ∪  tanh(pre(t-1)) [blocks 128..191]
__global__ void __launch_bounds__(256) kB(int t,
    const float* __restrict__ W_att_h, const float* __restrict__ W_beta)
{
    __shared__ __align__(16) float As[BK*BM];
    __shared__ __align__(16) float Ws[BK*BN];
    if (blockIdx.x < 128) {
        if (t > 30) return;
        const int z = blockIdx.x >> 3;       // 0..15
        const int seg = z >> 3;
        const int kstart = (z & 7) * 64;
        const int n0 = (blockIdx.x & 7) * BN;
        const float* W = seg ? W_beta : W_att_h;
        float* C = seg ? g_gpre : g_hp;
        ull acc[4][4];
        #pragma unroll
        for (int p = 0; p < 4; p++)
            #pragma unroll
            for (int j = 0; j < 4; j++) acc[p][j] = 0ull;
        dev_gemm(g_h, H_, W, H_, A_, 0, n0, kstart, 64, acc, As, Ws);
        atomic_epilogue(acc, C, A_, n0);
    } else {
        if (t == 0) return;
        const int s = (t-1) & 1;
        for (int i = (blockIdx.x - 128)*256 + threadIdx.x; i < B_*E_; i += 64*256)
            g_pre[s][i] = tanhf(g_pre[s][i]);
    }
}

// fused attention(t): scores -> softmax -> context -> gated ctx; block per b
__global__ void __launch_bounds__(256) kattn(
    const float* __restrict__ ann,
    const float* __restrict__ w_att_v,
    const float* __restrict__ b_att_v,
    const int*   __restrict__ lengths,
    int t, float* __restrict__ alphas_out)
{
    __shared__ float hp_s[A_];
    __shared__ float wv_s[A_];
    __shared__ float sc[L_];
    __shared__ float red[8];
    __shared__ float sval[2];

    const int b = blockIdx.x;
    const int tid = threadIdx.x;
    const int w = tid >> 5, lane = tid & 31;
    const int s = t & 1;

    for (int i = tid; i < A_; i += 256) {
        hp_s[i] = g_hp[b*A_ + i];
        wv_s[i] = w_att_v[i];
    }
    __syncthreads();

    const float bv = b_att_v[0];
    const float* ap = g_annproj + (size_t)b*L_*A_;

    for (int l = w; l < L_; l += 8) {
        const float* row = ap + (size_t)l*A_;
        float sacc = 0.f;
        #pragma unroll 4
        for (int a = lane; a < A_; a += 32)
            sacc += fmaxf(row[a] + hp_s[a], 0.f) * wv_s[a];
        #pragma unroll
        for (int o = 16; o; o >>= 1) sacc += __shfl_down_sync(0xffffffffu, sacc, o);
        if (lane == 0) sc[l] = sacc + bv;
    }
    __syncthreads();

    float mx = -1e30f;
    for (int i = tid; i < L_; i += 256) mx = fmaxf(mx, sc[i]);
    #pragma unroll
    for (int o = 16; o; o >>= 1) mx = fmaxf(mx, __shfl_xor_sync(0xffffffffu, mx, o));
    if (lane == 0) red[w] = mx;
    __syncthreads();
    if (tid == 0) {
        float m = red[0];
        #pragma unroll
        for (int i = 1; i < 8; i++) m = fmaxf(m, red[i]);
        sval[0] = m;
    }
    __syncthreads();
    mx = sval[0];

    float ss = 0.f;
    for (int i = tid; i < L_; i += 256) {
        float e = expf(sc[i] - mx);
        sc[i] = e;
        ss += e;
    }
    #pragma unroll
    for (int o = 16; o; o >>= 1) ss += __shfl_xor_sync(0xffffffffu, ss, o);
    if (lane == 0) red[w] = ss;
    __syncthreads();
    if (tid == 0) {
        float s2 = 0.f;
        #pragma unroll
        for (int i = 0; i < 8; i++) s2 += red[i];
        sval[1] = s2;
    }
    __syncthreads();
    const float inv = 1.f / sval[1];

    int dl = lengths[b] - 1; if (dl < 1) dl = 1;
    const bool act = dl > t;
    for (int i = tid; i < L_; i += 256) {
        float a = sc[i] * inv;
        sc[i] = a;
        alphas_out[((size_t)b*TD + t)*L_ + i] = act ? a : 0.f;
    }
    __syncthreads();

    const float* an = ann + (size_t)b*L_*F_;
    for (int f = tid; f < F_; f += 256) {
        float acc = 0.f;
        #pragma unroll 4
        for (int l = 0; l < L_; l++)
            acc = fmaf(sc[l], an[(size_t)l*F_ + f], acc);
        const float gate = sigf(g_gpre[b*F_ + f]);
        g_gctx[s][b*F_ + f] = gate * acc;
    }
}

// kD: gates(t) [blocks 0..383]  ∪  logits(t-1) [blocks 384..540]
__global__ void __launch_bounds__(256) kD(int t,
    const float* __restrict__ W_ih, const float* __restrict__ W_hh,
    const float* __restrict__ W_out, const float* __restrict__ b_out,
    const int* __restrict__ lengths, float* __restrict__ out)
{
    __shared__ __align__(16) float As[BK*BM];
    __shared__ __align__(16) float Ws[BK*BN];
    if (blockIdx.x < 384) {
        if (t > 30) return;
        const int s = t & 1;
        const int z = blockIdx.x >> 5;       // 0..11
        const int seg = z >> 2;
        const int kstart = (z & 3) * 128;
        const int n0 = (blockIdx.x & 31) * BN;
        const float *A, *W; int ldw;
        if      (seg == 0) { A = g_emb[s];  W = W_ih;       ldw = 1024; }
        else if (seg == 1) { A = g_gctx[s]; W = W_ih + 512; ldw = 1024; }
        else               { A = g_h;       W = W_hh;       ldw = 512;  }
        ull acc[4][4];
        #pragma unroll
        for (int p = 0; p < 4; p++)
            #pragma unroll
            for (int j = 0; j < 4; j++) acc[p][j] = 0ull;
        dev_gemm(A, 512, W, ldw, 2048, 0, n0, kstart, 128, acc, As, Ws);
        atomic_epilogue(acc, g_gates, 2048, n0);
    } else {
        if (t == 0) return;
        const int u = t - 1;
        const int s = u & 1;
        const int n0 = (blockIdx.x - 384) * BN;
        ull acc[4][4];
        #pragma unroll
        for (int p = 0; p < 4; p++)
            #pragma unroll
            for (int j = 0; j < 4; j++) acc[p][j] = 0ull;
        dev_gemm(g_pre[s], E_, W_out, E_, V_, 0, n0, 0, E_, acc, As, Ws);
        const int tx = threadIdx.x & 15, ty = threadIdx.x >> 4;
        #pragma unroll
        for (int p = 0; p < 4; p++) {
            #pragma unroll
            for (int rr = 0; rr < 2; rr++) {
                const int b = ty*8 + 2*p + rr;
                int dl = lengths[b] - 1; if (dl < 1) dl = 1;
                const bool act = dl > u;
                float* row = out + ((size_t)b*TD + u) * V_;
                #pragma unroll
                for (int j = 0; j < 4; j++) {
                    int n = n0 + tx*4 + j;
                    if (n < V_) {
                        float v = rr ? hi32(acc[p][j]) : lo32(acc[p][j]);
                        row[n] = act ? (v + b_out[n]) : 0.f;
                    }
                }
            }
        }
    }
}

// LSTM pointwise + masked carry commit
__global__ void __launch_bounds__(256) kE(const int* __restrict__ lengths, int t) {
    const int b = blockIdx.x;
    const int s = t & 1;
    int dl = lengths[b] - 1; if (dl < 1) dl = 1;
    const bool act = dl > t;
    for (int j = threadIdx.x; j < 512; j += 256) {
        const float* g = g_gates + b*2048;
        const float i_ = g[j], f_ = g[512 + j], gg = g[1024 + j], o_ = g[1536 + j];
        const float c_old = g_c[b*H_ + j];
        const float cn = sigf(f_) * c_old + sigf(i_) * tanhf(gg);
        const float hn = sigf(o_) * tanhf(cn);
        g_hnew[s][b*H_ + j] = hn;
        if (act) {
            g_c[b*H_ + j] = cn;
            g_h[b*H_ + j] = hn;
        }
    }
}

__global__ void kdeclen(const int* __restrict__ lengths, float* __restrict__ out) {
    const int b = threadIdx.x;
    if (b < B_) {
        int dl = lengths[b] - 1; if (dl < 1) dl = 1;
        out[(size_t)LOGITS_SZ + ALPHA_SZ + b] = (float)dl;
    }
}

// ---------------- host launcher ----------------
extern "C" void kernel_launch(void* const* d_in, const int* in_sizes, int n_in,
                              void* d_out, int out_size)
{
    const float* ann      = (const float*)d_in[0];
    const int*   captions = (const int*)  d_in[1];
    const int*   lengths  = (const int*)  d_in[2];
    const float* E_emb    = (const float*)d_in[3];
    const float* W_init_h = (const float*)d_in[4];
    const float* b_init_h = (const float*)d_in[5];
    const float* W_init_c = (const float*)d_in[6];
    const float* b_init_c = (const float*)d_in[7];
    const float* W_att_f  = (const float*)d_in[8];
    const float* b_att_f  = (const float*)d_in[9];
    const float* W_att_h  = (const float*)d_in[10];
    const float* b_att_h  = (const float*)d_in[11];
    const float* w_att_v  = (const float*)d_in[12];
    const float* b_att_v  = (const float*)d_in[13];
    const float* W_beta   = (const float*)d_in[14];
    const float* b_beta   = (const float*)d_in[15];
    const float* b_ih     = (const float*)d_in[18];
    const float* b_hh     = (const float*)d_in[19];
    const float* W_ih     = (const float*)d_in[16];
    const float* W_hh     = (const float*)d_in[17];
    const float* W_y      = (const float*)d_in[20];
    const float* W_h      = (const float*)d_in[21];
    const float* W_z      = (const float*)d_in[22];
    const float* W_out    = (const float*)d_in[23];
    const float* b_out    = (const float*)d_in[24];

    float* out = (float*)d_out;

    // prologue
    kmean<<<B_, 256>>>(ann, b_init_h, b_init_c);
    kInit<<<64, 256>>>(W_init_h, W_init_c);
    kTanhHC<<<64, 256>>>();
    kAnnProj<<<dim3(8, 196), 256>>>(ann, W_att_f, b_att_f);

    // pipelined decode loop: step t recurrent work overlapped (in-launch)
    // with step t-1's pre/logits work
    for (int t = 0; t <= TD; t++) {
        kA<<<224, 256>>>(t, captions, E_emb, b_att_h, b_beta, b_ih, b_hh,
                         W_y, W_h, W_z);
        kB<<<192, 256>>>(t, W_att_h, W_beta);
        if (t <= 30)
            kattn<<<B_, 256>>>(ann, w_att_v, b_att_v, lengths, t, out + LOGITS_SZ);
        kD<<<541, 256>>>(t, W_ih, W_hh, W_out, b_out, lengths, out);
        if (t <= 30)
            kE<<<B_, 256>>>(lengths, t);
    }

    kdeclen<<<1, 128>>>(lengths, out);
}

// round 6
// speedup vs baseline: 1.1985x; 1.0135x over previous
#include <cuda_runtime.h>
#include <cuda_bf16.h>
#include <math.h>

typedef unsigned long long ull;

// ---------------- problem constants ----------------
#define B_  128
#define L_  196
#define T_  32
#define TD  31          // T_dec
#define F_  512
#define H_  512
#define A_  512
#define E_  512
#define V_  10000

#define LOGITS_SZ (B_*TD*V_)   // 39,680,000
#define ALPHA_SZ  (B_*TD*L_)   // 777,728

// ---------------- scratch (device globals) ----------------
__device__ float g_mean [B_*F_];
__device__ float g_h    [B_*H_];
__device__ float g_c    [B_*H_];
__device__ float g_hp   [B_*A_];
__device__ float g_gpre [B_*F_];
__device__ float g_gates[B_*4*H_];
// double-buffered (software pipeline, pre/logits shifted by one step)
__device__ float g_emb [2][B_*E_];
__device__ float g_gctx[2][B_*F_];
__device__ float g_hnew[2][B_*H_];
__device__ float g_pre [2][B_*E_];
__device__ float g_annproj[(size_t)B_*L_*A_];   // ~51 MB, loop-invariant

__device__ __forceinline__ float sigf(float x){ return 1.f/(1.f+expf(-x)); }
__device__ __forceinline__ float lo32(ull v){ return __uint_as_float((unsigned)v); }
__device__ __forceinline__ float hi32(ull v){ return __uint_as_float((unsigned)(v>>32)); }

// packed fp32x2 FMA (sm_100+; doubles fp32 FMA throughput vs scalar FFMA)
#define FMA2(acc,a,b) asm("fma.rn.f32x2 %0, %1, %2, %0;" : "+l"(acc) : "l"(a), "l"(b))
#define PACK2(d,s)    asm("mov.b64 %0, {%1, %1};"        : "=l"(d)   : "r"(s))

// ---------------- GEMM core: C[128 x N] = A[128 x K] * W[N x K]^T --------
// acc[p][j] holds packed rows {ty*8+2p, ty*8+2p+1} at column n0+tx*4+j.
#define BM 128
#define BN 64
#define BK 16

__device__ __forceinline__ void dev_gemm(
    const float* __restrict__ A, int lda,
    const float* __restrict__ W, int ldw, int nmax,
    int m0, int n0, int kstart, int kcount,
    ull (&acc)[4][4], float* As, float* Ws)
{
    const int tid = threadIdx.x;
    for (int kt = 0; kt < kcount; kt += BK) {
        // A tile 128x16 -> As[k][m]
        int f = tid;
        #pragma unroll
        for (int r = 0; r < 2; r++, f += 256) {
            int m  = f >> 2;
            int kk = (f & 3) << 2;
            float4 v = *reinterpret_cast<const float4*>(
                &A[(size_t)(m0 + m) * lda + kstart + kt + kk]);
            As[(kk+0)*BM + m] = v.x; As[(kk+1)*BM + m] = v.y;
            As[(kk+2)*BM + m] = v.z; As[(kk+3)*BM + m] = v.w;
        }
        // W tile 64x16 -> Ws[k][n] (row clamp for ragged N)
        {
            int n  = tid >> 2;
            int kk = (tid & 3) << 2;
            int nr = n0 + n; if (nr >= nmax) nr = nmax - 1;
            float4 w = *reinterpret_cast<const float4*>(
                &W[(size_t)nr * ldw + kstart + kt + kk]);
            Ws[(kk+0)*BN + n] = w.x; Ws[(kk+1)*BN + n] = w.y;
            Ws[(kk+2)*BN + n] = w.z; Ws[(kk+3)*BN + n] = w.w;
        }
        __syncthreads();
        const int tx = tid & 15, ty = tid >> 4;
        #pragma unroll
        for (int k = 0; k < BK; k++) {
            const ull* a64 = reinterpret_cast<const ull*>(As + k*BM + ty*8);
            ull a0 = a64[0], a1 = a64[1], a2 = a64[2], a3 = a64[3];
            const unsigned* bw = reinterpret_cast<const unsigned*>(Ws + k*BN + tx*4);
            unsigned u0 = bw[0], u1 = bw[1], u2 = bw[2], u3 = bw[3];
            ull b0, b1, b2, b3;
            PACK2(b0,u0); PACK2(b1,u1); PACK2(b2,u2); PACK2(b3,u3);
            FMA2(acc[0][0],a0,b0); FMA2(acc[0][1],a0,b1); FMA2(acc[0][2],a0,b2); FMA2(acc[0][3],a0,b3);
            FMA2(acc[1][0],a1,b0); FMA2(acc[1][1],a1,b1); FMA2(acc[1][2],a1,b2); FMA2(acc[1][3],a1,b3);
            FMA2(acc[2][0],a2,b0); FMA2(acc[2][1],a2,b1); FMA2(acc[2][2],a2,b2); FMA2(acc[2][3],a2,b3);
            FMA2(acc[3][0],a3,b0); FMA2(acc[3][1],a3,b1); FMA2(acc[3][2],a3,b2); FMA2(acc[3][3],a3,b3);
        }
        __syncthreads();
    }
}

__device__ __forceinline__ void atomic_epilogue(
    ull (&acc)[4][4], float* __restrict__ C, int N, int n0)
{
    const int tx = threadIdx.x & 15, ty = threadIdx.x >> 4;
    #pragma unroll
    for (int p = 0; p < 4; p++) {
        float* R0 = C + (size_t)(ty*8 + 2*p) * N + n0 + tx*4;
        float* R1 = R0 + N;
        #pragma unroll
        for (int j = 0; j < 4; j++) {
            atomicAdd(&R0[j], lo32(acc[p][j]));
            atomicAdd(&R1[j], hi32(acc[p][j]));
        }
    }
}

// ---------------- prologue kernels ----------------

// mean over L + bias-init h0/c0
__global__ void __launch_bounds__(256) kmean(const float* __restrict__ ann,
                      const float* __restrict__ b_init_h,
                      const float* __restrict__ b_init_c)
{
    const int b = blockIdx.x;
    for (int f = threadIdx.x; f < F_; f += blockDim.x) {
        const float* p = ann + (size_t)b*L_*F_ + f;
        float s = 0.f;
        #pragma unroll 4
        for (int l = 0; l < L_; l++) s += p[(size_t)l*F_];
        g_mean[b*F_ + f] = s * (1.f/196.f);
        g_h[b*H_ + f] = b_init_h[f];
        g_c[b*H_ + f] = b_init_c[f];
    }
}

// h0/c0 GEMMs (split-K atomic): grid 64
__global__ void __launch_bounds__(256) kInit(const float* __restrict__ W_init_h,
                                             const float* __restrict__ W_init_c)
{
    __shared__ __align__(16) float As[BK*BM];
    __shared__ __align__(16) float Ws[BK*BN];
    const int z = blockIdx.x >> 3;          // 0..7
    const int seg = z >> 2;
    const int kstart = (z & 3) * 128;
    const int n0 = (blockIdx.x & 7) * BN;
    const float* W = seg ? W_init_c : W_init_h;
    float* C = seg ? g_c : g_h;
    ull acc[4][4];
    #pragma unroll
    for (int p = 0; p < 4; p++)
        #pragma unroll
        for (int j = 0; j < 4; j++) acc[p][j] = 0ull;
    dev_gemm(g_mean, F_, W, F_, H_, 0, n0, kstart, 128, acc, As, Ws);
    atomic_epilogue(acc, C, H_, n0);
}

__global__ void __launch_bounds__(256) kTanhHC() {
    for (int i = blockIdx.x*256 + threadIdx.x; i < B_*H_; i += 64*256) {
        g_h[i] = tanhf(g_h[i]);
        g_c[i] = tanhf(g_c[i]);
    }
}

// ann_proj = ann @ W_att_f^T + b_att_f, grid (8, 196)
__global__ void __launch_bounds__(256) kAnnProj(
    const float* __restrict__ ann,
    const float* __restrict__ W_att_f,
    const float* __restrict__ b_att_f)
{
    __shared__ __align__(16) float As[BK*BM];
    __shared__ __align__(16) float Ws[BK*BN];
    const int n0 = blockIdx.x * BN;
    const int m0 = blockIdx.y * BM;
    ull acc[4][4];
    #pragma unroll
    for (int p = 0; p < 4; p++)
        #pragma unroll
        for (int j = 0; j < 4; j++) acc[p][j] = 0ull;
    dev_gemm(ann, F_, W_att_f, F_, A_, m0, n0, 0, F_, acc, As, Ws);
    const int tx = threadIdx.x & 15, ty = threadIdx.x >> 4;
    const int n = n0 + tx*4;
    float4 bb = *reinterpret_cast<const float4*>(&b_att_f[n]);
    #pragma unroll
    for (int p = 0; p < 4; p++) {
        float* R0 = g_annproj + (size_t)(m0 + ty*8 + 2*p) * A_ + n;
        float* R1 = R0 + A_;
        float4 v0, v1;
        v0.x = lo32(acc[p][0]) + bb.x; v0.y = lo32(acc[p][1]) + bb.y;
        v0.z = lo32(acc[p][2]) + bb.z; v0.w = lo32(acc[p][3]) + bb.w;
        v1.x = hi32(acc[p][0]) + bb.x; v1.y = hi32(acc[p][1]) + bb.y;
        v1.z = hi32(acc[p][2]) + bb.z; v1.w = hi32(acc[p][3]) + bb.w;
        *reinterpret_cast<float4*>(R0) = v0;
        *reinterpret_cast<float4*>(R1) = v1;
    }
}

// ---------------- pipelined step kernels ----------------

// kA: pre-gemm(t-1)  [blocks 0..95]  ∪  prep(t) [blocks 96..223]
__global__ void __launch_bounds__(256) kA(int t,
    const int* __restrict__ captions, const float* __restrict__ E_emb,
    const float* __restrict__ b_att_h, const float* __restrict__ b_beta,
    const float* __restrict__ b_ih, const float* __restrict__ b_hh,
    const float* __restrict__ W_y, const float* __restrict__ W_h,
    const float* __restrict__ W_z)
{
    __shared__ __align__(16) float As[BK*BM];
    __shared__ __align__(16) float Ws[BK*BN];
    if (blockIdx.x < 96) {
        if (t == 0) return;
        const int s = (t-1) & 1;
        const int z = blockIdx.x >> 3;       // 0..11
        const int seg = z >> 2;
        const int kstart = (z & 3) * 128;
        const int n0 = (blockIdx.x & 7) * BN;
        const float *A, *W;
        if      (seg == 0) { A = g_emb[s];  W = W_y; }
        else if (seg == 1) { A = g_hnew[s]; W = W_h; }
        else               { A = g_gctx[s]; W = W_z; }
        ull acc[4][4];
        #pragma unroll
        for (int p = 0; p < 4; p++)
            #pragma unroll
            for (int j = 0; j < 4; j++) acc[p][j] = 0ull;
        dev_gemm(A, 512, W, 512, E_, 0, n0, kstart, 128, acc, As, Ws);
        atomic_epilogue(acc, g_pre[s], E_, n0);
    } else {
        if (t > 30) return;
        const int b = blockIdx.x - 96;
        const int s = t & 1;
        const int tok = captions[b*T_ + t];
        for (int j = threadIdx.x; j < 512; j += 256) {
            g_emb[s][b*512 + j] = E_emb[(size_t)tok*512 + j];
            g_hp  [b*512 + j] = b_att_h[j];
            g_gpre[b*512 + j] = b_beta[j];
            g_pre[s][b*512 + j] = 0.f;
            #pragma unroll
            for (int q = 0; q < 4; q++)
                g_gates[b*2048 + q*512 + j] = b_ih[q*512 + j] + b_hh[q*512 + j];
        }
    }
}

// kB: hp/gpre GEMMs(t) [blocks 0..127]  ∪  tanh(pre(t-1)) [blocks 128..191]
__global__ void __launch_bounds__(256) kB(int t,
    const float* __restrict__ W_att_h, const float* __restrict__ W_beta)
{
    __shared__ __align__(16) float As[BK*BM];
    __shared__ __align__(16) float Ws[BK*BN];
    if (blockIdx.x < 128) {
        if (t > 30) return;
        const int z = blockIdx.x >> 3;       // 0..15
        const int seg = z >> 3;
        const int kstart = (z & 7) * 64;
        const int n0 = (blockIdx.x & 7) * BN;
        const float* W = seg ? W_beta : W_att_h;
        float* C = seg ? g_gpre : g_hp;
        ull acc[4][4];
        #pragma unroll
        for (int p = 0; p < 4; p++)
            #pragma unroll
            for (int j = 0; j < 4; j++) acc[p][j] = 0ull;
        dev_gemm(g_h, H_, W, H_, A_, 0, n0, kstart, 64, acc, As, Ws);
        atomic_epilogue(acc, C, A_, n0);
    } else {
        if (t == 0) return;
        const int s = (t-1) & 1;
        for (int i = (blockIdx.x - 128)*256 + threadIdx.x; i < B_*E_; i += 64*256)
            g_pre[s][i] = tanhf(g_pre[s][i]);
    }
}

// fused attention(t): scores -> softmax -> context -> gated ctx; block per b
__global__ void __launch_bounds__(256) kattn(
    const float* __restrict__ ann,
    const float* __restrict__ w_att_v,
    const float* __restrict__ b_att_v,
    const int*   __restrict__ lengths,
    int t, float* __restrict__ alphas_out)
{
    __shared__ float hp_s[A_];
    __shared__ float wv_s[A_];
    __shared__ float sc[L_];
    __shared__ float red[8];
    __shared__ float sval[2];

    const int b = blockIdx.x;
    const int tid = threadIdx.x;
    const int w = tid >> 5, lane = tid & 31;
    const int s = t & 1;

    for (int i = tid; i < A_; i += 256) {
        hp_s[i] = g_hp[b*A_ + i];
        wv_s[i] = w_att_v[i];
    }
    __syncthreads();

    const float bv = b_att_v[0];
    const float* ap = g_annproj + (size_t)b*L_*A_;

    for (int l = w; l < L_; l += 8) {
        const float* row = ap + (size_t)l*A_;
        float sacc = 0.f;
        #pragma unroll 4
        for (int a = lane; a < A_; a += 32)
            sacc += fmaxf(row[a] + hp_s[a], 0.f) * wv_s[a];
        #pragma unroll
        for (int o = 16; o; o >>= 1) sacc += __shfl_down_sync(0xffffffffu, sacc, o);
        if (lane == 0) sc[l] = sacc + bv;
    }
    __syncthreads();

    float mx = -1e30f;
    for (int i = tid; i < L_; i += 256) mx = fmaxf(mx, sc[i]);
    #pragma unroll
    for (int o = 16; o; o >>= 1) mx = fmaxf(mx, __shfl_xor_sync(0xffffffffu, mx, o));
    if (lane == 0) red[w] = mx;
    __syncthreads();
    if (tid == 0) {
        float m = red[0];
        #pragma unroll
        for (int i = 1; i < 8; i++) m = fmaxf(m, red[i]);
        sval[0] = m;
    }
    __syncthreads();
    mx = sval[0];

    float ss = 0.f;
    for (int i = tid; i < L_; i += 256) {
        float e = expf(sc[i] - mx);
        sc[i] = e;
        ss += e;
    }
    #pragma unroll
    for (int o = 16; o; o >>= 1) ss += __shfl_xor_sync(0xffffffffu, ss, o);
    if (lane == 0) red[w] = ss;
    __syncthreads();
    if (tid == 0) {
        float s2 = 0.f;
        #pragma unroll
        for (int i = 0; i < 8; i++) s2 += red[i];
        sval[1] = s2;
    }
    __syncthreads();
    const float inv = 1.f / sval[1];

    int dl = lengths[b] - 1; if (dl < 1) dl = 1;
    const bool act = dl > t;
    for (int i = tid; i < L_; i += 256) {
        float a = sc[i] * inv;
        sc[i] = a;
        alphas_out[((size_t)b*TD + t)*L_ + i] = act ? a : 0.f;
    }
    __syncthreads();

    const float* an = ann + (size_t)b*L_*F_;
    for (int f = tid; f < F_; f += 256) {
        float acc = 0.f;
        #pragma unroll 4
        for (int l = 0; l < L_; l++)
            acc = fmaf(sc[l], an[(size_t)l*F_ + f], acc);
        const float gate = sigf(g_gpre[b*F_ + f]);
        g_gctx[s][b*F_ + f] = gate * acc;
    }
}

// kD: gates(t) [blocks 0..383]  ∪  logits(t-1) [blocks 384..540]
__global__ void __launch_bounds__(256) kD(int t,
    const float* __restrict__ W_ih, const float* __restrict__ W_hh,
    const float* __restrict__ W_out, const float* __restrict__ b_out,
    const int* __restrict__ lengths, float* __restrict__ out)
{
    __shared__ __align__(16) float As[BK*BM];
    __shared__ __align__(16) float Ws[BK*BN];
    if (blockIdx.x < 384) {
        if (t > 30) return;
        const int s = t & 1;
        const int z = blockIdx.x >> 5;       // 0..11
        const int seg = z >> 2;
        const int kstart = (z & 3) * 128;
        const int n0 = (blockIdx.x & 31) * BN;
        const float *A, *W; int ldw;
        if      (seg == 0) { A = g_emb[s];  W = W_ih;       ldw = 1024; }
        else if (seg == 1) { A = g_gctx[s]; W = W_ih + 512; ldw = 1024; }
        else               { A = g_h;       W = W_hh;       ldw = 512;  }
        ull acc[4][4];
        #pragma unroll
        for (int p = 0; p < 4; p++)
            #pragma unroll
            for (int j = 0; j < 4; j++) acc[p][j] = 0ull;
        dev_gemm(A, 512, W, ldw, 2048, 0, n0, kstart, 128, acc, As, Ws);
        atomic_epilogue(acc, g_gates, 2048, n0);
    } else {
        if (t == 0) return;
        const int u = t - 1;
        const int s = u & 1;
        const int n0 = (blockIdx.x - 384) * BN;
        ull acc[4][4];
        #pragma unroll
        for (int p = 0; p < 4; p++)
            #pragma unroll
            for (int j = 0; j < 4; j++) acc[p][j] = 0ull;
        dev_gemm(g_pre[s], E_, W_out, E_, V_, 0, n0, 0, E_, acc, As, Ws);
        const int tx = threadIdx.x & 15, ty = threadIdx.x >> 4;
        #pragma unroll
        for (int p = 0; p < 4; p++) {
            #pragma unroll
            for (int rr = 0; rr < 2; rr++) {
                const int b = ty*8 + 2*p + rr;
                int dl = lengths[b] - 1; if (dl < 1) dl = 1;
                const bool act = dl > u;
                float* row = out + ((size_t)b*TD + u) * V_;
                #pragma unroll
                for (int j = 0; j < 4; j++) {
                    int n = n0 + tx*4 + j;
                    if (n < V_) {
                        float v = rr ? hi32(acc[p][j]) : lo32(acc[p][j]);
                        row[n] = act ? (v + b_out[n]) : 0.f;
                    }
                }
            }
        }
    }
}

// LSTM pointwise + masked carry commit
__global__ void __launch_bounds__(256) kE(const int* __restrict__ lengths, int t) {
    const int b = blockIdx.x;
    const int s = t & 1;
    int dl = lengths[b] - 1; if (dl < 1) dl = 1;
    const bool act = dl > t;
    for (int j = threadIdx.x; j < 512; j += 256) {
        const float* g = g_gates + b*2048;
        const float i_ = g[j], f_ = g[512 + j], gg = g[1024 + j], o_ = g[1536 + j];
        const float c_old = g_c[b*H_ + j];
        const float cn = sigf(f_) * c_old + sigf(i_) * tanhf(gg);
        const float hn = sigf(o_) * tanhf(cn);
        g_hnew[s][b*H_ + j] = hn;
        if (act) {
            g_c[b*H_ + j] = cn;
            g_h[b*H_ + j] = hn;
        }
    }
}

__global__ void kdeclen(const int* __restrict__ lengths, float* __restrict__ out) {
    const int b = threadIdx.x;
    if (b < B_) {
        int dl = lengths[b] - 1; if (dl < 1) dl = 1;
        out[(size_t)LOGITS_SZ + ALPHA_SZ + b] = (float)dl;
    }
}

// ---------------- host launcher ----------------
extern "C" void kernel_launch(void* const* d_in, const int* in_sizes, int n_in,
                              void* d_out, int out_size)
{
    const float* ann      = (const float*)d_in[0];
    const int*   captions = (const int*)  d_in[1];
    const int*   lengths  = (const int*)  d_in[2];
    const float* E_emb    = (const float*)d_in[3];
    const float* W_init_h = (const float*)d_in[4];
    const float* b_init_h = (const float*)d_in[5];
    const float* W_init_c = (const float*)d_in[6];
    const float* b_init_c = (const float*)d_in[7];
    const float* W_att_f  = (const float*)d_in[8];
    const float* b_att_f  = (const float*)d_in[9];
    const float* W_att_h  = (const float*)d_in[10];
    const float* b_att_h  = (const float*)d_in[11];
    const float* w_att_v  = (const float*)d_in[12];
    const float* b_att_v  = (const float*)d_in[13];
    const float* W_beta   = (const float*)d_in[14];
    const float* b_beta   = (const float*)d_in[15];
    const float* b_ih     = (const float*)d_in[18];
    const float* b_hh     = (const float*)d_in[19];
    const float* W_ih     = (const float*)d_in[16];
    const float* W_hh     = (const float*)d_in[17];
    const float* W_y      = (const float*)d_in[20];
    const float* W_h      = (const float*)d_in[21];
    const float* W_z      = (const float*)d_in[22];
    const float* W_out    = (const float*)d_in[23];
    const float* b_out    = (const float*)d_in[24];

    float* out = (float*)d_out;

    // prologue
    kmean<<<B_, 256>>>(ann, b_init_h, b_init_c);
    kInit<<<64, 256>>>(W_init_h, W_init_c);
    kTanhHC<<<64, 256>>>();
    kAnnProj<<<dim3(8, 196), 256>>>(ann, W_att_f, b_att_f);

    // pipelined decode loop: step t recurrent work overlapped (in-launch)
    // with step t-1's pre/logits work
    for (int t = 0; t <= TD; t++) {
        kA<<<224, 256>>>(t, captions, E_emb, b_att_h, b_beta, b_ih, b_hh,
                         W_y, W_h, W_z);
        kB<<<192, 256>>>(t, W_att_h, W_beta);
        if (t <= 30)
            kattn<<<B_, 256>>>(ann, w_att_v, b_att_v, lengths, t, out + LOGITS_SZ);
        kD<<<541, 256>>>(t, W_ih, W_hh, W_out, b_out, lengths, out);
        if (t <= 30)
            kE<<<B_, 256>>>(lengths, t);
    }

    kdeclen<<<1, 128>>>(lengths, out);
}

// round 7
// speedup vs baseline: 1.2770x; 1.0655x over previous
#include <cuda_runtime.h>
#include <cuda_bf16.h>
#include <math.h>

typedef __nv_bfloat16 bf16;

// ---------------- problem constants ----------------
#define B_  128
#define L_  196
#define T_  32
#define TD  31
#define F_  512
#define H_  512
#define V_  10000
#define K_  512

#define LOGITS_SZ (B_*TD*V_)
#define ALPHA_SZ  (B_*TD*L_)

// ---------------- fp32 state ----------------
__device__ float g_mean [B_*F_];
__device__ float g_h    [B_*H_];
__device__ float g_c    [B_*H_];
__device__ float g_hp   [B_*F_];
__device__ float g_gpre [B_*F_];
__device__ float g_gates[B_*4*H_];
__device__ float g_pre  [2][B_*F_];
__device__ float g_annproj[(size_t)B_*L_*F_];

// ---------------- bf16 hi/lo activation buffers ----------------
__device__ bf16 s_meanh[B_*F_],  s_meanl[B_*F_];
__device__ bf16 s_hh[B_*H_],     s_hl[B_*H_];
__device__ bf16 s_embh [2][B_*F_], s_embl [2][B_*F_];
__device__ bf16 s_gctxh[2][B_*F_], s_gctxl[2][B_*F_];
__device__ bf16 s_hnewh[2][B_*H_], s_hnewl[2][B_*H_];
__device__ bf16 s_preh [2][B_*F_], s_prel [2][B_*F_];
__device__ bf16 s_annh[(size_t)B_*L_*F_], s_annl[(size_t)B_*L_*F_];

// ---------------- bf16 hi/lo split weights (prologue-converted) ----------
__device__ bf16 w_outh[(size_t)V_*K_], w_outl[(size_t)V_*K_];
__device__ bf16 w_ihah[2048*K_], w_ihal[2048*K_];   // W_ih[:, :512]
__device__ bf16 w_ihbh[2048*K_], w_ihbl[2048*K_];   // W_ih[:, 512:]
__device__ bf16 w_hhh [2048*K_], w_hhl [2048*K_];
__device__ bf16 w_yh [512*K_], w_yl [512*K_];
__device__ bf16 w_hh2[512*K_], w_hl2[512*K_];
__device__ bf16 w_zh [512*K_], w_zl [512*K_];
__device__ bf16 w_atthh[512*K_], w_atthl[512*K_];
__device__ bf16 w_betah[512*K_], w_betal[512*K_];
__device__ bf16 w_attfh[512*K_], w_attfl[512*K_];
__device__ bf16 w_inhh[512*K_], w_inhl[512*K_];
__device__ bf16 w_inch[512*K_], w_incl[512*K_];

__device__ __forceinline__ float sigf(float x){ return 1.f/(1.f+expf(-x)); }
__device__ __forceinline__ void split2(float x, bf16& h, bf16& l){
    h = __float2bfloat16(x);
    l = __float2bfloat16(x - __bfloat162float(h));
}

// ---------------- bf16 MMA GEMM core ----------------
// Block: 256 thr / 8 warps, output tile 128(m) x 128(n), K=512 per call.
// A: [128][512] bf16 row-major (k contig). W: [nmax][512] bf16 row-major.
// SMEM tiles padded to 40 bf16/row -> conflict-free fragment LDS.
#define KC   32
#define LDP  40          // padded row (bf16)
#define SM_BYTES (2*128*LDP*2)

#define MMA16816(d, a, b) asm volatile( \
    "mma.sync.aligned.m16n8k16.row.col.f32.bf16.bf16.f32 " \
    "{%0,%1,%2,%3}, {%4,%5,%6,%7}, {%8,%9}, {%0,%1,%2,%3};" \
    : "+f"(d[0]), "+f"(d[1]), "+f"(d[2]), "+f"(d[3]) \
    : "r"(a[0]), "r"(a[1]), "r"(a[2]), "r"(a[3]), "r"(b[0]), "r"(b[1]))

__device__ __forceinline__ void mma_gemm512(
    const bf16* __restrict__ A,     // 128 x 512
    const bf16* __restrict__ W,     // nmax x 512 (rows n0..n0+127 used)
    int n0, int nmax,
    float (&acc)[2][8][4], bf16* As, bf16* Bs)
{
    const int tid  = threadIdx.x;
    const int row  = tid >> 1, half = tid & 1;    // loader mapping
    const int wid  = tid >> 5, lane = tid & 31;
    const int g    = lane >> 2, tg = lane & 3;
    const int wm   = wid >> 1,  wn = wid & 1;
    const unsigned* As32 = reinterpret_cast<const unsigned*>(As);
    const unsigned* Bs32 = reinterpret_cast<const unsigned*>(Bs);

    int wrow = n0 + row; if (wrow >= nmax) wrow = nmax - 1;
    const bf16* arow = A + (size_t)row * K_ + half * 16;
    const bf16* wrowp = W + (size_t)wrow * K_ + half * 16;
    bf16* sa = As + row * LDP + half * 16;
    bf16* sb = Bs + row * LDP + half * 16;

    for (int k0 = 0; k0 < K_; k0 += KC) {
        const uint4* pa = reinterpret_cast<const uint4*>(arow + k0);
        const uint4* pb = reinterpret_cast<const uint4*>(wrowp + k0);
        uint4 va0 = pa[0], va1 = pa[1];
        uint4 vb0 = pb[0], vb1 = pb[1];
        reinterpret_cast<uint4*>(sa)[0] = va0;
        reinterpret_cast<uint4*>(sa)[1] = va1;
        reinterpret_cast<uint4*>(sb)[0] = vb0;
        reinterpret_cast<uint4*>(sb)[1] = vb1;
        __syncthreads();

        #pragma unroll
        for (int kk = 0; kk < KC; kk += 16) {
            const int kb = kk >> 1;
            unsigned a[2][4], b[8][2];
            #pragma unroll
            for (int mt = 0; mt < 2; mt++) {
                const int m = wm*32 + mt*16 + g;
                const unsigned* p  = As32 + m*(LDP/2) + kb + tg;
                const unsigned* p8 = p + 8*(LDP/2);
                a[mt][0] = p[0];  a[mt][1] = p8[0];
                a[mt][2] = p[4];  a[mt][3] = p8[4];
            }
            #pragma unroll
            for (int j = 0; j < 8; j++) {
                const int n = wn*64 + j*8 + g;
                const unsigned* p = Bs32 + n*(LDP/2) + kb + tg;
                b[j][0] = p[0];
                b[j][1] = p[4];
            }
            #pragma unroll
            for (int mt = 0; mt < 2; mt++)
                #pragma unroll
                for (int j = 0; j < 8; j++)
                    MMA16816(acc[mt][j], a[mt], b[j]);
        }
        __syncthreads();
    }
}

__device__ __forceinline__ void acc_zero(float (&acc)[2][8][4]) {
    #pragma unroll
    for (int mt = 0; mt < 2; mt++)
        #pragma unroll
        for (int j = 0; j < 8; j++)
            #pragma unroll
            for (int q = 0; q < 4; q++) acc[mt][j][q] = 0.f;
}

// atomic-accumulate epilogue into fp32 C[128][ldc] at columns n0..
__device__ __forceinline__ void epi_atomic(
    float (&acc)[2][8][4], float* __restrict__ C, int ldc, int n0, int nmax)
{
    const int lane = threadIdx.x & 31, wid = threadIdx.x >> 5;
    const int g = lane >> 2, tg = lane & 3;
    const int wm = wid >> 1, wn = wid & 1;
    #pragma unroll
    for (int mt = 0; mt < 2; mt++) {
        const int r0 = wm*32 + mt*16 + g, r1 = r0 + 8;
        #pragma unroll
        for (int j = 0; j < 8; j++) {
            const int c = n0 + wn*64 + j*8 + 2*tg;
            if (c < nmax) {
                atomicAdd(&C[(size_t)r0*ldc + c], acc[mt][j][0]);
                atomicAdd(&C[(size_t)r1*ldc + c], acc[mt][j][2]);
            }
            if (c + 1 < nmax) {
                atomicAdd(&C[(size_t)r0*ldc + c + 1], acc[mt][j][1]);
                atomicAdd(&C[(size_t)r1*ldc + c + 1], acc[mt][j][3]);
            }
        }
    }
}

// ---------------- prologue kernels ----------------

// fp32 -> bf16 hi/lo split; rows x 512, src row stride rstride, col offset coloff
__global__ void __launch_bounds__(256) kConv(
    const float* __restrict__ src, int rstride, int coloff,
    bf16* __restrict__ dh, bf16* __restrict__ dl, int nrows)
{
    const int total = nrows * 512;
    for (int i = blockIdx.x*256 + threadIdx.x; i < total; i += gridDim.x*256) {
        const int r = i >> 9, c = i & 511;
        split2(src[(size_t)r*rstride + coloff + c], dh[i], dl[i]);
    }
}

// mean over L + split(mean) + bias-init of h0/c0
__global__ void __launch_bounds__(256) kmean(const float* __restrict__ ann,
    const float* __restrict__ b_init_h, const float* __restrict__ b_init_c)
{
    const int b = blockIdx.x;
    for (int f = threadIdx.x; f < F_; f += 256) {
        const float* p = ann + (size_t)b*L_*F_ + f;
        float s = 0.f;
        #pragma unroll 4
        for (int l = 0; l < L_; l++) s += p[(size_t)l*F_];
        s *= (1.f/196.f);
        g_mean[b*F_ + f] = s;
        split2(s, s_meanh[b*F_ + f], s_meanl[b*F_ + f]);
        g_h[b*H_ + f] = b_init_h[f];
        g_c[b*H_ + f] = b_init_c[f];
    }
}

// h0/c0 GEMM (tensor): 2 outputs x 3 regions x 4 ntiles = 24 blocks
__global__ void __launch_bounds__(256, 2) kInitT()
{
    __shared__ __align__(16) bf16 As[128*LDP];
    __shared__ __align__(16) bf16 Bs[128*LDP];
    const int z = blockIdx.x;
    const int which = z / 12, region = (z / 4) % 3, nt = z % 4;
    const bf16* A = (region == 1) ? s_meanl : s_meanh;
    const bf16* W;
    if (which == 0) W = (region == 2) ? w_inhl : w_inhh;
    else            W = (region == 2) ? w_incl : w_inch;
    float (*C) = which ? g_c : g_h;
    float acc[2][8][4]; acc_zero(acc);
    mma_gemm512(A, W, nt*128, 512, acc, As, Bs);
    epi_atomic(acc, C, 512, nt*128, 512);
}

__global__ void __launch_bounds__(256) kTanhHC() {
    for (int i = blockIdx.x*256 + threadIdx.x; i < B_*H_; i += 64*256) {
        const float h = tanhf(g_h[i]);
        g_h[i] = h;
        g_c[i] = tanhf(g_c[i]);
        split2(h, s_hh[i], s_hl[i]);
    }
}

// ann_proj (tensor, direct store): grid (4, 196), 3 regions in-block
__global__ void __launch_bounds__(256, 2) kAnnProjT(const float* __restrict__ b_att_f)
{
    __shared__ __align__(16) bf16 As[128*LDP];
    __shared__ __align__(16) bf16 Bs[128*LDP];
    const int n0 = blockIdx.x * 128;
    const size_t m0 = (size_t)blockIdx.y * 128;
    float acc[2][8][4]; acc_zero(acc);
    #pragma unroll
    for (int region = 0; region < 3; region++) {
        const bf16* A = ((region == 1) ? s_annl : s_annh) + m0 * K_;
        const bf16* W = (region == 2) ? w_attfl : w_attfh;
        mma_gemm512(A, W, n0, 512, acc, As, Bs);
    }
    const int lane = threadIdx.x & 31, wid = threadIdx.x >> 5;
    const int g = lane >> 2, tg = lane & 3;
    const int wm = wid >> 1, wn = wid & 1;
    #pragma unroll
    for (int mt = 0; mt < 2; mt++) {
        const int r0 = wm*32 + mt*16 + g, r1 = r0 + 8;
        #pragma unroll
        for (int j = 0; j < 8; j++) {
            const int c = n0 + wn*64 + j*8 + 2*tg;
            const float b0 = b_att_f[c], b1 = b_att_f[c+1];
            g_annproj[(m0 + r0)*F_ + c    ] = acc[mt][j][0] + b0;
            g_annproj[(m0 + r0)*F_ + c + 1] = acc[mt][j][1] + b1;
            g_annproj[(m0 + r1)*F_ + c    ] = acc[mt][j][2] + b0;
            g_annproj[(m0 + r1)*F_ + c + 1] = acc[mt][j][3] + b1;
        }
    }
}

// ---------------- pipelined step kernels ----------------

// kA: pre-gemm(t-1) [0,36)  ∪  prep(t) [36,164)  ∪  out-row-init(t-1) [164,228)
__global__ void __launch_bounds__(256, 2) kA(int t,
    const int* __restrict__ captions, const float* __restrict__ E_emb,
    const float* __restrict__ b_att_h, const float* __restrict__ b_beta,
    const float* __restrict__ b_ih, const float* __restrict__ b_hh,
    const float* __restrict__ b_out, const int* __restrict__ lengths,
    float* __restrict__ out)
{
    __shared__ __align__(16) bf16 As[128*LDP];
    __shared__ __align__(16) bf16 Bs[128*LDP];
    if (blockIdx.x < 36) {
        if (t == 0) return;
        const int s = (t-1) & 1;
        const int z = blockIdx.x;
        const int seg = z / 12, region = (z / 4) % 3, nt = z % 4;
        const bf16 *A, *W;
        if      (seg == 0) A = (region == 1) ? s_embl [s] : s_embh [s];
        else if (seg == 1) A = (region == 1) ? s_hnewl[s] : s_hnewh[s];
        else               A = (region == 1) ? s_gctxl[s] : s_gctxh[s];
        if      (seg == 0) W = (region == 2) ? w_yl  : w_yh;
        else if (seg == 1) W = (region == 2) ? w_hl2 : w_hh2;
        else               W = (region == 2) ? w_zl  : w_zh;
        float acc[2][8][4]; acc_zero(acc);
        mma_gemm512(A, W, nt*128, 512, acc, As, Bs);
        epi_atomic(acc, g_pre[s], 512, nt*128, 512);
    } else if (blockIdx.x < 164) {
        if (t > 30) return;
        const int b = blockIdx.x - 36;
        const int s = t & 1;
        const int tok = captions[b*T_ + t];
        for (int j = threadIdx.x; j < 512; j += 256) {
            const float e = E_emb[(size_t)tok*512 + j];
            split2(e, s_embh[s][b*512 + j], s_embl[s][b*512 + j]);
            g_hp  [b*512 + j] = b_att_h[j];
            g_gpre[b*512 + j] = b_beta[j];
            g_pre[s][b*512 + j] = 0.f;
            #pragma unroll
            for (int q = 0; q < 4; q++)
                g_gates[b*2048 + q*512 + j] = b_ih[q*512 + j] + b_hh[q*512 + j];
        }
    } else {
        if (t == 0) return;
        const int u = t - 1;
        const int base = (blockIdx.x - 164) * 2;
        #pragma unroll
        for (int r = 0; r < 2; r++) {
            const int b = base + r;
            int dl = lengths[b] - 1; if (dl < 1) dl = 1;
            const bool act = dl > u;
            float* row = out + ((size_t)b*TD + u) * V_;
            for (int n = threadIdx.x; n < V_; n += 256)
                row[n] = act ? b_out[n] : 0.f;
        }
    }
}

// kB: hp/gpre GEMMs(t) [0,24)  ∪  tanh+split(pre(t-1)) [24,40)
__global__ void __launch_bounds__(256, 2) kB(int t)
{
    __shared__ __align__(16) bf16 As[128*LDP];
    __shared__ __align__(16) bf16 Bs[128*LDP];
    if (blockIdx.x < 24) {
        if (t > 30) return;
        const int z = blockIdx.x;
        const int which = z / 12, region = (z / 4) % 3, nt = z % 4;
        const bf16* A = (region == 1) ? s_hl : s_hh;
        const bf16* W;
        if (which == 0) W = (region == 2) ? w_atthl : w_atthh;
        else            W = (region == 2) ? w_betal : w_betah;
        float* C = which ? g_gpre : g_hp;
        float acc[2][8][4]; acc_zero(acc);
        mma_gemm512(A, W, nt*128, 512, acc, As, Bs);
        epi_atomic(acc, C, 512, nt*128, 512);
    } else {
        if (t == 0) return;
        const int s = (t-1) & 1;
        for (int i = (blockIdx.x - 24)*256 + threadIdx.x; i < B_*F_; i += 16*256) {
            const float v = tanhf(g_pre[s][i]);
            split2(v, s_preh[s][i], s_prel[s][i]);
        }
    }
}

// fused attention(t): scores -> softmax -> context -> gated ctx (bf16 split out)
__global__ void __launch_bounds__(256) kattn(
    const float* __restrict__ ann,
    const float* __restrict__ w_att_v,
    const float* __restrict__ b_att_v,
    const int*   __restrict__ lengths,
    int t, float* __restrict__ alphas_out)
{
    __shared__ float hp_s[F_];
    __shared__ float wv_s[F_];
    __shared__ float sc[L_];
    __shared__ float red[8];
    __shared__ float sval[2];

    const int b = blockIdx.x;
    const int tid = threadIdx.x;
    const int w = tid >> 5, lane = tid & 31;
    const int s = t & 1;

    for (int i = tid; i < F_; i += 256) {
        hp_s[i] = g_hp[b*F_ + i];
        wv_s[i] = w_att_v[i];
    }
    __syncthreads();

    const float bv = b_att_v[0];
    const float* ap = g_annproj + (size_t)b*L_*F_;

    for (int l = w; l < L_; l += 8) {
        const float* row = ap + (size_t)l*F_;
        float sacc = 0.f;
        #pragma unroll 4
        for (int a = lane; a < F_; a += 32)
            sacc += fmaxf(row[a] + hp_s[a], 0.f) * wv_s[a];
        #pragma unroll
        for (int o = 16; o; o >>= 1) sacc += __shfl_down_sync(0xffffffffu, sacc, o);
        if (lane == 0) sc[l] = sacc + bv;
    }
    __syncthreads();

    float mx = -1e30f;
    for (int i = tid; i < L_; i += 256) mx = fmaxf(mx, sc[i]);
    #pragma unroll
    for (int o = 16; o; o >>= 1) mx = fmaxf(mx, __shfl_xor_sync(0xffffffffu, mx, o));
    if (lane == 0) red[w] = mx;
    __syncthreads();
    if (tid == 0) {
        float m = red[0];
        #pragma unroll
        for (int i = 1; i < 8; i++) m = fmaxf(m, red[i]);
        sval[0] = m;
    }
    __syncthreads();
    mx = sval[0];

    float ss = 0.f;
    for (int i = tid; i < L_; i += 256) {
        const float e = expf(sc[i] - mx);
        sc[i] = e;
        ss += e;
    }
    #pragma unroll
    for (int o = 16; o; o >>= 1) ss += __shfl_xor_sync(0xffffffffu, ss, o);
    if (lane == 0) red[w] = ss;
    __syncthreads();
    if (tid == 0) {
        float s2 = 0.f;
        #pragma unroll
        for (int i = 0; i < 8; i++) s2 += red[i];
        sval[1] = s2;
    }
    __syncthreads();
    const float inv = 1.f / sval[1];

    int dl = lengths[b] - 1; if (dl < 1) dl = 1;
    const bool act = dl > t;
    for (int i = tid; i < L_; i += 256) {
        const float a = sc[i] * inv;
        sc[i] = a;
        alphas_out[((size_t)b*TD + t)*L_ + i] = act ? a : 0.f;
    }
    __syncthreads();

    const float* an = ann + (size_t)b*L_*F_;
    for (int f = tid; f < F_; f += 256) {
        float acc = 0.f;
        #pragma unroll 4
        for (int l = 0; l < L_; l++)
            acc = fmaf(sc[l], an[(size_t)l*F_ + f], acc);
        const float gate = sigf(g_gpre[b*F_ + f]);
        split2(gate * acc, s_gctxh[s][b*F_ + f], s_gctxl[s][b*F_ + f]);
    }
}

// kD: gates(t) [0,144)  ∪  logits(t-1) [144,381)
__global__ void __launch_bounds__(256, 2) kD(int t,
    const int* __restrict__ lengths, float* __restrict__ out)
{
    __shared__ __align__(16) bf16 As[128*LDP];
    __shared__ __align__(16) bf16 Bs[128*LDP];
    if (blockIdx.x < 144) {
        if (t > 30) return;
        const int s = t & 1;
        const int z = blockIdx.x;
        const int seg = z / 48, region = (z / 16) % 3, nt = z % 16;
        const bf16 *A, *W;
        if      (seg == 0) A = (region == 1) ? s_embl [s] : s_embh [s];
        else if (seg == 1) A = (region == 1) ? s_gctxl[s] : s_gctxh[s];
        else               A = (region == 1) ? s_hl        : s_hh;
        if      (seg == 0) W = (region == 2) ? w_ihal : w_ihah;
        else if (seg == 1) W = (region == 2) ? w_ihbl : w_ihbh;
        else               W = (region == 2) ? w_hhl  : w_hhh;
        float acc[2][8][4]; acc_zero(acc);
        mma_gemm512(A, W, nt*128, 2048, acc, As, Bs);
        epi_atomic(acc, g_gates, 2048, nt*128, 2048);
    } else {
        if (t == 0) return;
        const int u = t - 1;
        const int s = u & 1;
        const int z = blockIdx.x - 144;
        const int region = z / 79, nt = z % 79;
        const int n0 = nt * 128;
        const bf16* A = (region == 1) ? s_prel[s] : s_preh[s];
        const bf16* W = (region == 2) ? w_outl    : w_outh;
        float acc[2][8][4]; acc_zero(acc);
        mma_gemm512(A, W, n0, V_, acc, As, Bs);
        const int lane = threadIdx.x & 31, wid = threadIdx.x >> 5;
        const int g = lane >> 2, tg = lane & 3;
        const int wm = wid >> 1, wn = wid & 1;
        #pragma unroll
        for (int mt = 0; mt < 2; mt++) {
            const int r0 = wm*32 + mt*16 + g, r1 = r0 + 8;
            int dl0 = lengths[r0] - 1; if (dl0 < 1) dl0 = 1;
            int dl1 = lengths[r1] - 1; if (dl1 < 1) dl1 = 1;
            const bool a0 = dl0 > u, a1 = dl1 > u;
            float* row0 = out + ((size_t)r0*TD + u) * V_;
            float* row1 = out + ((size_t)r1*TD + u) * V_;
            #pragma unroll
            for (int j = 0; j < 8; j++) {
                const int c = n0 + wn*64 + j*8 + 2*tg;
                if (c < V_) {
                    if (a0) atomicAdd(&row0[c], acc[mt][j][0]);
                    if (a1) atomicAdd(&row1[c], acc[mt][j][2]);
                }
                if (c + 1 < V_) {
                    if (a0) atomicAdd(&row0[c+1], acc[mt][j][1]);
                    if (a1) atomicAdd(&row1[c+1], acc[mt][j][3]);
                }
            }
        }
    }
}

// LSTM pointwise + masked carry commit + bf16 splits
__global__ void __launch_bounds__(256) kE(const int* __restrict__ lengths, int t)
{
    const int b = blockIdx.x;
    const int s = t & 1;
    int dl = lengths[b] - 1; if (dl < 1) dl = 1;
    const bool act = dl > t;
    for (int j = threadIdx.x; j < 512; j += 256) {
        const float* g = g_gates + b*2048;
        const float i_ = g[j], f_ = g[512 + j], gg = g[1024 + j], o_ = g[1536 + j];
        const float c_old = g_c[b*H_ + j];
        const float cn = sigf(f_) * c_old + sigf(i_) * tanhf(gg);
        const float hn = sigf(o_) * tanhf(cn);
        split2(hn, s_hnewh[s][b*H_ + j], s_hnewl[s][b*H_ + j]);
        float hc = g_h[b*H_ + j];
        if (act) {
            g_c[b*H_ + j] = cn;
            hc = hn;
            g_h[b*H_ + j] = hn;
        }
        split2(hc, s_hh[b*H_ + j], s_hl[b*H_ + j]);
    }
}

__global__ void kdeclen(const int* __restrict__ lengths, float* __restrict__ out)
{
    const int b = threadIdx.x;
    if (b < B_) {
        int dl = lengths[b] - 1; if (dl < 1) dl = 1;
        out[(size_t)LOGITS_SZ + ALPHA_SZ + b] = (float)dl;
    }
}

// ---------------- host launcher ----------------
extern "C" void kernel_launch(void* const* d_in, const int* in_sizes, int n_in,
                              void* d_out, int out_size)
{
    const float* ann      = (const float*)d_in[0];
    const int*   captions = (const int*)  d_in[1];
    const int*   lengths  = (const int*)  d_in[2];
    const float* E_emb    = (const float*)d_in[3];
    const float* W_init_h = (const float*)d_in[4];
    const float* b_init_h = (const float*)d_in[5];
    const float* W_init_c = (const float*)d_in[6];
    const float* b_init_c = (const float*)d_in[7];
    const float* W_att_f  = (const float*)d_in[8];
    const float* b_att_f  = (const float*)d_in[9];
    const float* W_att_h  = (const float*)d_in[10];
    const float* b_att_h  = (const float*)d_in[11];
    const float* w_att_v  = (const float*)d_in[12];
    const float* b_att_v  = (const float*)d_in[13];
    const float* W_beta   = (const float*)d_in[14];
    const float* b_beta   = (const float*)d_in[15];
    const float* W_ih     = (const float*)d_in[16];
    const float* W_hh     = (const float*)d_in[17];
    const float* b_ih     = (const float*)d_in[18];
    const float* b_hh     = (const float*)d_in[19];
    const float* W_y      = (const float*)d_in[20];
    const float* W_h      = (const float*)d_in[21];
    const float* W_z      = (const float*)d_in[22];
    const float* W_out    = (const float*)d_in[23];
    const float* b_out    = (const float*)d_in[24];

    float* out = (float*)d_out;

    bf16 *p; bf16 *q;
    // -- weight splits (loop-invariant) --
    #define CONV(SYM_H, SYM_L, SRC, RS, CO, ROWS, GRID) do { \
        cudaGetSymbolAddress((void**)&p, SYM_H); \
        cudaGetSymbolAddress((void**)&q, SYM_L); \
        kConv<<<GRID, 256>>>(SRC, RS, CO, p, q, ROWS); } while (0)

    CONV(w_outh, w_outl, W_out, 512, 0, V_, 512);
    CONV(w_ihah, w_ihal, W_ih, 1024, 0,   2048, 160);
    CONV(w_ihbh, w_ihbl, W_ih, 1024, 512, 2048, 160);
    CONV(w_hhh,  w_hhl,  W_hh,  512, 0,   2048, 160);
    CONV(w_yh,   w_yl,   W_y,   512, 0,   512,  64);
    CONV(w_hh2,  w_hl2,  W_h,   512, 0,   512,  64);
    CONV(w_zh,   w_zl,   W_z,   512, 0,   512,  64);
    CONV(w_atthh, w_atthl, W_att_h, 512, 0, 512, 64);
    CONV(w_betah, w_betal, W_beta,  512, 0, 512, 64);
    CONV(w_attfh, w_attfl, W_att_f, 512, 0, 512, 64);
    CONV(w_inhh,  w_inhl,  W_init_h, 512, 0, 512, 64);
    CONV(w_inch,  w_incl,  W_init_c, 512, 0, 512, 64);
    CONV(s_annh,  s_annl,  ann, 512, 0, B_*L_, 512);
    #undef CONV

    // -- prologue --
    kmean<<<B_, 256>>>(ann, b_init_h, b_init_c);
    kInitT<<<24, 256>>>();
    kTanhHC<<<64, 256>>>();
    kAnnProjT<<<dim3(4, 196), 256>>>(b_att_f);

    // -- pipelined decode loop --
    for (int t = 0; t <= TD; t++) {
        kA<<<228, 256>>>(t, captions, E_emb, b_att_h, b_beta, b_ih, b_hh,
                         b_out, lengths, out);
        kB<<<40, 256>>>(t);
        if (t <= 30)
            kattn<<<B_, 256>>>(ann, w_att_v, b_att_v, lengths, t, out + LOGITS_SZ);
        kD<<<381, 256>>>(t, lengths, out);
        if (t <= 30)
            kE<<<B_, 256>>>(lengths, t);
    }

    kdeclen<<<1, 128>>>(lengths, out);
}

// round 8
// speedup vs baseline: 1.6024x; 1.2549x over previous
#include <cuda_runtime.h>
#include <cuda_bf16.h>
#include <math.h>

typedef __nv_bfloat16 bf16;

// ---------------- problem constants ----------------
#define B_  128
#define L_  196
#define T_  32
#define TD  31
#define F_  512
#define H_  512
#define V_  10000
#define K_  512

#define LOGITS_SZ (B_*TD*V_)
#define ALPHA_SZ  (B_*TD*L_)

// ---------------- fp32 state ----------------
__device__ float g_h    [B_*H_];          // init preact only
__device__ float g_c    [B_*H_];
__device__ float g_hp   [B_*F_];
__device__ float g_gpre [B_*F_];
__device__ float g_gates[2][B_*2048];
__device__ float g_pre  [2][B_*F_];
__device__ float g_annproj[(size_t)B_*L_*F_];

// ---------------- bf16 hi/lo activation buffers ----------------
__device__ bf16 s_meanh[B_*F_],  s_meanl[B_*F_];
__device__ bf16 s_hh[B_*H_],     s_hl[B_*H_];
__device__ bf16 s_embh [2][B_*F_], s_embl [2][B_*F_];
__device__ bf16 s_gctxh[2][B_*F_], s_gctxl[2][B_*F_];
__device__ bf16 s_hnewh[2][B_*H_], s_hnewl[2][B_*H_];
__device__ bf16 s_preh [2][B_*F_], s_prel [2][B_*F_];
__device__ bf16 s_annh[(size_t)B_*L_*F_], s_annl[(size_t)B_*L_*F_];

// ---------------- bf16 hi/lo split weights ----------------
__device__ bf16 w_outh[(size_t)V_*K_], w_outl[(size_t)V_*K_];
__device__ bf16 w_ihah[2048*K_], w_ihal[2048*K_];
__device__ bf16 w_ihbh[2048*K_], w_ihbl[2048*K_];
__device__ bf16 w_hhh [2048*K_], w_hhl [2048*K_];
__device__ bf16 w_yh [512*K_], w_yl [512*K_];
__device__ bf16 w_hh2[512*K_], w_hl2[512*K_];
__device__ bf16 w_zh [512*K_], w_zl [512*K_];
__device__ bf16 w_atthh[512*K_], w_atthl[512*K_];
__device__ bf16 w_betah[512*K_], w_betal[512*K_];
__device__ bf16 w_attfh[512*K_], w_attfl[512*K_];
__device__ bf16 w_inhh[512*K_], w_inhl[512*K_];
__device__ bf16 w_inch[512*K_], w_incl[512*K_];

__device__ __forceinline__ float sigf(float x){ return 1.f/(1.f+expf(-x)); }
__device__ __forceinline__ void split2(float x, bf16& h, bf16& l){
    h = __float2bfloat16(x);
    l = __float2bfloat16(x - __bfloat162float(h));
}

// ---------------- merged 3-region bf16 MMA GEMM core ----------------
// Block 256 thr / 8 warps (4m x 2n). Out tile 128(m) x 64(n), K=512.
// acc = Ah*Wh + Al*Wh + Ah*Wl  (fp32 split-bf16; al*wl dropped, ~2^-16 rel)
// Reg-staged double buffer: ldg(c+1) issued before mma(c).
#define KC    32
#define LDPA  40
#define LDPW  40

struct Tiles {
    bf16 Ah[128*LDPA]; bf16 Al[128*LDPA];
    bf16 Wh[ 64*LDPW]; bf16 Wl[ 64*LDPW];
};   // 30,720 B

#define MMA16816(d, a, b) asm volatile( \
    "mma.sync.aligned.m16n8k16.row.col.f32.bf16.bf16.f32 " \
    "{%0,%1,%2,%3}, {%4,%5,%6,%7}, {%8,%9}, {%0,%1,%2,%3};" \
    : "+f"(d[0]), "+f"(d[1]), "+f"(d[2]), "+f"(d[3]) \
    : "r"(a[0]), "r"(a[1]), "r"(a[2]), "r"(a[3]), "r"(b[0]), "r"(b[1]))

__device__ __forceinline__ void mma_chunk(
    const Tiles* S, float (&acc)[2][4][4], int wm, int wn, int g, int tg)
{
    const unsigned* Ah32 = reinterpret_cast<const unsigned*>(S->Ah);
    const unsigned* Al32 = reinterpret_cast<const unsigned*>(S->Al);
    const unsigned* Wh32 = reinterpret_cast<const unsigned*>(S->Wh);
    const unsigned* Wl32 = reinterpret_cast<const unsigned*>(S->Wl);
    #pragma unroll
    for (int ks = 0; ks < 2; ks++) {
        const int kb = ks * 8;
        unsigned ah[2][4], al[2][4], bh[4][2], bl[4][2];
        #pragma unroll
        for (int mt = 0; mt < 2; mt++) {
            const int m = wm*32 + mt*16 + g;
            const unsigned* p  = Ah32 + m*(LDPA/2) + kb + tg;
            const unsigned* p8 = p + 8*(LDPA/2);
            ah[mt][0] = p[0]; ah[mt][1] = p8[0]; ah[mt][2] = p[4]; ah[mt][3] = p8[4];
            const unsigned* q  = Al32 + m*(LDPA/2) + kb + tg;
            const unsigned* q8 = q + 8*(LDPA/2);
            al[mt][0] = q[0]; al[mt][1] = q8[0]; al[mt][2] = q[4]; al[mt][3] = q8[4];
        }
        #pragma unroll
        for (int j = 0; j < 4; j++) {
            const int n = wn*32 + j*8 + g;
            const unsigned* p = Wh32 + n*(LDPW/2) + kb + tg;
            bh[j][0] = p[0]; bh[j][1] = p[4];
            const unsigned* q = Wl32 + n*(LDPW/2) + kb + tg;
            bl[j][0] = q[0]; bl[j][1] = q[4];
        }
        #pragma unroll
        for (int mt = 0; mt < 2; mt++)
            #pragma unroll
            for (int j = 0; j < 4; j++) {
                MMA16816(acc[mt][j], ah[mt], bh[j]);
                MMA16816(acc[mt][j], al[mt], bh[j]);
                MMA16816(acc[mt][j], ah[mt], bl[j]);
            }
    }
}

__device__ __forceinline__ void core3(
    const bf16* __restrict__ Ah, const bf16* __restrict__ Al,   // 128 x 512
    const bf16* __restrict__ Wh, const bf16* __restrict__ Wl,   // nmax x 512
    int n0, int nmax, float (&acc)[2][4][4], Tiles* S)
{
    const int tid = threadIdx.x;
    const int wid = tid >> 5, lane = tid & 31;
    const int g = lane >> 2, tg = lane & 3;
    const int wm = wid >> 1, wn = wid & 1;

    const int ar = tid >> 1, ac = (tid & 1) * 16;     // A: 2 uint4 per thread
    const int wr = tid >> 2, wc = (tid & 3) * 8;      // W: 1 uint4 per thread
    int wrow = n0 + wr; if (wrow >= nmax) wrow = nmax - 1;

    const uint4* gAh = reinterpret_cast<const uint4*>(Ah + (size_t)ar*K_ + ac);
    const uint4* gAl = reinterpret_cast<const uint4*>(Al + (size_t)ar*K_ + ac);
    const uint4* gWh = reinterpret_cast<const uint4*>(Wh + (size_t)wrow*K_ + wc);
    const uint4* gWl = reinterpret_cast<const uint4*>(Wl + (size_t)wrow*K_ + wc);
    uint4* sAh = reinterpret_cast<uint4*>(S->Ah + ar*LDPA + ac);
    uint4* sAl = reinterpret_cast<uint4*>(S->Al + ar*LDPA + ac);
    uint4* sWh = reinterpret_cast<uint4*>(S->Wh + wr*LDPW + wc);
    uint4* sWl = reinterpret_cast<uint4*>(S->Wl + wr*LDPW + wc);

    uint4 rAh0 = gAh[0], rAh1 = gAh[1];
    uint4 rAl0 = gAl[0], rAl1 = gAl[1];
    uint4 rWh  = gWh[0], rWl  = gWl[0];
    sAh[0] = rAh0; sAh[1] = rAh1;
    sAl[0] = rAl0; sAl[1] = rAl1;
    sWh[0] = rWh;  sWl[0] = rWl;
    __syncthreads();

    #pragma unroll 1
    for (int c = 1; c < K_/KC; c++) {
        const uint4* pAh = gAh + c*4; const uint4* pAl = gAl + c*4;
        rAh0 = pAh[0]; rAh1 = pAh[1];
        rAl0 = pAl[0]; rAl1 = pAl[1];
        rWh = gWh[c*4]; rWl = gWl[c*4];
        mma_chunk(S, acc, wm, wn, g, tg);
        __syncthreads();
        sAh[0] = rAh0; sAh[1] = rAh1;
        sAl[0] = rAl0; sAl[1] = rAl1;
        sWh[0] = rWh;  sWl[0] = rWl;
        __syncthreads();
    }
    mma_chunk(S, acc, wm, wn, g, tg);
}

__device__ __forceinline__ void acc_zero(float (&acc)[2][4][4]) {
    #pragma unroll
    for (int mt = 0; mt < 2; mt++)
        #pragma unroll
        for (int j = 0; j < 4; j++)
            #pragma unroll
            for (int q = 0; q < 4; q++) acc[mt][j][q] = 0.f;
}

// direct store with bias into fp32 C[128][ldc]
__device__ __forceinline__ void epi_store(
    float (&acc)[2][4][4], float* __restrict__ C, int ldc, int n0,
    const float* __restrict__ bias)
{
    const int lane = threadIdx.x & 31, wid = threadIdx.x >> 5;
    const int g = lane >> 2, tg = lane & 3;
    const int wm = wid >> 1, wn = wid & 1;
    #pragma unroll
    for (int mt = 0; mt < 2; mt++) {
        const int r0 = wm*32 + mt*16 + g, r1 = r0 + 8;
        #pragma unroll
        for (int j = 0; j < 4; j++) {
            const int c = n0 + wn*32 + j*8 + 2*tg;
            const float b0 = bias ? bias[c] : 0.f;
            const float b1 = bias ? bias[c+1] : 0.f;
            *reinterpret_cast<float2*>(&C[(size_t)r0*ldc + c]) =
                make_float2(acc[mt][j][0] + b0, acc[mt][j][1] + b1);
            *reinterpret_cast<float2*>(&C[(size_t)r1*ldc + c]) =
                make_float2(acc[mt][j][2] + b0, acc[mt][j][3] + b1);
        }
    }
}

__device__ __forceinline__ void epi_atomic(
    float (&acc)[2][4][4], float* __restrict__ C, int ldc, int n0)
{
    const int lane = threadIdx.x & 31, wid = threadIdx.x >> 5;
    const int g = lane >> 2, tg = lane & 3;
    const int wm = wid >> 1, wn = wid & 1;
    #pragma unroll
    for (int mt = 0; mt < 2; mt++) {
        const int r0 = wm*32 + mt*16 + g, r1 = r0 + 8;
        #pragma unroll
        for (int j = 0; j < 4; j++) {
            const int c = n0 + wn*32 + j*8 + 2*tg;
            atomicAdd(&C[(size_t)r0*ldc + c    ], acc[mt][j][0]);
            atomicAdd(&C[(size_t)r0*ldc + c + 1], acc[mt][j][1]);
            atomicAdd(&C[(size_t)r1*ldc + c    ], acc[mt][j][2]);
            atomicAdd(&C[(size_t)r1*ldc + c + 1], acc[mt][j][3]);
        }
    }
}

// ---------------- fused conversion + mean kernel (one launch) ----------
// jobs: 12 weight splits + ann split + per-b mean/split
__global__ void __launch_bounds__(256) kConvAll(
    const float* __restrict__ W_out, const float* __restrict__ W_ih,
    const float* __restrict__ W_hh,  const float* __restrict__ W_y,
    const float* __restrict__ W_h,   const float* __restrict__ W_z,
    const float* __restrict__ W_att_h, const float* __restrict__ W_beta,
    const float* __restrict__ W_att_f, const float* __restrict__ W_init_h,
    const float* __restrict__ W_init_c, const float* __restrict__ ann)
{
    const int z = blockIdx.x, tid = threadIdx.x;
    const float* src; bf16 *dh, *dl; int rs, co, start;
    if      (z < 2500) { src=W_out; dh=w_outh; dl=w_outl; rs=512; co=0;   start=0; }
    else if (z < 3012) { src=W_ih;  dh=w_ihah; dl=w_ihal; rs=1024;co=0;   start=2500; }
    else if (z < 3524) { src=W_ih;  dh=w_ihbh; dl=w_ihbl; rs=1024;co=512; start=3012; }
    else if (z < 4036) { src=W_hh;  dh=w_hhh;  dl=w_hhl;  rs=512; co=0;   start=3524; }
    else if (z < 4164) { src=W_y;   dh=w_yh;   dl=w_yl;   rs=512; co=0;   start=4036; }
    else if (z < 4292) { src=W_h;   dh=w_hh2;  dl=w_hl2;  rs=512; co=0;   start=4164; }
    else if (z < 4420) { src=W_z;   dh=w_zh;   dl=w_zl;   rs=512; co=0;   start=4292; }
    else if (z < 4548) { src=W_att_h; dh=w_atthh; dl=w_atthl; rs=512; co=0; start=4420; }
    else if (z < 4676) { src=W_beta;  dh=w_betah; dl=w_betal; rs=512; co=0; start=4548; }
    else if (z < 4804) { src=W_att_f; dh=w_attfh; dl=w_attfl; rs=512; co=0; start=4676; }
    else if (z < 4932) { src=W_init_h;dh=w_inhh;  dl=w_inhl;  rs=512; co=0; start=4804; }
    else if (z < 5060) { src=W_init_c;dh=w_inch;  dl=w_incl;  rs=512; co=0; start=4932; }
    else if (z < 11332){ src=ann;     dh=s_annh;  dl=s_annl;  rs=512; co=0; start=5060; }
    else {
        // mean job: one block per b
        const int b = z - 11332;
        for (int f = tid; f < F_; f += 256) {
            const float* p = ann + (size_t)b*L_*F_ + f;
            float s = 0.f;
            #pragma unroll 4
            for (int l = 0; l < L_; l++) s += p[(size_t)l*F_];
            split2(s * (1.f/196.f), s_meanh[b*F_ + f], s_meanl[b*F_ + f]);
        }
        return;
    }
    const int base = (z - start) * 2048;
    #pragma unroll
    for (int it = 0; it < 8; it++) {
        const int idx = base + it*256 + tid;
        const int r = idx >> 9, c = idx & 511;
        split2(src[(size_t)r*rs + co + c], dh[idx], dl[idx]);
    }
}

// h0/c0 preact (direct store + bias): 16 blocks
__global__ void __launch_bounds__(256, 2) kInitT(
    const float* __restrict__ b_init_h, const float* __restrict__ b_init_c)
{
    __shared__ Tiles S;
    const int z = blockIdx.x;
    const int which = z >> 3, nt = z & 7;
    float acc[2][4][4]; acc_zero(acc);
    core3(s_meanh, s_meanl,
          which ? w_inch : w_inhh, which ? w_incl : w_inhl,
          nt*64, 512, acc, &S);
    epi_store(acc, which ? g_c : g_h, 512, nt*64, which ? b_init_c : b_init_h);
}

__global__ void __launch_bounds__(256) kTanhHC() {
    for (int i = blockIdx.x*256 + threadIdx.x; i < B_*H_; i += 64*256) {
        const float h = tanhf(g_h[i]);
        split2(h, s_hh[i], s_hl[i]);
        g_c[i] = tanhf(g_c[i]);
    }
}

// ann_proj: grid (8, 196) -> direct store + bias
__global__ void __launch_bounds__(256, 2) kAnnProjT(const float* __restrict__ b_att_f)
{
    __shared__ Tiles S;
    const int n0 = blockIdx.x * 64;
    const size_t m0 = (size_t)blockIdx.y * 128;
    float acc[2][4][4]; acc_zero(acc);
    core3(s_annh + m0*K_, s_annl + m0*K_, w_attfh, w_attfl, n0, 512, acc, &S);
    epi_store(acc, g_annproj + m0*F_, F_, n0, b_att_f);
}

// ---------------- pipelined step kernels (4 per step) ----------------

// kA: LSTM(t-1) [0,128)  ∪  prep(t) [128,256)
__global__ void __launch_bounds__(256) kA(int t,
    const int* __restrict__ captions, const float* __restrict__ E_emb,
    const float* __restrict__ b_ih, const float* __restrict__ b_hh,
    const int* __restrict__ lengths)
{
    const int z = blockIdx.x, tid = threadIdx.x;
    if (z < 128) {
        if (t == 0) return;
        const int b = z, u = t - 1, su = u & 1;
        int dl = lengths[b] - 1; if (dl < 1) dl = 1;
        const bool act = dl > u;
        const float* g = g_gates[su] + b*2048;
        for (int j = tid; j < 512; j += 256) {
            const float i_ = g[j], f_ = g[512+j], gg = g[1024+j], o_ = g[1536+j];
            const float c_old = g_c[b*H_ + j];
            const float cn = sigf(f_) * c_old + sigf(i_) * tanhf(gg);
            const float hn = sigf(o_) * tanhf(cn);
            split2(hn, s_hnewh[su][b*H_ + j], s_hnewl[su][b*H_ + j]);
            if (act) {
                g_c[b*H_ + j] = cn;
                split2(hn, s_hh[b*H_ + j], s_hl[b*H_ + j]);
            }
        }
    } else {
        if (t > 30) return;
        const int b = z - 128, s = t & 1;
        const int tok = captions[b*T_ + t];
        for (int j = tid; j < 512; j += 256) {
            split2(E_emb[(size_t)tok*512 + j], s_embh[s][b*512 + j], s_embl[s][b*512 + j]);
            g_pre[s][b*512 + j] = 0.f;
            #pragma unroll
            for (int q = 0; q < 4; q++)
                g_gates[s][b*2048 + q*512 + j] = b_ih[q*512 + j] + b_hh[q*512 + j];
        }
    }
}

// kB: hp/gpre(t) [0,16)  ∪  pre-gemm(t-1) [16,40)
__global__ void __launch_bounds__(256, 2) kB(int t,
    const float* __restrict__ b_att_h, const float* __restrict__ b_beta)
{
    __shared__ Tiles S;
    const int z = blockIdx.x;
    if (z < 16) {
        if (t > 30) return;
        const int which = z >> 3, nt = z & 7;
        float acc[2][4][4]; acc_zero(acc);
        core3(s_hh, s_hl,
              which ? w_betah : w_atthh, which ? w_betal : w_atthl,
              nt*64, 512, acc, &S);
        epi_store(acc, which ? g_gpre : g_hp, 512, nt*64,
                  which ? b_beta : b_att_h);
    } else {
        if (t == 0) return;
        const int zz = z - 16, seg = zz >> 3, nt = zz & 7;
        const int s = (t-1) & 1;
        const bf16 *Ah, *Al, *Wh, *Wl;
        if      (seg == 0) { Ah=s_embh[s];  Al=s_embl[s];  Wh=w_yh;  Wl=w_yl;  }
        else if (seg == 1) { Ah=s_hnewh[s]; Al=s_hnewl[s]; Wh=w_hh2; Wl=w_hl2; }
        else               { Ah=s_gctxh[s]; Al=s_gctxl[s]; Wh=w_zh;  Wl=w_zl;  }
        float acc[2][4][4]; acc_zero(acc);
        core3(Ah, Al, Wh, Wl, nt*64, 512, acc, &S);
        epi_atomic(acc, g_pre[s], 512, nt*64);
    }
}

// kattn: attention(t) [0,128)  ∪  tanh+split pre(t-1) [128,144)
__global__ void __launch_bounds__(256) kattn(
    const float* __restrict__ ann,
    const float* __restrict__ w_att_v,
    const float* __restrict__ b_att_v,
    const int*   __restrict__ lengths,
    int t, float* __restrict__ alphas_out)
{
    if (blockIdx.x >= 128) {
        if (t == 0) return;
        const int s = (t-1) & 1;
        for (int i = (blockIdx.x - 128)*256 + threadIdx.x; i < B_*F_; i += 16*256) {
            const float v = tanhf(g_pre[s][i]);
            split2(v, s_preh[s][i], s_prel[s][i]);
        }
        return;
    }
    if (t > 30) return;

    __shared__ float hp_s[F_];
    __shared__ float wv_s[F_];
    __shared__ float sc[L_];
    __shared__ float red[8];
    __shared__ float sval[2];

    const int b = blockIdx.x;
    const int tid = threadIdx.x;
    const int w = tid >> 5, lane = tid & 31;
    const int s = t & 1;

    for (int i = tid; i < F_; i += 256) {
        hp_s[i] = g_hp[b*F_ + i];
        wv_s[i] = w_att_v[i];
    }
    __syncthreads();

    const float bv = b_att_v[0];
    const float* ap = g_annproj + (size_t)b*L_*F_;

    for (int l = w; l < L_; l += 8) {
        const float* row = ap + (size_t)l*F_;
        float sacc = 0.f;
        #pragma unroll 4
        for (int a = lane; a < F_; a += 32)
            sacc += fmaxf(row[a] + hp_s[a], 0.f) * wv_s[a];
        #pragma unroll
        for (int o = 16; o; o >>= 1) sacc += __shfl_down_sync(0xffffffffu, sacc, o);
        if (lane == 0) sc[l] = sacc + bv;
    }
    __syncthreads();

    float mx = -1e30f;
    for (int i = tid; i < L_; i += 256) mx = fmaxf(mx, sc[i]);
    #pragma unroll
    for (int o = 16; o; o >>= 1) mx = fmaxf(mx, __shfl_xor_sync(0xffffffffu, mx, o));
    if (lane == 0) red[w] = mx;
    __syncthreads();
    if (tid == 0) {
        float m = red[0];
        #pragma unroll
        for (int i = 1; i < 8; i++) m = fmaxf(m, red[i]);
        sval[0] = m;
    }
    __syncthreads();
    mx = sval[0];

    float ss = 0.f;
    for (int i = tid; i < L_; i += 256) {
        const float e = expf(sc[i] - mx);
        sc[i] = e;
        ss += e;
    }
    #pragma unroll
    for (int o = 16; o; o >>= 1) ss += __shfl_xor_sync(0xffffffffu, ss, o);
    if (lane == 0) red[w] = ss;
    __syncthreads();
    if (tid == 0) {
        float s2 = 0.f;
        #pragma unroll
        for (int i = 0; i < 8; i++) s2 += red[i];
        sval[1] = s2;
    }
    __syncthreads();
    const float inv = 1.f / sval[1];

    int dl = lengths[b] - 1; if (dl < 1) dl = 1;
    const bool act = dl > t;
    for (int i = tid; i < L_; i += 256) {
        const float a = sc[i] * inv;
        sc[i] = a;
        alphas_out[((size_t)b*TD + t)*L_ + i] = act ? a : 0.f;
    }
    __syncthreads();

    const float* an = ann + (size_t)b*L_*F_;
    for (int f = tid; f < F_; f += 256) {
        float acc = 0.f;
        #pragma unroll 4
        for (int l = 0; l < L_; l++)
            acc = fmaf(sc[l], an[(size_t)l*F_ + f], acc);
        const float gate = sigf(g_gpre[b*F_ + f]);
        split2(gate * acc, s_gctxh[s][b*F_ + f], s_gctxl[s][b*F_ + f]);
    }
}

// kD: gates(t) [0,96)  ∪  logits(t-1) direct-store [96,253)
__global__ void __launch_bounds__(256, 2) kD(int t,
    const float* __restrict__ b_out, const int* __restrict__ lengths,
    float* __restrict__ out)
{
    __shared__ Tiles S;
    const int z = blockIdx.x;
    if (z < 96) {
        if (t > 30) return;
        const int s = t & 1;
        const int seg = z >> 5, nt = z & 31;
        const bf16 *Ah, *Al, *Wh, *Wl;
        if      (seg == 0) { Ah=s_embh[s];  Al=s_embl[s];  Wh=w_ihah; Wl=w_ihal; }
        else if (seg == 1) { Ah=s_gctxh[s]; Al=s_gctxl[s]; Wh=w_ihbh; Wl=w_ihbl; }
        else               { Ah=s_hh;       Al=s_hl;       Wh=w_hhh;  Wl=w_hhl;  }
        float acc[2][4][4]; acc_zero(acc);
        core3(Ah, Al, Wh, Wl, nt*64, 2048, acc, &S);
        epi_atomic(acc, g_gates[s], 2048, nt*64);
    } else {
        if (t == 0) return;
        const int u = t - 1, s = u & 1;
        const int n0 = (z - 96) * 64;
        float acc[2][4][4]; acc_zero(acc);
        core3(s_preh[s], s_prel[s], w_outh, w_outl, n0, V_, acc, &S);

        const int lane = threadIdx.x & 31, wid = threadIdx.x >> 5;
        const int g = lane >> 2, tg = lane & 3;
        const int wm = wid >> 1, wn = wid & 1;
        #pragma unroll
        for (int mt = 0; mt < 2; mt++) {
            const int r0 = wm*32 + mt*16 + g, r1 = r0 + 8;
            int dl0 = lengths[r0] - 1; if (dl0 < 1) dl0 = 1;
            int dl1 = lengths[r1] - 1; if (dl1 < 1) dl1 = 1;
            const bool a0 = dl0 > u, a1 = dl1 > u;
            float* row0 = out + ((size_t)r0*TD + u) * V_;
            float* row1 = out + ((size_t)r1*TD + u) * V_;
            #pragma unroll
            for (int j = 0; j < 4; j++) {
                const int c = n0 + wn*32 + j*8 + 2*tg;
                if (c < V_) {
                    const float b0 = b_out[c], b1 = b_out[c+1];
                    *reinterpret_cast<float2*>(&row0[c]) = a0 ?
                        make_float2(acc[mt][j][0] + b0, acc[mt][j][1] + b1) :
                        make_float2(0.f, 0.f);
                    *reinterpret_cast<float2*>(&row1[c]) = a1 ?
                        make_float2(acc[mt][j][2] + b0, acc[mt][j][3] + b1) :
                        make_float2(0.f, 0.f);
                }
            }
        }
    }
}

__global__ void kdeclen(const int* __restrict__ lengths, float* __restrict__ out)
{
    const int b = threadIdx.x;
    if (b < B_) {
        int dl = lengths[b] - 1; if (dl < 1) dl = 1;
        out[(size_t)LOGITS_SZ + ALPHA_SZ + b] = (float)dl;
    }
}

// ---------------- host launcher ----------------
extern "C" void kernel_launch(void* const* d_in, const int* in_sizes, int n_in,
                              void* d_out, int out_size)
{
    const float* ann      = (const float*)d_in[0];
    const int*   captions = (const int*)  d_in[1];
    const int*   lengths  = (const int*)  d_in[2];
    const float* E_emb    = (const float*)d_in[3];
    const float* W_init_h = (const float*)d_in[4];
    const float* b_init_h = (const float*)d_in[5];
    const float* W_init_c = (const float*)d_in[6];
    const float* b_init_c = (const float*)d_in[7];
    const float* W_att_f  = (const float*)d_in[8];
    const float* b_att_f  = (const float*)d_in[9];
    const float* W_att_h  = (const float*)d_in[10];
    const float* b_att_h  = (const float*)d_in[11];
    const float* w_att_v  = (const float*)d_in[12];
    const float* b_att_v  = (const float*)d_in[13];
    const float* W_beta   = (const float*)d_in[14];
    const float* b_beta   = (const float*)d_in[15];
    const float* W_ih     = (const float*)d_in[16];
    const float* W_hh     = (const float*)d_in[17];
    const float* b_ih     = (const float*)d_in[18];
    const float* b_hh     = (const float*)d_in[19];
    const float* W_y      = (const float*)d_in[20];
    const float* W_h      = (const float*)d_in[21];
    const float* W_z      = (const float*)d_in[22];
    const float* W_out    = (const float*)d_in[23];
    const float* b_out    = (const float*)d_in[24];

    float* out = (float*)d_out;

    // launch 0: all splits + mean    (11332 conv blocks + 128 mean blocks)
    kConvAll<<<11460, 256>>>(W_out, W_ih, W_hh, W_y, W_h, W_z,
                             W_att_h, W_beta, W_att_f, W_init_h, W_init_c, ann);
    // launch 1-2: h0/c0
    kInitT<<<16, 256>>>(b_init_h, b_init_c);
    kTanhHC<<<64, 256>>>();
    // launch 3: step-0 prep (independent of annproj)
    kA<<<256, 256>>>(0, captions, E_emb, b_ih, b_hh, lengths);
    // launch 4: step-0 hp/gpre
    kB<<<40, 256>>>(0, b_att_h, b_beta);
    // launch 5 (PROFILED): ann_proj with the merged-region tensor core
    kAnnProjT<<<dim3(8, 196), 256>>>(b_att_f);
    // step 0 remainder
    kattn<<<144, 256>>>(ann, w_att_v, b_att_v, lengths, 0, out + LOGITS_SZ);
    kD<<<253, 256>>>(0, b_out, lengths, out);

    for (int t = 1; t <= TD; t++) {
        kA<<<256, 256>>>(t, captions, E_emb, b_ih, b_hh, lengths);
        kB<<<40, 256>>>(t, b_att_h, b_beta);
        kattn<<<144, 256>>>(ann, w_att_v, b_att_v, lengths, t, out + LOGITS_SZ);
        kD<<<253, 256>>>(t, b_out, lengths, out);
    }

    kdeclen<<<1, 128>>>(lengths, out);
}

// round 10
// speedup vs baseline: 2.3702x; 1.4791x over previous
#include <cuda_runtime.h>
#include <cuda_bf16.h>
#include <math.h>
#include <stdint.h>

typedef __nv_bfloat16 bf16;

// ---------------- problem constants ----------------
#define B_  128
#define L_  196
#define T_  32
#define TD  31
#define F_  512
#define H_  512
#define V_  10000
#define K_  512

#define LOGITS_SZ (B_*TD*V_)
#define ALPHA_SZ  (B_*TD*L_)

// dynamic smem: 2 stages x 40KB
#define STAGE_B 40960
#define DSM     (2*STAGE_B)

// ---------------- fp32 state ----------------
__device__ float g_h    [B_*H_];
__device__ float g_c    [B_*H_];
__device__ float g_hp   [B_*F_];
__device__ float g_gpre [B_*F_];
__device__ float g_gates[2][B_*2048];
__device__ float g_pre  [2][B_*F_];
__device__ float g_annproj[(size_t)B_*L_*F_];

// ---------------- bf16 hi/lo activations ----------------
__device__ bf16 s_meanh[B_*F_],  s_meanl[B_*F_];
__device__ bf16 s_hh[B_*H_],     s_hl[B_*H_];
__device__ bf16 s_embh [2][B_*F_], s_embl [2][B_*F_];
__device__ bf16 s_gctxh[2][B_*F_], s_gctxl[2][B_*F_];
__device__ bf16 s_hnewh[2][B_*H_], s_hnewl[2][B_*H_];
__device__ bf16 s_preh [2][B_*F_], s_prel [2][B_*F_];
__device__ bf16 s_annh[(size_t)B_*L_*F_], s_annl[(size_t)B_*L_*F_];

// ---------------- bf16 hi/lo weights ----------------
__device__ bf16 w_outh[(size_t)V_*K_], w_outl[(size_t)V_*K_];
__device__ bf16 w_ihah[2048*K_], w_ihal[2048*K_];
__device__ bf16 w_ihbh[2048*K_], w_ihbl[2048*K_];
__device__ bf16 w_hhh [2048*K_], w_hhl [2048*K_];
__device__ bf16 w_yh [512*K_], w_yl [512*K_];
__device__ bf16 w_hh2[512*K_], w_hl2[512*K_];
__device__ bf16 w_zh [512*K_], w_zl [512*K_];
__device__ bf16 w_atthh[512*K_], w_atthl[512*K_];
__device__ bf16 w_betah[512*K_], w_betal[512*K_];
__device__ bf16 w_attfh[512*K_], w_attfl[512*K_];
__device__ bf16 w_inhh[512*K_], w_inhl[512*K_];
__device__ bf16 w_inch[512*K_], w_incl[512*K_];

__device__ __forceinline__ float sigf(float x){ return 1.f/(1.f+expf(-x)); }
__device__ __forceinline__ void split2(float x, bf16& h, bf16& l){
    h = __float2bfloat16(x);
    l = __float2bfloat16(x - __bfloat162float(h));
}
__device__ __forceinline__ uint32_t smem_u32(const void* p){
    uint32_t a;
    asm("{ .reg .u64 t; cvta.to.shared.u64 t, %1; cvt.u32.u64 %0, t; }"
        : "=r"(a) : "l"(p));
    return a;
}

#define MMA16816(d, a, b) asm volatile( \
    "mma.sync.aligned.m16n8k16.row.col.f32.bf16.bf16.f32 " \
    "{%0,%1,%2,%3}, {%4,%5,%6,%7}, {%8,%9}, {%0,%1,%2,%3};" \
    : "+f"(d[0]), "+f"(d[1]), "+f"(d[2]), "+f"(d[3]) \
    : "r"(a[0]), "r"(a[1]), "r"(a[2]), "r"(a[3]), "r"(b[0]), "r"(b[1]))

// ---------------- cp.async pipelined HMMA core ----------------
// Block 256 thr / 8 warps (4m x 2n). Output 128(m) x NJ*16(n). KC=32.
// acc = Ah*Wh + Al*Wh + Ah*Wl  (split-bf16, fp32 accum).
// Stage layout (bytes): Ah 0, Al 10240, Wh 20480, Wl 30720; row pitch 80B.

template<int NJ>
__device__ __forceinline__ void load_stage(
    char* st, const bf16* __restrict__ Ah, const bf16* __restrict__ Al,
    const bf16* __restrict__ Wh, const bf16* __restrict__ Wl,
    int n0, int nmax, int ch)
{
    const int tid = threadIdx.x;
    #pragma unroll
    for (int i = 0; i < 8; i++) {
        const int idx = i*256 + tid;
        const int region = idx >> 9;          // 0:Ah 1:Al 2:Wh 3:Wl
        const int rr = (idx >> 2) & 127;
        const int q = idx & 3;
        const bf16* src;
        if (region == 0)      src = Ah + rr*K_ + ch*32 + q*8;
        else if (region == 1) src = Al + rr*K_ + ch*32 + q*8;
        else {
            if (rr >= NJ*16) continue;        // W tile has NJ*16 rows
            int row = n0 + rr; if (row >= nmax) row = nmax - 1;
            src = ((region == 3) ? Wl : Wh) + (size_t)row*K_ + ch*32 + q*8;
        }
        const uint32_t dst = smem_u32(st + region*10240 + rr*80 + q*16);
        const uint64_t gsrc = (uint64_t)__cvta_generic_to_global(src);
        asm volatile("cp.async.cg.shared.global [%0], [%1], 16;"
                     :: "r"(dst), "l"(gsrc) : "memory");
    }
    asm volatile("cp.async.commit_group;" ::: "memory");
}

template<int NJ>
__device__ __forceinline__ void core_cp(
    const bf16* const* Ahs, const bf16* const* Als,
    const bf16* const* Whs, const bf16* const* Wls,
    int nseg, int n0, int nmax, float (&acc)[2][NJ][4])
{
    extern __shared__ char dynsm[];
    const int tid = threadIdx.x;
    const int wid = tid >> 5, lane = tid & 31;
    const int g = lane >> 2, tg = lane & 3;
    const int wm = wid >> 1, wn = wid & 1;
    const int total = nseg * 16;

    load_stage<NJ>(dynsm,           Ahs[0], Als[0], Whs[0], Wls[0], n0, nmax, 0);
    load_stage<NJ>(dynsm + STAGE_B, Ahs[0], Als[0], Whs[0], Wls[0], n0, nmax, 1);

    for (int c = 0; c < total; c++) {
        if (c + 1 < total) asm volatile("cp.async.wait_group 1;" ::: "memory");
        else               asm volatile("cp.async.wait_group 0;" ::: "memory");
        __syncthreads();
        const unsigned* st32 = (const unsigned*)(dynsm + (c & 1)*STAGE_B);
        #pragma unroll
        for (int ks = 0; ks < 2; ks++) {
            const int kb = ks * 8;
            unsigned bh[NJ][2], ah[2][4], al[2][4], bl[NJ][2];
            #pragma unroll
            for (int j = 0; j < NJ; j++) {
                const unsigned* p = st32 + 5120 + (wn*NJ*8 + j*8 + g)*20 + kb + tg;
                bh[j][0] = p[0]; bh[j][1] = p[4];
            }
            #pragma unroll
            for (int mt = 0; mt < 2; mt++) {
                const unsigned* p = st32 + (wm*32 + mt*16 + g)*20 + kb + tg;
                ah[mt][0] = p[0]; ah[mt][1] = p[160]; ah[mt][2] = p[4]; ah[mt][3] = p[164];
            }
            #pragma unroll
            for (int mt = 0; mt < 2; mt++)
                #pragma unroll
                for (int j = 0; j < NJ; j++) MMA16816(acc[mt][j], ah[mt], bh[j]);
            #pragma unroll
            for (int mt = 0; mt < 2; mt++) {
                const unsigned* p = st32 + 2560 + (wm*32 + mt*16 + g)*20 + kb + tg;
                al[mt][0] = p[0]; al[mt][1] = p[160]; al[mt][2] = p[4]; al[mt][3] = p[164];
            }
            #pragma unroll
            for (int mt = 0; mt < 2; mt++)
                #pragma unroll
                for (int j = 0; j < NJ; j++) MMA16816(acc[mt][j], al[mt], bh[j]);
            #pragma unroll
            for (int j = 0; j < NJ; j++) {
                const unsigned* p = st32 + 7680 + (wn*NJ*8 + j*8 + g)*20 + kb + tg;
                bl[j][0] = p[0]; bl[j][1] = p[4];
            }
            #pragma unroll
            for (int mt = 0; mt < 2; mt++)
                #pragma unroll
                for (int j = 0; j < NJ; j++) MMA16816(acc[mt][j], ah[mt], bl[j]);
        }
        if (c + 2 < total) {
            __syncthreads();
            const int tc = c + 2;
            load_stage<NJ>(dynsm + (c & 1)*STAGE_B,
                Ahs[tc >> 4], Als[tc >> 4], Whs[tc >> 4], Wls[tc >> 4],
                n0, nmax, tc & 15);
        }
    }
}

template<int NJ>
__device__ __forceinline__ void acc_zero(float (&acc)[2][NJ][4]) {
    #pragma unroll
    for (int mt = 0; mt < 2; mt++)
        #pragma unroll
        for (int j = 0; j < NJ; j++)
            #pragma unroll
            for (int q = 0; q < 4; q++) acc[mt][j][q] = 0.f;
}

template<int NJ>
__device__ __forceinline__ void epi_store(
    float (&acc)[2][NJ][4], float* __restrict__ C, int ldc, int n0,
    const float* __restrict__ bias)
{
    const int lane = threadIdx.x & 31, wid = threadIdx.x >> 5;
    const int g = lane >> 2, tg = lane & 3;
    const int wm = wid >> 1, wn = wid & 1;
    #pragma unroll
    for (int mt = 0; mt < 2; mt++) {
        const int r0 = wm*32 + mt*16 + g, r1 = r0 + 8;
        #pragma unroll
        for (int j = 0; j < NJ; j++) {
            const int c = n0 + wn*NJ*8 + j*8 + 2*tg;
            const float b0 = bias ? bias[c] : 0.f;
            const float b1 = bias ? bias[c+1] : 0.f;
            *reinterpret_cast<float2*>(&C[(size_t)r0*ldc + c]) =
                make_float2(acc[mt][j][0] + b0, acc[mt][j][1] + b1);
            *reinterpret_cast<float2*>(&C[(size_t)r1*ldc + c]) =
                make_float2(acc[mt][j][2] + b0, acc[mt][j][3] + b1);
        }
    }
}

template<int NJ>
__device__ __forceinline__ void epi_atomic(
    float (&acc)[2][NJ][4], float* __restrict__ C, int ldc, int n0)
{
    const int lane = threadIdx.x & 31, wid = threadIdx.x >> 5;
    const int g = lane >> 2, tg = lane & 3;
    const int wm = wid >> 1, wn = wid & 1;
    #pragma unroll
    for (int mt = 0; mt < 2; mt++) {
        const int r0 = wm*32 + mt*16 + g, r1 = r0 + 8;
        #pragma unroll
        for (int j = 0; j < NJ; j++) {
            const int c = n0 + wn*NJ*8 + j*8 + 2*tg;
            atomicAdd(&C[(size_t)r0*ldc + c    ], acc[mt][j][0]);
            atomicAdd(&C[(size_t)r0*ldc + c + 1], acc[mt][j][1]);
            atomicAdd(&C[(size_t)r1*ldc + c    ], acc[mt][j][2]);
            atomicAdd(&C[(size_t)r1*ldc + c + 1], acc[mt][j][3]);
        }
    }
}

// ---------------- prologue kernels ----------------

__global__ void __launch_bounds__(256) kConvAll(
    const float* __restrict__ W_out, const float* __restrict__ W_ih,
    const float* __restrict__ W_hh,  const float* __restrict__ W_y,
    const float* __restrict__ W_h,   const float* __restrict__ W_z,
    const float* __restrict__ W_att_h, const float* __restrict__ W_beta,
    const float* __restrict__ W_att_f, const float* __restrict__ W_init_h,
    const float* __restrict__ W_init_c, const float* __restrict__ ann)
{
    const int z = blockIdx.x, tid = threadIdx.x;
    const float* src; bf16 *dh, *dl; int rs, co, start;
    if      (z < 2500) { src=W_out; dh=w_outh; dl=w_outl; rs=512; co=0;   start=0; }
    else if (z < 3012) { src=W_ih;  dh=w_ihah; dl=w_ihal; rs=1024;co=0;   start=2500; }
    else if (z < 3524) { src=W_ih;  dh=w_ihbh; dl=w_ihbl; rs=1024;co=512; start=3012; }
    else if (z < 4036) { src=W_hh;  dh=w_hhh;  dl=w_hhl;  rs=512; co=0;   start=3524; }
    else if (z < 4164) { src=W_y;   dh=w_yh;   dl=w_yl;   rs=512; co=0;   start=4036; }
    else if (z < 4292) { src=W_h;   dh=w_hh2;  dl=w_hl2;  rs=512; co=0;   start=4164; }
    else if (z < 4420) { src=W_z;   dh=w_zh;   dl=w_zl;   rs=512; co=0;   start=4292; }
    else if (z < 4548) { src=W_att_h; dh=w_atthh; dl=w_atthl; rs=512; co=0; start=4420; }
    else if (z < 4676) { src=W_beta;  dh=w_betah; dl=w_betal; rs=512; co=0; start=4548; }
    else if (z < 4804) { src=W_att_f; dh=w_attfh; dl=w_attfl; rs=512; co=0; start=4676; }
    else if (z < 4932) { src=W_init_h;dh=w_inhh;  dl=w_inhl;  rs=512; co=0; start=4804; }
    else if (z < 5060) { src=W_init_c;dh=w_inch;  dl=w_incl;  rs=512; co=0; start=4932; }
    else if (z < 11332){ src=ann;     dh=s_annh;  dl=s_annl;  rs=512; co=0; start=5060; }
    else {
        const int b = z - 11332;
        for (int f = tid; f < F_; f += 256) {
            const float* p = ann + (size_t)b*L_*F_ + f;
            float s = 0.f;
            #pragma unroll 4
            for (int l = 0; l < L_; l++) s += p[(size_t)l*F_];
            split2(s * (1.f/196.f), s_meanh[b*F_ + f], s_meanl[b*F_ + f]);
        }
        return;
    }
    const int bse = (z - start) * 2048;
    #pragma unroll
    for (int it = 0; it < 8; it++) {
        const int idx = bse + it*256 + tid;
        const int r = idx >> 9, c = idx & 511;
        split2(src[(size_t)r*rs + co + c], dh[idx], dl[idx]);
    }
}

// h0/c0 preact: 16 blocks, NJ=4
__global__ void __launch_bounds__(256) kInitT(
    const float* __restrict__ b_init_h, const float* __restrict__ b_init_c)
{
    const int z = blockIdx.x;
    const int which = z >> 3, n0 = (z & 7) * 64;
    const bf16* Ahs[1] = { s_meanh };
    const bf16* Als[1] = { s_meanl };
    const bf16* Whs[1] = { which ? w_inch : w_inhh };
    const bf16* Wls[1] = { which ? w_incl : w_inhl };
    float acc[2][4][4]; acc_zero<4>(acc);
    core_cp<4>(Ahs, Als, Whs, Wls, 1, n0, 512, acc);
    epi_store<4>(acc, which ? g_c : g_h, 512, n0, which ? b_init_c : b_init_h);
}

__global__ void __launch_bounds__(256) kTanhHC() {
    for (int i = blockIdx.x*256 + threadIdx.x; i < B_*H_; i += 64*256) {
        const float h = tanhf(g_h[i]);
        split2(h, s_hh[i], s_hl[i]);
        g_c[i] = tanhf(g_c[i]);
    }
}

// ann_proj: 196 m-tiles x 4 n-tiles = 784 blocks, NJ=8  (PROFILED at idx 3)
__global__ void __launch_bounds__(256) kAnnProj(const float* __restrict__ b_att_f)
{
    const int z = blockIdx.x;
    const size_t m0 = (size_t)(z >> 2) * 128;
    const int n0 = (z & 3) * 128;
    const bf16* Ahs[1] = { s_annh + m0*K_ };
    const bf16* Als[1] = { s_annl + m0*K_ };
    const bf16* Whs[1] = { w_attfh };
    const bf16* Wls[1] = { w_attfl };
    float acc[2][8][4]; acc_zero<8>(acc);
    core_cp<8>(Ahs, Als, Whs, Wls, 1, n0, 512, acc);
    epi_store<8>(acc, g_annproj + m0*F_, F_, n0, b_att_f);
}

// ---------------- step kernels (4 launches/step) ----------------

// kA: LSTM(t-1) [0,128)  ∪  prep(t) [128,256)
__global__ void __launch_bounds__(256) kA(int t,
    const int* __restrict__ captions, const float* __restrict__ E_emb,
    const float* __restrict__ b_ih, const float* __restrict__ b_hh,
    const int* __restrict__ lengths)
{
    const int z = blockIdx.x, tid = threadIdx.x;
    if (z < 128) {
        if (t == 0) return;
        const int b = z, u = t - 1, su = u & 1;
        int dl = lengths[b] - 1; if (dl < 1) dl = 1;
        const bool act = dl > u;
        const float* gg_ = g_gates[su] + b*2048;
        for (int j = tid; j < 512; j += 256) {
            const float i_ = gg_[j], f_ = gg_[512+j], ggv = gg_[1024+j], o_ = gg_[1536+j];
            const float c_old = g_c[b*H_ + j];
            const float cn = sigf(f_) * c_old + sigf(i_) * tanhf(ggv);
            const float hn = sigf(o_) * tanhf(cn);
            split2(hn, s_hnewh[su][b*H_ + j], s_hnewl[su][b*H_ + j]);
            if (act) {
                g_c[b*H_ + j] = cn;
                split2(hn, s_hh[b*H_ + j], s_hl[b*H_ + j]);
            }
        }
    } else {
        if (t > 30) return;
        const int b = z - 128, s = t & 1;
        const int tok = captions[b*T_ + t];
        for (int j = tid; j < 512; j += 256) {
            split2(E_emb[(size_t)tok*512 + j], s_embh[s][b*512 + j], s_embl[s][b*512 + j]);
            g_pre[s][b*512 + j] = 0.f;
            #pragma unroll
            for (int q = 0; q < 4; q++)
                g_gates[s][b*2048 + q*512 + j] = b_ih[q*512 + j] + b_hh[q*512 + j];
        }
    }
}

// kB: hp/gpre(t) [0,16) direct  ∪  pre-gemm(t-1) [16,40) atomic   (NJ=4)
__global__ void __launch_bounds__(256) kB(int t,
    const float* __restrict__ b_att_h, const float* __restrict__ b_beta)
{
    const int z = blockIdx.x;
    if (z < 16) {
        if (t > 30) return;
        const int which = z >> 3, n0 = (z & 7) * 64;
        const bf16* Ahs[1] = { s_hh };
        const bf16* Als[1] = { s_hl };
        const bf16* Whs[1] = { which ? w_betah : w_atthh };
        const bf16* Wls[1] = { which ? w_betal : w_atthl };
        float acc[2][4][4]; acc_zero<4>(acc);
        core_cp<4>(Ahs, Als, Whs, Wls, 1, n0, 512, acc);
        epi_store<4>(acc, which ? g_gpre : g_hp, 512, n0,
                     which ? b_beta : b_att_h);
    } else {
        if (t == 0) return;
        const int zz = z - 16, seg = zz >> 3, n0 = (zz & 7) * 64;
        const int s = (t-1) & 1;
        const bf16 *Ah, *Al, *Wh, *Wl;
        if      (seg == 0) { Ah=s_embh[s];  Al=s_embl[s];  Wh=w_yh;  Wl=w_yl;  }
        else if (seg == 1) { Ah=s_hnewh[s]; Al=s_hnewl[s]; Wh=w_hh2; Wl=w_hl2; }
        else               { Ah=s_gctxh[s]; Al=s_gctxl[s]; Wh=w_zh;  Wl=w_zl;  }
        const bf16* Ahs[1] = { Ah };
        const bf16* Als[1] = { Al };
        const bf16* Whs[1] = { Wh };
        const bf16* Wls[1] = { Wl };
        float acc[2][4][4]; acc_zero<4>(acc);
        core_cp<4>(Ahs, Als, Whs, Wls, 1, n0, 512, acc);
        epi_atomic<4>(acc, g_pre[s], 512, n0);
    }
}

// kattn: attention(t) [0,128) (512 thr)  ∪  tanh+split pre(t-1) [128,144)
__global__ void __launch_bounds__(512) kattn(
    const float* __restrict__ ann,
    const float* __restrict__ w_att_v,
    const float* __restrict__ b_att_v,
    const int*   __restrict__ lengths,
    int t, float* __restrict__ alphas_out)
{
    if (blockIdx.x >= 128) {
        if (t == 0) return;
        const int s = (t-1) & 1;
        for (int i = (blockIdx.x - 128)*512 + threadIdx.x; i < B_*F_; i += 16*512) {
            const float v = tanhf(g_pre[s][i]);
            split2(v, s_preh[s][i], s_prel[s][i]);
        }
        return;
    }
    if (t > 30) return;

    __shared__ float hp_s[F_];
    __shared__ float wv_s[F_];
    __shared__ float sc[L_];
    __shared__ float red[16];
    __shared__ float sval[2];

    const int b = blockIdx.x;
    const int tid = threadIdx.x;
    const int w = tid >> 5, lane = tid & 31;
    const int s = t & 1;

    if (tid < F_) {
        hp_s[tid] = g_hp[b*F_ + tid];
        wv_s[tid] = w_att_v[tid];
    }
    __syncthreads();

    const float bv = b_att_v[0];
    const float* ap = g_annproj + (size_t)b*L_*F_;

    for (int l = w; l < L_; l += 16) {
        const float* row = ap + (size_t)l*F_;
        float sacc = 0.f;
        #pragma unroll 4
        for (int a = lane; a < F_; a += 32)
            sacc += fmaxf(row[a] + hp_s[a], 0.f) * wv_s[a];
        #pragma unroll
        for (int o = 16; o; o >>= 1) sacc += __shfl_down_sync(0xffffffffu, sacc, o);
        if (lane == 0) sc[l] = sacc + bv;
    }
    __syncthreads();

    float mx = -1e30f;
    if (tid < L_) mx = sc[tid];
    #pragma unroll
    for (int o = 16; o; o >>= 1) mx = fmaxf(mx, __shfl_xor_sync(0xffffffffu, mx, o));
    if (lane == 0) red[w] = mx;
    __syncthreads();
    if (tid == 0) {
        float m = red[0];
        #pragma unroll
        for (int i = 1; i < 16; i++) m = fmaxf(m, red[i]);
        sval[0] = m;
    }
    __syncthreads();
    mx = sval[0];

    float ss = 0.f;
    if (tid < L_) {
        const float e = expf(sc[tid] - mx);
        sc[tid] = e;
        ss = e;
    }
    #pragma unroll
    for (int o = 16; o; o >>= 1) ss += __shfl_xor_sync(0xffffffffu, ss, o);
    if (lane == 0) red[w] = ss;
    __syncthreads();
    if (tid == 0) {
        float s2 = 0.f;
        #pragma unroll
        for (int i = 0; i < 16; i++) s2 += red[i];
        sval[1] = s2;
    }
    __syncthreads();
    const float inv = 1.f / sval[1];

    int dl = lengths[b] - 1; if (dl < 1) dl = 1;
    const bool act = dl > t;
    if (tid < L_) {
        const float a = sc[tid] * inv;
        sc[tid] = a;
        alphas_out[((size_t)b*TD + t)*L_ + tid] = act ? a : 0.f;
    }
    __syncthreads();

    // context: one f per thread
    const float* an = ann + (size_t)b*L_*F_;
    const int f = tid;
    float acc = 0.f;
    #pragma unroll 4
    for (int l = 0; l < L_; l++)
        acc = fmaf(sc[l], an[(size_t)l*F_ + f], acc);
    const float gate = sigf(g_gpre[b*F_ + f]);
    split2(gate * acc, s_gctxh[s][b*F_ + f], s_gctxl[s][b*F_ + f]);
}

// kD: gates(t) atomic [0,48)  ∪  logits(t-1) direct [48,127)   (NJ=8)
__global__ void __launch_bounds__(256) kD(int t,
    const float* __restrict__ b_out, const int* __restrict__ lengths,
    float* __restrict__ out)
{
    const int z = blockIdx.x;
    if (z < 48) {
        if (t > 30) return;
        const int s = t & 1;
        const int seg = z >> 4, n0 = (z & 15) * 128;
        const bf16 *Ah, *Al, *Wh, *Wl;
        if      (seg == 0) { Ah=s_embh[s];  Al=s_embl[s];  Wh=w_ihah; Wl=w_ihal; }
        else if (seg == 1) { Ah=s_gctxh[s]; Al=s_gctxl[s]; Wh=w_ihbh; Wl=w_ihbl; }
        else               { Ah=s_hh;       Al=s_hl;       Wh=w_hhh;  Wl=w_hhl;  }
        const bf16* Ahs[1] = { Ah };
        const bf16* Als[1] = { Al };
        const bf16* Whs[1] = { Wh };
        const bf16* Wls[1] = { Wl };
        float acc[2][8][4]; acc_zero<8>(acc);
        core_cp<8>(Ahs, Als, Whs, Wls, 1, n0, 2048, acc);
        epi_atomic<8>(acc, g_gates[s], 2048, n0);
    } else {
        if (t == 0) return;
        const int u = t - 1, s = u & 1;
        const int n0 = (z - 48) * 128;
        const bf16* Ahs[1] = { s_preh[s] };
        const bf16* Als[1] = { s_prel[s] };
        const bf16* Whs[1] = { w_outh };
        const bf16* Wls[1] = { w_outl };
        float acc[2][8][4]; acc_zero<8>(acc);
        core_cp<8>(Ahs, Als, Whs, Wls, 1, n0, V_, acc);

        const int lane = threadIdx.x & 31, wid = threadIdx.x >> 5;
        const int g = lane >> 2, tg = lane & 3;
        const int wm = wid >> 1, wn = wid & 1;
        #pragma unroll
        for (int mt = 0; mt < 2; mt++) {
            const int r0 = wm*32 + mt*16 + g, r1 = r0 + 8;
            int dl0 = lengths[r0] - 1; if (dl0 < 1) dl0 = 1;
            int dl1 = lengths[r1] - 1; if (dl1 < 1) dl1 = 1;
            const bool a0 = dl0 > u, a1 = dl1 > u;
            float* row0 = out + ((size_t)r0*TD + u) * V_;
            float* row1 = out + ((size_t)r1*TD + u) * V_;
            #pragma unroll
            for (int j = 0; j < 8; j++) {
                const int c = n0 + wn*64 + j*8 + 2*tg;
                if (c < V_) {
                    const float b0 = b_out[c], b1 = b_out[c+1];
                    *reinterpret_cast<float2*>(&row0[c]) = a0 ?
                        make_float2(acc[mt][j][0] + b0, acc[mt][j][1] + b1) :
                        make_float2(0.f, 0.f);
                    *reinterpret_cast<float2*>(&row1[c]) = a1 ?
                        make_float2(acc[mt][j][2] + b0, acc[mt][j][3] + b1) :
                        make_float2(0.f, 0.f);
                }
            }
        }
    }
}

__global__ void kdeclen(const int* __restrict__ lengths, float* __restrict__ out)
{
    const int b = threadIdx.x;
    if (b < B_) {
        int dl = lengths[b] - 1; if (dl < 1) dl = 1;
        out[(size_t)LOGITS_SZ + ALPHA_SZ + b] = (float)dl;
    }
}

// ---------------- host launcher ----------------
extern "C" void kernel_launch(void* const* d_in, const int* in_sizes, int n_in,
                              void* d_out, int out_size)
{
    const float* ann      = (const float*)d_in[0];
    const int*   captions = (const int*)  d_in[1];
    const int*   lengths  = (const int*)  d_in[2];
    const float* E_emb    = (const float*)d_in[3];
    const float* W_init_h = (const float*)d_in[4];
    const float* b_init_h = (const float*)d_in[5];
    const float* W_init_c = (const float*)d_in[6];
    const float* b_init_c = (const float*)d_in[7];
    const float* W_att_f  = (const float*)d_in[8];
    const float* b_att_f  = (const float*)d_in[9];
    const float* W_att_h  = (const float*)d_in[10];
    const float* b_att_h  = (const float*)d_in[11];
    const float* w_att_v  = (const float*)d_in[12];
    const float* b_att_v  = (const float*)d_in[13];
    const float* W_beta   = (const float*)d_in[14];
    const float* b_beta   = (const float*)d_in[15];
    const float* W_ih     = (const float*)d_in[16];
    const float* W_hh     = (const float*)d_in[17];
    const float* b_ih     = (const float*)d_in[18];
    const float* b_hh     = (const float*)d_in[19];
    const float* W_y      = (const float*)d_in[20];
    const float* W_h      = (const float*)d_in[21];
    const float* W_z      = (const float*)d_in[22];
    const float* W_out    = (const float*)d_in[23];
    const float* b_out    = (const float*)d_in[24];

    float* out = (float*)d_out;

    cudaFuncSetAttribute(kInitT,   cudaFuncAttributeMaxDynamicSharedMemorySize, DSM);
    cudaFuncSetAttribute(kAnnProj, cudaFuncAttributeMaxDynamicSharedMemorySize, DSM);
    cudaFuncSetAttribute(kB,       cudaFuncAttributeMaxDynamicSharedMemorySize, DSM);
    cudaFuncSetAttribute(kD,       cudaFuncAttributeMaxDynamicSharedMemorySize, DSM);

    // prologue (kAnnProj at launch index 3 -> profiled)
    kConvAll<<<11460, 256>>>(W_out, W_ih, W_hh, W_y, W_h, W_z,
                             W_att_h, W_beta, W_att_f, W_init_h, W_init_c, ann);
    kInitT<<<16, 256, DSM>>>(b_init_h, b_init_c);
    kTanhHC<<<64, 256>>>();
    kAnnProj<<<784, 256, DSM>>>(b_att_f);

    // pipelined decode loop (4 launches/step)
    for (int t = 0; t <= TD; t++) {
        kA<<<256, 256>>>(t, captions, E_emb, b_ih, b_hh, lengths);
        kB<<<40, 256, DSM>>>(t, b_att_h, b_beta);
        kattn<<<144, 512>>>(ann, w_att_v, b_att_v, lengths, t, out + LOGITS_SZ);
        kD<<<127, 256, DSM>>>(t, b_out, lengths, out);
    }

    kdeclen<<<1, 128>>>(lengths, out);
}

// round 11
// speedup vs baseline: 2.4210x; 1.0214x over previous
#include <cuda_runtime.h>
#include <cuda_bf16.h>
#include <math.h>
#include <stdint.h>

typedef __nv_bfloat16 bf16;

// ---------------- problem constants ----------------
#define B_  128
#define L_  196
#define T_  32
#define TD  31
#define F_  512
#define H_  512
#define V_  10000
#define K_  512

#define LOGITS_SZ (B_*TD*V_)
#define ALPHA_SZ  (B_*TD*L_)

// ---------------- fp32 state ----------------
__device__ float g_h    [B_*H_];
__device__ float g_c    [B_*H_];
__device__ float g_hp   [B_*F_];
__device__ float g_gpre [B_*F_];
__device__ float g_gates[2][B_*2048];
__device__ float g_pre  [2][B_*F_];
__device__ float g_annproj[(size_t)B_*L_*F_];

// ---------------- bf16 hi/lo activations ----------------
__device__ bf16 s_meanh[B_*F_],  s_meanl[B_*F_];
__device__ bf16 s_hh[B_*H_],     s_hl[B_*H_];
__device__ bf16 s_embh [2][B_*F_], s_embl [2][B_*F_];
__device__ bf16 s_gctxh[2][B_*F_], s_gctxl[2][B_*F_];
__device__ bf16 s_hnewh[2][B_*H_], s_hnewl[2][B_*H_];
__device__ bf16 s_preh [2][B_*F_], s_prel [2][B_*F_];
__device__ bf16 s_annh[(size_t)B_*L_*F_], s_annl[(size_t)B_*L_*F_];

// ---------------- bf16 hi/lo weights ----------------
__device__ bf16 w_outh[(size_t)V_*K_], w_outl[(size_t)V_*K_];
__device__ bf16 w_ihah[2048*K_], w_ihal[2048*K_];
__device__ bf16 w_ihbh[2048*K_], w_ihbl[2048*K_];
__device__ bf16 w_hhh [2048*K_], w_hhl [2048*K_];
__device__ bf16 w_yh [512*K_], w_yl [512*K_];
__device__ bf16 w_hh2[512*K_], w_hl2[512*K_];
__device__ bf16 w_zh [512*K_], w_zl [512*K_];
__device__ bf16 w_atthh[512*K_], w_atthl[512*K_];
__device__ bf16 w_betah[512*K_], w_betal[512*K_];
__device__ bf16 w_attfh[512*K_], w_attfl[512*K_];
__device__ bf16 w_inhh[512*K_], w_inhl[512*K_];
__device__ bf16 w_inch[512*K_], w_incl[512*K_];

__device__ __forceinline__ float sigf(float x){ return 1.f/(1.f+expf(-x)); }
__device__ __forceinline__ void split2(float x, bf16& h, bf16& l){
    h = __float2bfloat16(x);
    l = __float2bfloat16(x - __bfloat162float(h));
}
__device__ __forceinline__ uint32_t smem_u32(const void* p){
    uint32_t a;
    asm("{ .reg .u64 t; cvta.to.shared.u64 t, %1; cvt.u32.u64 %0, t; }"
        : "=r"(a) : "l"(p));
    return a;
}

#define MMA16816(d, a, b) asm volatile( \
    "mma.sync.aligned.m16n8k16.row.col.f32.bf16.bf16.f32 " \
    "{%0,%1,%2,%3}, {%4,%5,%6,%7}, {%8,%9}, {%0,%1,%2,%3};" \
    : "+f"(d[0]), "+f"(d[1]), "+f"(d[2]), "+f"(d[3]) \
    : "r"(a[0]), "r"(a[1]), "r"(a[2]), "r"(a[3]), "r"(b[0]), "r"(b[1]))

#define LDSM4(r0, r1, r2, r3, addr) asm volatile( \
    "ldmatrix.sync.aligned.m8n8.x4.shared.b16 {%0,%1,%2,%3}, [%4];" \
    : "=r"(r0), "=r"(r1), "=r"(r2), "=r"(r3) : "r"(addr))

// ---------------- cp.async + ldmatrix pipelined HMMA core ----------------
// Block 256 thr / 8 warps (4m x 2n). Output 128(m) x NJ*16(n). KC=32.
// acc = Ah*Wh + Al*Wh + Ah*Wl (split-bf16, fp32 accum).
// Stage layout (bytes, pitch 80/row, 64B valid):
//   Ah 0, Al 10240, Wh 20480, Wl 20480+NJ*1280.  Stage = 20480 + NJ*2560.
// 3 stages, one __syncthreads per chunk.

template<int NJ>
__device__ __forceinline__ void load_stage(
    char* st, const bf16* __restrict__ Ah, const bf16* __restrict__ Al,
    const bf16* __restrict__ Wh, const bf16* __restrict__ Wl,
    int n0, int nmax, int ch)
{
    const int tid = threadIdx.x;
    constexpr int WC  = NJ*64;          // 16B-copies per W region
    constexpr int TOT = 1024 + 2*WC;
    #pragma unroll
    for (int i = 0; i < (TOT + 255)/256; i++) {
        const int idx = i*256 + tid;
        if (idx < TOT) {
            const bf16* src; uint32_t dst;
            if (idx < 1024) {
                const int half = idx >> 9;                 // 0=Ah 1=Al
                const int rr = (idx >> 2) & 127, q = idx & 3;
                src = (half ? Al : Ah) + (size_t)rr*K_ + ch*32 + q*8;
                dst = smem_u32(st + half*10240 + rr*80 + q*16);
            } else {
                const int w = idx - 1024;
                const int half = (w >= WC) ? 1 : 0;
                const int ww = half ? w - WC : w;
                const int rr = ww >> 2, q = ww & 3;
                int row = n0 + rr; if (row >= nmax) row = nmax - 1;
                src = (half ? Wl : Wh) + (size_t)row*K_ + ch*32 + q*8;
                dst = smem_u32(st + 20480 + half*(NJ*1280) + rr*80 + q*16);
            }
            asm volatile("cp.async.cg.shared.global [%0], [%1], 16;"
                         :: "r"(dst), "l"((uint64_t)__cvta_generic_to_global(src))
                         : "memory");
        }
    }
    asm volatile("cp.async.commit_group;" ::: "memory");
}

template<int NJ>
__device__ __forceinline__ void mma_chunk(
    uint32_t sb, uint32_t aoff, uint32_t boff, float (&acc)[2][NJ][4])
{
    #pragma unroll
    for (int ks = 0; ks < 2; ks++) {
        const uint32_t ko = ks*32;
        unsigned ah[2][4], al[2][4], bh[NJ][2], bl[NJ][2];
        #pragma unroll
        for (int mt = 0; mt < 2; mt++) {
            LDSM4(ah[mt][0], ah[mt][1], ah[mt][2], ah[mt][3],
                  sb + aoff + mt*1280 + ko);
            LDSM4(al[mt][0], al[mt][1], al[mt][2], al[mt][3],
                  sb + 10240 + aoff + mt*1280 + ko);
        }
        #pragma unroll
        for (int jp = 0; jp < NJ/2; jp++) {
            LDSM4(bh[2*jp][0], bh[2*jp][1], bh[2*jp+1][0], bh[2*jp+1][1],
                  sb + boff + jp*1280 + ko);
            LDSM4(bl[2*jp][0], bl[2*jp][1], bl[2*jp+1][0], bl[2*jp+1][1],
                  sb + boff + NJ*1280 + jp*1280 + ko);
        }
        #pragma unroll
        for (int mt = 0; mt < 2; mt++)
            #pragma unroll
            for (int j = 0; j < NJ; j++) MMA16816(acc[mt][j], ah[mt], bh[j]);
        #pragma unroll
        for (int mt = 0; mt < 2; mt++)
            #pragma unroll
            for (int j = 0; j < NJ; j++) MMA16816(acc[mt][j], al[mt], bh[j]);
        #pragma unroll
        for (int mt = 0; mt < 2; mt++)
            #pragma unroll
            for (int j = 0; j < NJ; j++) MMA16816(acc[mt][j], ah[mt], bl[j]);
    }
}

template<int NJ>
__device__ __forceinline__ void core_cp(
    const bf16* const* Ahs, const bf16* const* Als,
    const bf16* const* Whs, const bf16* const* Wls,
    int nseg, int n0, int nmax, float (&acc)[2][NJ][4])
{
    extern __shared__ char dynsm[];
    constexpr int STG = 20480 + NJ*2560;
    const int tid = threadIdx.x;
    const int wid = tid >> 5, lane = tid & 31;
    const int wm = wid >> 1, wn = wid & 1;
    const uint32_t sb0 = smem_u32(dynsm);
    const uint32_t aoff = (uint32_t)((wm*32 + (lane & 15))*80 + ((lane >> 4) & 1)*16);
    const uint32_t boff = (uint32_t)(20480 +
        (wn*(NJ*8) + ((lane >> 4) & 1)*8 + (lane & 7))*80 + ((lane >> 3) & 1)*16);
    const int total = nseg * 16;

    load_stage<NJ>(dynsm,       Ahs[0], Als[0], Whs[0], Wls[0], n0, nmax, 0);
    load_stage<NJ>(dynsm + STG, Ahs[0], Als[0], Whs[0], Wls[0], n0, nmax, 1);

    for (int c = 0; c < total; c++) {
        if (c + 1 < total) asm volatile("cp.async.wait_group 1;" ::: "memory");
        else               asm volatile("cp.async.wait_group 0;" ::: "memory");
        __syncthreads();
        if (c + 2 < total) {
            const int tc = c + 2;
            load_stage<NJ>(dynsm + (tc % 3)*STG,
                Ahs[tc >> 4], Als[tc >> 4], Whs[tc >> 4], Wls[tc >> 4],
                n0, nmax, tc & 15);
        }
        mma_chunk<NJ>(sb0 + (c % 3)*STG, aoff, boff, acc);
    }
}

template<int NJ>
__device__ __forceinline__ void acc_zero(float (&acc)[2][NJ][4]) {
    #pragma unroll
    for (int mt = 0; mt < 2; mt++)
        #pragma unroll
        for (int j = 0; j < NJ; j++)
            #pragma unroll
            for (int q = 0; q < 4; q++) acc[mt][j][q] = 0.f;
}

template<int NJ>
__device__ __forceinline__ void epi_store(
    float (&acc)[2][NJ][4], float* __restrict__ C, int ldc, int n0,
    const float* __restrict__ bias)
{
    const int lane = threadIdx.x & 31, wid = threadIdx.x >> 5;
    const int g = lane >> 2, tg = lane & 3;
    const int wm = wid >> 1, wn = wid & 1;
    #pragma unroll
    for (int mt = 0; mt < 2; mt++) {
        const int r0 = wm*32 + mt*16 + g, r1 = r0 + 8;
        #pragma unroll
        for (int j = 0; j < NJ; j++) {
            const int c = n0 + wn*NJ*8 + j*8 + 2*tg;
            const float b0 = bias ? bias[c] : 0.f;
            const float b1 = bias ? bias[c+1] : 0.f;
            *reinterpret_cast<float2*>(&C[(size_t)r0*ldc + c]) =
                make_float2(acc[mt][j][0] + b0, acc[mt][j][1] + b1);
            *reinterpret_cast<float2*>(&C[(size_t)r1*ldc + c]) =
                make_float2(acc[mt][j][2] + b0, acc[mt][j][3] + b1);
        }
    }
}

template<int NJ>
__device__ __forceinline__ void epi_atomic(
    float (&acc)[2][NJ][4], float* __restrict__ C, int ldc, int n0)
{
    const int lane = threadIdx.x & 31, wid = threadIdx.x >> 5;
    const int g = lane >> 2, tg = lane & 3;
    const int wm = wid >> 1, wn = wid & 1;
    #pragma unroll
    for (int mt = 0; mt < 2; mt++) {
        const int r0 = wm*32 + mt*16 + g, r1 = r0 + 8;
        #pragma unroll
        for (int j = 0; j < NJ; j++) {
            const int c = n0 + wn*NJ*8 + j*8 + 2*tg;
            atomicAdd(&C[(size_t)r0*ldc + c    ], acc[mt][j][0]);
            atomicAdd(&C[(size_t)r0*ldc + c + 1], acc[mt][j][1]);
            atomicAdd(&C[(size_t)r1*ldc + c    ], acc[mt][j][2]);
            atomicAdd(&C[(size_t)r1*ldc + c + 1], acc[mt][j][3]);
        }
    }
}

// ---------------- prologue kernels ----------------

__global__ void __launch_bounds__(256) kConvAll(
    const float* __restrict__ W_out, const float* __restrict__ W_ih,
    const float* __restrict__ W_hh,  const float* __restrict__ W_y,
    const float* __restrict__ W_h,   const float* __restrict__ W_z,
    const float* __restrict__ W_att_h, const float* __restrict__ W_beta,
    const float* __restrict__ W_att_f, const float* __restrict__ W_init_h,
    const float* __restrict__ W_init_c, const float* __restrict__ ann)
{
    const int z = blockIdx.x, tid = threadIdx.x;
    const float* src; bf16 *dh, *dl; int rs, co, start;
    if      (z < 2500) { src=W_out; dh=w_outh; dl=w_outl; rs=512; co=0;   start=0; }
    else if (z < 3012) { src=W_ih;  dh=w_ihah; dl=w_ihal; rs=1024;co=0;   start=2500; }
    else if (z < 3524) { src=W_ih;  dh=w_ihbh; dl=w_ihbl; rs=1024;co=512; start=3012; }
    else if (z < 4036) { src=W_hh;  dh=w_hhh;  dl=w_hhl;  rs=512; co=0;   start=3524; }
    else if (z < 4164) { src=W_y;   dh=w_yh;   dl=w_yl;   rs=512; co=0;   start=4036; }
    else if (z < 4292) { src=W_h;   dh=w_hh2;  dl=w_hl2;  rs=512; co=0;   start=4164; }
    else if (z < 4420) { src=W_z;   dh=w_zh;   dl=w_zl;   rs=512; co=0;   start=4292; }
    else if (z < 4548) { src=W_att_h; dh=w_atthh; dl=w_atthl; rs=512; co=0; start=4420; }
    else if (z < 4676) { src=W_beta;  dh=w_betah; dl=w_betal; rs=512; co=0; start=4548; }
    else if (z < 4804) { src=W_att_f; dh=w_attfh; dl=w_attfl; rs=512; co=0; start=4676; }
    else if (z < 4932) { src=W_init_h;dh=w_inhh;  dl=w_inhl;  rs=512; co=0; start=4804; }
    else if (z < 5060) { src=W_init_c;dh=w_inch;  dl=w_incl;  rs=512; co=0; start=4932; }
    else if (z < 11332){ src=ann;     dh=s_annh;  dl=s_annl;  rs=512; co=0; start=5060; }
    else {
        const int b = z - 11332;
        for (int f = tid; f < F_; f += 256) {
            const float* p = ann + (size_t)b*L_*F_ + f;
            float s = 0.f;
            #pragma unroll 4
            for (int l = 0; l < L_; l++) s += p[(size_t)l*F_];
            split2(s * (1.f/196.f), s_meanh[b*F_ + f], s_meanl[b*F_ + f]);
        }
        return;
    }
    const int bse = (z - start) * 2048;
    #pragma unroll
    for (int it = 0; it < 8; it++) {
        const int idx = bse + it*256 + tid;
        const int r = idx >> 9, c = idx & 511;
        split2(src[(size_t)r*rs + co + c], dh[idx], dl[idx]);
    }
}

// h0/c0 preact: 16 blocks, NJ=4
__global__ void __launch_bounds__(256) kInitT(
    const float* __restrict__ b_init_h, const float* __restrict__ b_init_c)
{
    const int z = blockIdx.x;
    const int which = z >> 3, n0 = (z & 7) * 64;
    const bf16* Ahs[1] = { s_meanh };
    const bf16* Als[1] = { s_meanl };
    const bf16* Whs[1] = { which ? w_inch : w_inhh };
    const bf16* Wls[1] = { which ? w_incl : w_inhl };
    float acc[2][4][4]; acc_zero<4>(acc);
    core_cp<4>(Ahs, Als, Whs, Wls, 1, n0, 512, acc);
    epi_store<4>(acc, which ? g_c : g_h, 512, n0, which ? b_init_c : b_init_h);
}

__global__ void __launch_bounds__(256) kTanhHC() {
    for (int i = blockIdx.x*256 + threadIdx.x; i < B_*H_; i += 64*256) {
        const float h = tanhf(g_h[i]);
        split2(h, s_hh[i], s_hl[i]);
        g_c[i] = tanhf(g_c[i]);
    }
}

// ann_proj: 196 m-tiles x 4 n-tiles = 784 blocks, NJ=8  (PROFILED at idx 3)
__global__ void __launch_bounds__(256) kAnnProj(const float* __restrict__ b_att_f)
{
    const int z = blockIdx.x;
    const size_t m0 = (size_t)(z >> 2) * 128;
    const int n0 = (z & 3) * 128;
    const bf16* Ahs[1] = { s_annh + m0*K_ };
    const bf16* Als[1] = { s_annl + m0*K_ };
    const bf16* Whs[1] = { w_attfh };
    const bf16* Wls[1] = { w_attfl };
    float acc[2][8][4]; acc_zero<8>(acc);
    core_cp<8>(Ahs, Als, Whs, Wls, 1, n0, 512, acc);
    epi_store<8>(acc, g_annproj + m0*F_, F_, n0, b_att_f);
}

// ---------------- step kernels (4 launches/step) ----------------

// kA: LSTM(t-1) [0,128)  ∪  prep(t) [128,256)
__global__ void __launch_bounds__(256) kA(int t,
    const int* __restrict__ captions, const float* __restrict__ E_emb,
    const float* __restrict__ b_ih, const float* __restrict__ b_hh,
    const int* __restrict__ lengths)
{
    const int z = blockIdx.x, tid = threadIdx.x;
    if (z < 128) {
        if (t == 0) return;
        const int b = z, u = t - 1, su = u & 1;
        int dl = lengths[b] - 1; if (dl < 1) dl = 1;
        const bool act = dl > u;
        const float* gg_ = g_gates[su] + b*2048;
        for (int j = tid; j < 512; j += 256) {
            const float i_ = gg_[j], f_ = gg_[512+j], ggv = gg_[1024+j], o_ = gg_[1536+j];
            const float c_old = g_c[b*H_ + j];
            const float cn = sigf(f_) * c_old + sigf(i_) * tanhf(ggv);
            const float hn = sigf(o_) * tanhf(cn);
            split2(hn, s_hnewh[su][b*H_ + j], s_hnewl[su][b*H_ + j]);
            if (act) {
                g_c[b*H_ + j] = cn;
                split2(hn, s_hh[b*H_ + j], s_hl[b*H_ + j]);
            }
        }
    } else {
        if (t > 30) return;
        const int b = z - 128, s = t & 1;
        const int tok = captions[b*T_ + t];
        for (int j = tid; j < 512; j += 256) {
            split2(E_emb[(size_t)tok*512 + j], s_embh[s][b*512 + j], s_embl[s][b*512 + j]);
            g_pre[s][b*512 + j] = 0.f;
            #pragma unroll
            for (int q = 0; q < 4; q++)
                g_gates[s][b*2048 + q*512 + j] = b_ih[q*512 + j] + b_hh[q*512 + j];
        }
    }
}

// kB: hp/gpre(t) [0,16) direct  ∪  pre-gemm(t-1) [16,40) atomic   (NJ=4)
__global__ void __launch_bounds__(256) kB(int t,
    const float* __restrict__ b_att_h, const float* __restrict__ b_beta)
{
    const int z = blockIdx.x;
    if (z < 16) {
        if (t > 30) return;
        const int which = z >> 3, n0 = (z & 7) * 64;
        const bf16* Ahs[1] = { s_hh };
        const bf16* Als[1] = { s_hl };
        const bf16* Whs[1] = { which ? w_betah : w_atthh };
        const bf16* Wls[1] = { which ? w_betal : w_atthl };
        float acc[2][4][4]; acc_zero<4>(acc);
        core_cp<4>(Ahs, Als, Whs, Wls, 1, n0, 512, acc);
        epi_store<4>(acc, which ? g_gpre : g_hp, 512, n0,
                     which ? b_beta : b_att_h);
    } else {
        if (t == 0) return;
        const int zz = z - 16, seg = zz >> 3, n0 = (zz & 7) * 64;
        const int s = (t-1) & 1;
        const bf16 *Ah, *Al, *Wh, *Wl;
        if      (seg == 0) { Ah=s_embh[s];  Al=s_embl[s];  Wh=w_yh;  Wl=w_yl;  }
        else if (seg == 1) { Ah=s_hnewh[s]; Al=s_hnewl[s]; Wh=w_hh2; Wl=w_hl2; }
        else               { Ah=s_gctxh[s]; Al=s_gctxl[s]; Wh=w_zh;  Wl=w_zl;  }
        const bf16* Ahs[1] = { Ah };
        const bf16* Als[1] = { Al };
        const bf16* Whs[1] = { Wh };
        const bf16* Wls[1] = { Wl };
        float acc[2][4][4]; acc_zero<4>(acc);
        core_cp<4>(Ahs, Als, Whs, Wls, 1, n0, 512, acc);
        epi_atomic<4>(acc, g_pre[s], 512, n0);
    }
}

// kattn: attention(t) [0,128) (512 thr)  ∪  tanh+split pre(t-1) [128,144)
__global__ void __launch_bounds__(512) kattn(
    const float* __restrict__ ann,
    const float* __restrict__ w_att_v,
    const float* __restrict__ b_att_v,
    const int*   __restrict__ lengths,
    int t, float* __restrict__ alphas_out)
{
    if (blockIdx.x >= 128) {
        if (t == 0) return;
        const int s = (t-1) & 1;
        for (int i = (blockIdx.x - 128)*512 + threadIdx.x; i < B_*F_; i += 16*512) {
            const float v = tanhf(g_pre[s][i]);
            split2(v, s_preh[s][i], s_prel[s][i]);
        }
        return;
    }
    if (t > 30) return;

    __shared__ float hp_s[F_];
    __shared__ float wv_s[F_];
    __shared__ float sc[L_];
    __shared__ float red[16];
    __shared__ float sval[2];

    const int b = blockIdx.x;
    const int tid = threadIdx.x;
    const int w = tid >> 5, lane = tid & 31;
    const int s = t & 1;

    if (tid < F_) {
        hp_s[tid] = g_hp[b*F_ + tid];
        wv_s[tid] = w_att_v[tid];
    }
    __syncthreads();

    const float bv = b_att_v[0];
    const float* ap = g_annproj + (size_t)b*L_*F_;

    for (int l = w; l < L_; l += 16) {
        const float* row = ap + (size_t)l*F_;
        float sacc = 0.f;
        #pragma unroll 4
        for (int a = lane; a < F_; a += 32)
            sacc += fmaxf(row[a] + hp_s[a], 0.f) * wv_s[a];
        #pragma unroll
        for (int o = 16; o; o >>= 1) sacc += __shfl_down_sync(0xffffffffu, sacc, o);
        if (lane == 0) sc[l] = sacc + bv;
    }
    __syncthreads();

    float mx = -1e30f;
    if (tid < L_) mx = sc[tid];
    #pragma unroll
    for (int o = 16; o; o >>= 1) mx = fmaxf(mx, __shfl_xor_sync(0xffffffffu, mx, o));
    if (lane == 0) red[w] = mx;
    __syncthreads();
    if (tid == 0) {
        float m = red[0];
        #pragma unroll
        for (int i = 1; i < 16; i++) m = fmaxf(m, red[i]);
        sval[0] = m;
    }
    __syncthreads();
    mx = sval[0];

    float ss = 0.f;
    if (tid < L_) {
        const float e = expf(sc[tid] - mx);
        sc[tid] = e;
        ss = e;
    }
    #pragma unroll
    for (int o = 16; o; o >>= 1) ss += __shfl_xor_sync(0xffffffffu, ss, o);
    if (lane == 0) red[w] = ss;
    __syncthreads();
    if (tid == 0) {
        float s2 = 0.f;
        #pragma unroll
        for (int i = 0; i < 16; i++) s2 += red[i];
        sval[1] = s2;
    }
    __syncthreads();
    const float inv = 1.f / sval[1];

    int dl = lengths[b] - 1; if (dl < 1) dl = 1;
    const bool act = dl > t;
    if (tid < L_) {
        const float a = sc[tid] * inv;
        sc[tid] = a;
        alphas_out[((size_t)b*TD + t)*L_ + tid] = act ? a : 0.f;
    }
    __syncthreads();

    const float* an = ann + (size_t)b*L_*F_;
    const int f = tid;
    float acc = 0.f;
    #pragma unroll 4
    for (int l = 0; l < L_; l++)
        acc = fmaf(sc[l], an[(size_t)l*F_ + f], acc);
    const float gate = sigf(g_gpre[b*F_ + f]);
    split2(gate * acc, s_gctxh[s][b*F_ + f], s_gctxl[s][b*F_ + f]);
}

// kD: gates(t) atomic [0,48)  ∪  logits(t-1) direct [48,127)   (NJ=8)
__global__ void __launch_bounds__(256) kD(int t,
    const float* __restrict__ b_out, const int* __restrict__ lengths,
    float* __restrict__ out)
{
    const int z = blockIdx.x;
    if (z < 48) {
        if (t > 30) return;
        const int s = t & 1;
        const int seg = z >> 4, n0 = (z & 15) * 128;
        const bf16 *Ah, *Al, *Wh, *Wl;
        if      (seg == 0) { Ah=s_embh[s];  Al=s_embl[s];  Wh=w_ihah; Wl=w_ihal; }
        else if (seg == 1) { Ah=s_gctxh[s]; Al=s_gctxl[s]; Wh=w_ihbh; Wl=w_ihbl; }
        else               { Ah=s_hh;       Al=s_hl;       Wh=w_hhh;  Wl=w_hhl;  }
        const bf16* Ahs[1] = { Ah };
        const bf16* Als[1] = { Al };
        const bf16* Whs[1] = { Wh };
        const bf16* Wls[1] = { Wl };
        float acc[2][8][4]; acc_zero<8>(acc);
        core_cp<8>(Ahs, Als, Whs, Wls, 1, n0, 2048, acc);
        epi_atomic<8>(acc, g_gates[s], 2048, n0);
    } else {
        if (t == 0) return;
        const int u = t - 1, s = u & 1;
        const int n0 = (z - 48) * 128;
        const bf16* Ahs[1] = { s_preh[s] };
        const bf16* Als[1] = { s_prel[s] };
        const bf16* Whs[1] = { w_outh };
        const bf16* Wls[1] = { w_outl };
        float acc[2][8][4]; acc_zero<8>(acc);
        core_cp<8>(Ahs, Als, Whs, Wls, 1, n0, V_, acc);

        const int lane = threadIdx.x & 31, wid = threadIdx.x >> 5;
        const int g = lane >> 2, tg = lane & 3;
        const int wm = wid >> 1, wn = wid & 1;
        #pragma unroll
        for (int mt = 0; mt < 2; mt++) {
            const int r0 = wm*32 + mt*16 + g, r1 = r0 + 8;
            int dl0 = lengths[r0] - 1; if (dl0 < 1) dl0 = 1;
            int dl1 = lengths[r1] - 1; if (dl1 < 1) dl1 = 1;
            const bool a0 = dl0 > u, a1 = dl1 > u;
            float* row0 = out + ((size_t)r0*TD + u) * V_;
            float* row1 = out + ((size_t)r1*TD + u) * V_;
            #pragma unroll
            for (int j = 0; j < 8; j++) {
                const int c = n0 + wn*64 + j*8 + 2*tg;
                if (c < V_) {
                    const float b0 = b_out[c], b1 = b_out[c+1];
                    *reinterpret_cast<float2*>(&row0[c]) = a0 ?
                        make_float2(acc[mt][j][0] + b0, acc[mt][j][1] + b1) :
                        make_float2(0.f, 0.f);
                    *reinterpret_cast<float2*>(&row1[c]) = a1 ?
                        make_float2(acc[mt][j][2] + b0, acc[mt][j][3] + b1) :
                        make_float2(0.f, 0.f);
                }
            }
        }
    }
}

__global__ void kdeclen(const int* __restrict__ lengths, float* __restrict__ out)
{
    const int b = threadIdx.x;
    if (b < B_) {
        int dl = lengths[b] - 1; if (dl < 1) dl = 1;
        out[(size_t)LOGITS_SZ + ALPHA_SZ + b] = (float)dl;
    }
}

// ---------------- host launcher ----------------
extern "C" void kernel_launch(void* const* d_in, const int* in_sizes, int n_in,
                              void* d_out, int out_size)
{
    const float* ann      = (const float*)d_in[0];
    const int*   captions = (const int*)  d_in[1];
    const int*   lengths  = (const int*)  d_in[2];
    const float* E_emb    = (const float*)d_in[3];
    const float* W_init_h = (const float*)d_in[4];
    const float* b_init_h = (const float*)d_in[5];
    const float* W_init_c = (const float*)d_in[6];
    const float* b_init_c = (const float*)d_in[7];
    const float* W_att_f  = (const float*)d_in[8];
    const float* b_att_f  = (const float*)d_in[9];
    const float* W_att_h  = (const float*)d_in[10];
    const float* b_att_h  = (const float*)d_in[11];
    const float* w_att_v  = (const float*)d_in[12];
    const float* b_att_v  = (const float*)d_in[13];
    const float* W_beta   = (const float*)d_in[14];
    const float* b_beta   = (const float*)d_in[15];
    const float* W_ih     = (const float*)d_in[16];
    const float* W_hh     = (const float*)d_in[17];
    const float* b_ih     = (const float*)d_in[18];
    const float* b_hh     = (const float*)d_in[19];
    const float* W_y      = (const float*)d_in[20];
    const float* W_h      = (const float*)d_in[21];
    const float* W_z      = (const float*)d_in[22];
    const float* W_out    = (const float*)d_in[23];
    const float* b_out    = (const float*)d_in[24];

    float* out = (float*)d_out;

    const int DSM4 = 3 * (20480 + 4*2560);   // 92160
    const int DSM8 = 3 * (20480 + 8*2560);   // 122880
    cudaFuncSetAttribute(kInitT,   cudaFuncAttributeMaxDynamicSharedMemorySize, DSM4);
    cudaFuncSetAttribute(kAnnProj, cudaFuncAttributeMaxDynamicSharedMemorySize, DSM8);
    cudaFuncSetAttribute(kB,       cudaFuncAttributeMaxDynamicSharedMemorySize, DSM4);
    cudaFuncSetAttribute(kD,       cudaFuncAttributeMaxDynamicSharedMemorySize, DSM8);

    // prologue (kAnnProj at launch index 3 -> profiled)
    kConvAll<<<11460, 256>>>(W_out, W_ih, W_hh, W_y, W_h, W_z,
                             W_att_h, W_beta, W_att_f, W_init_h, W_init_c, ann);
    kInitT<<<16, 256, DSM4>>>(b_init_h, b_init_c);
    kTanhHC<<<64, 256>>>();
    kAnnProj<<<784, 256, DSM8>>>(b_att_f);

    // pipelined decode loop (4 launches/step)
    for (int t = 0; t <= TD; t++) {
        kA<<<256, 256>>>(t, captions, E_emb, b_ih, b_hh, lengths);
        kB<<<40, 256, DSM4>>>(t, b_att_h, b_beta);
        kattn<<<144, 512>>>(ann, w_att_v, b_att_v, lengths, t, out + LOGITS_SZ);
        kD<<<127, 256, DSM8>>>(t, b_out, lengths, out);
    }

    kdeclen<<<1, 128>>>(lengths, out);
}

// round 12
// speedup vs baseline: 2.5069x; 1.0355x over previous
#include <cuda_runtime.h>
#include <cuda_bf16.h>
#include <math.h>
#include <stdint.h>

typedef __nv_bfloat16 bf16;

// ---------------- problem constants ----------------
#define B_  128
#define L_  196
#define T_  32
#define TD  31
#define F_  512
#define H_  512
#define V_  10000
#define K_  512

#define LOGITS_SZ (B_*TD*V_)
#define ALPHA_SZ  (B_*TD*L_)

// GEMM stage: Ah 0 (10240), Al 10240, Wh 20480 (5120), Wl 25600. 3 stages.
#define STG   30720
#define DSMEM (3*STG)     // 92160 -> 2 CTAs/SM fit in 228KB

#if defined(__CUDA_ARCH__) && __CUDA_ARCH__ >= 900
#define GRID_SYNC() cudaGridDependencySynchronize()
#else
#define GRID_SYNC()
#endif

// ---------------- fp32 state ----------------
__device__ float g_h    [B_*H_];
__device__ float g_c    [B_*H_];
__device__ float g_hp   [B_*F_];
__device__ float g_gpre [B_*F_];
__device__ float g_gates[2][B_*2048];
__device__ float g_pre  [2][B_*F_];
__device__ float g_annproj[(size_t)B_*L_*F_];

// ---------------- bf16 hi/lo activations ----------------
__device__ bf16 s_meanh[B_*F_],  s_meanl[B_*F_];
__device__ bf16 s_hh[B_*H_],     s_hl[B_*H_];
__device__ bf16 s_embh [2][B_*F_], s_embl [2][B_*F_];
__device__ bf16 s_gctxh[2][B_*F_], s_gctxl[2][B_*F_];
__device__ bf16 s_hnewh[2][B_*H_], s_hnewl[2][B_*H_];
__device__ bf16 s_preh [2][B_*F_], s_prel [2][B_*F_];
__device__ bf16 s_annh[(size_t)B_*L_*F_], s_annl[(size_t)B_*L_*F_];

// ---------------- bf16 hi/lo weights ----------------
__device__ bf16 w_outh[(size_t)V_*K_], w_outl[(size_t)V_*K_];
__device__ bf16 w_ihah[2048*K_], w_ihal[2048*K_];
__device__ bf16 w_ihbh[2048*K_], w_ihbl[2048*K_];
__device__ bf16 w_hhh [2048*K_], w_hhl [2048*K_];
__device__ bf16 w_yh [512*K_], w_yl [512*K_];
__device__ bf16 w_hh2[512*K_], w_hl2[512*K_];
__device__ bf16 w_zh [512*K_], w_zl [512*K_];
__device__ bf16 w_atthh[512*K_], w_atthl[512*K_];
__device__ bf16 w_betah[512*K_], w_betal[512*K_];
__device__ bf16 w_attfh[512*K_], w_attfl[512*K_];
__device__ bf16 w_inhh[512*K_], w_inhl[512*K_];
__device__ bf16 w_inch[512*K_], w_incl[512*K_];

__device__ __forceinline__ float sigf(float x){ return 1.f/(1.f+expf(-x)); }
__device__ __forceinline__ void split2(float x, bf16& h, bf16& l){
    h = __float2bfloat16(x);
    l = __float2bfloat16(x - __bfloat162float(h));
}
__device__ __forceinline__ uint32_t smem_u32(const void* p){
    uint32_t a;
    asm("{ .reg .u64 t; cvta.to.shared.u64 t, %1; cvt.u32.u64 %0, t; }"
        : "=r"(a) : "l"(p));
    return a;
}

#define MMA16816(d, a, b) asm volatile( \
    "mma.sync.aligned.m16n8k16.row.col.f32.bf16.bf16.f32 " \
    "{%0,%1,%2,%3}, {%4,%5,%6,%7}, {%8,%9}, {%0,%1,%2,%3};" \
    : "+f"(d[0]), "+f"(d[1]), "+f"(d[2]), "+f"(d[3]) \
    : "r"(a[0]), "r"(a[1]), "r"(a[2]), "r"(a[3]), "r"(b[0]), "r"(b[1]))

#define LDSM4(r0, r1, r2, r3, addr) asm volatile( \
    "ldmatrix.sync.aligned.m8n8.x4.shared.b16 {%0,%1,%2,%3}, [%4];" \
    : "=r"(r0), "=r"(r1), "=r"(r2), "=r"(r3) : "r"(addr))

// ---------------- NJ=4 cp.async + ldmatrix HMMA core ----------------
// Block 256 thr / 8 warps (4m x 2n), out 128(m) x 64(n), KC=32, K=512/seg.
// acc = Ah*Wh + Al*Wh + Ah*Wl. 3 stages, 1 sync/chunk. 2 CTAs/SM.

__device__ __forceinline__ void load_stage(
    char* st, const bf16* __restrict__ Ah, const bf16* __restrict__ Al,
    const bf16* __restrict__ Wh, const bf16* __restrict__ Wl,
    int n0, int nmax, int ch)
{
    const int tid = threadIdx.x;
    #pragma unroll
    for (int i = 0; i < 6; i++) {
        const int idx = i*256 + tid;
        const bf16* src; uint32_t dst;
        if (idx < 1024) {
            const int half = idx >> 9;
            const int rr = (idx >> 2) & 127, q = idx & 3;
            src = (half ? Al : Ah) + (size_t)rr*K_ + ch*32 + q*8;
            dst = smem_u32(st + half*10240 + rr*80 + q*16);
        } else {
            const int w = idx - 1024;            // 0..511
            const int half = w >> 8;
            const int ww = w & 255;
            const int rr = ww >> 2, q = ww & 3;
            int row = n0 + rr; if (row >= nmax) row = nmax - 1;
            src = (half ? Wl : Wh) + (size_t)row*K_ + ch*32 + q*8;
            dst = smem_u32(st + 20480 + half*5120 + rr*80 + q*16);
        }
        asm volatile("cp.async.cg.shared.global [%0], [%1], 16;"
                     :: "r"(dst), "l"((uint64_t)__cvta_generic_to_global(src))
                     : "memory");
    }
    asm volatile("cp.async.commit_group;" ::: "memory");
}

__device__ __forceinline__ void mma_chunk(
    uint32_t sb, uint32_t aoff, uint32_t boff, float (&acc)[2][4][4])
{
    #pragma unroll
    for (int ks = 0; ks < 2; ks++) {
        const uint32_t ko = ks*32;
        unsigned ah[2][4], al[2][4], bh[4][2], bl[4][2];
        #pragma unroll
        for (int mt = 0; mt < 2; mt++) {
            LDSM4(ah[mt][0], ah[mt][1], ah[mt][2], ah[mt][3],
                  sb + aoff + mt*1280 + ko);
            LDSM4(al[mt][0], al[mt][1], al[mt][2], al[mt][3],
                  sb + 10240 + aoff + mt*1280 + ko);
        }
        #pragma unroll
        for (int jp = 0; jp < 2; jp++) {
            LDSM4(bh[2*jp][0], bh[2*jp][1], bh[2*jp+1][0], bh[2*jp+1][1],
                  sb + boff + jp*1280 + ko);
            LDSM4(bl[2*jp][0], bl[2*jp][1], bl[2*jp+1][0], bl[2*jp+1][1],
                  sb + boff + 5120 + jp*1280 + ko);
        }
        #pragma unroll
        for (int mt = 0; mt < 2; mt++)
            #pragma unroll
            for (int j = 0; j < 4; j++) MMA16816(acc[mt][j], ah[mt], bh[j]);
        #pragma unroll
        for (int mt = 0; mt < 2; mt++)
            #pragma unroll
            for (int j = 0; j < 4; j++) MMA16816(acc[mt][j], al[mt], bh[j]);
        #pragma unroll
        for (int mt = 0; mt < 2; mt++)
            #pragma unroll
            for (int j = 0; j < 4; j++) MMA16816(acc[mt][j], ah[mt], bl[j]);
    }
}

__device__ __forceinline__ void core_cp(
    const bf16* __restrict__ Ah, const bf16* __restrict__ Al,
    const bf16* __restrict__ Wh, const bf16* __restrict__ Wl,
    int n0, int nmax, float (&acc)[2][4][4])
{
    extern __shared__ char dynsm[];
    const int tid = threadIdx.x;
    const int wid = tid >> 5, lane = tid & 31;
    const int wm = wid >> 1, wn = wid & 1;
    const uint32_t sb0 = smem_u32(dynsm);
    const uint32_t aoff = (uint32_t)((wm*32 + (lane & 15))*80 + ((lane >> 4) & 1)*16);
    const uint32_t boff = (uint32_t)(20480 +
        (wn*32 + ((lane >> 4) & 1)*8 + (lane & 7))*80 + ((lane >> 3) & 1)*16);

    load_stage(dynsm,       Ah, Al, Wh, Wl, n0, nmax, 0);
    load_stage(dynsm + STG, Ah, Al, Wh, Wl, n0, nmax, 1);

    for (int c = 0; c < 16; c++) {
        if (c < 15) asm volatile("cp.async.wait_group 1;" ::: "memory");
        else        asm volatile("cp.async.wait_group 0;" ::: "memory");
        __syncthreads();
        if (c < 14)
            load_stage(dynsm + ((c + 2) % 3)*STG, Ah, Al, Wh, Wl, n0, nmax, c + 2);
        mma_chunk(sb0 + (c % 3)*STG, aoff, boff, acc);
    }
}

__device__ __forceinline__ void acc_zero(float (&acc)[2][4][4]) {
    #pragma unroll
    for (int mt = 0; mt < 2; mt++)
        #pragma unroll
        for (int j = 0; j < 4; j++)
            #pragma unroll
            for (int q = 0; q < 4; q++) acc[mt][j][q] = 0.f;
}

__device__ __forceinline__ void epi_store(
    float (&acc)[2][4][4], float* __restrict__ C, int ldc, int n0,
    const float* __restrict__ bias)
{
    const int lane = threadIdx.x & 31, wid = threadIdx.x >> 5;
    const int g = lane >> 2, tg = lane & 3;
    const int wm = wid >> 1, wn = wid & 1;
    #pragma unroll
    for (int mt = 0; mt < 2; mt++) {
        const int r0 = wm*32 + mt*16 + g, r1 = r0 + 8;
        #pragma unroll
        for (int j = 0; j < 4; j++) {
            const int c = n0 + wn*32 + j*8 + 2*tg;
            const float b0 = bias ? bias[c] : 0.f;
            const float b1 = bias ? bias[c+1] : 0.f;
            *reinterpret_cast<float2*>(&C[(size_t)r0*ldc + c]) =
                make_float2(acc[mt][j][0] + b0, acc[mt][j][1] + b1);
            *reinterpret_cast<float2*>(&C[(size_t)r1*ldc + c]) =
                make_float2(acc[mt][j][2] + b0, acc[mt][j][3] + b1);
        }
    }
}

__device__ __forceinline__ void epi_atomic(
    float (&acc)[2][4][4], float* __restrict__ C, int ldc, int n0)
{
    const int lane = threadIdx.x & 31, wid = threadIdx.x >> 5;
    const int g = lane >> 2, tg = lane & 3;
    const int wm = wid >> 1, wn = wid & 1;
    #pragma unroll
    for (int mt = 0; mt < 2; mt++) {
        const int r0 = wm*32 + mt*16 + g, r1 = r0 + 8;
        #pragma unroll
        for (int j = 0; j < 4; j++) {
            const int c = n0 + wn*32 + j*8 + 2*tg;
            atomicAdd(&C[(size_t)r0*ldc + c    ], acc[mt][j][0]);
            atomicAdd(&C[(size_t)r0*ldc + c + 1], acc[mt][j][1]);
            atomicAdd(&C[(size_t)r1*ldc + c    ], acc[mt][j][2]);
            atomicAdd(&C[(size_t)r1*ldc + c + 1], acc[mt][j][3]);
        }
    }
}

// ---------------- prologue kernels ----------------

__global__ void __launch_bounds__(256) kConvAll(
    const float* __restrict__ W_out, const float* __restrict__ W_ih,
    const float* __restrict__ W_hh,  const float* __restrict__ W_y,
    const float* __restrict__ W_h,   const float* __restrict__ W_z,
    const float* __restrict__ W_att_h, const float* __restrict__ W_beta,
    const float* __restrict__ W_att_f, const float* __restrict__ W_init_h,
    const float* __restrict__ W_init_c, const float* __restrict__ ann)
{
    const int z = blockIdx.x, tid = threadIdx.x;
    const float* src; bf16 *dh, *dl; int rs, co, start;
    if      (z < 2500) { src=W_out; dh=w_outh; dl=w_outl; rs=512; co=0;   start=0; }
    else if (z < 3012) { src=W_ih;  dh=w_ihah; dl=w_ihal; rs=1024;co=0;   start=2500; }
    else if (z < 3524) { src=W_ih;  dh=w_ihbh; dl=w_ihbl; rs=1024;co=512; start=3012; }
    else if (z < 4036) { src=W_hh;  dh=w_hhh;  dl=w_hhl;  rs=512; co=0;   start=3524; }
    else if (z < 4164) { src=W_y;   dh=w_yh;   dl=w_yl;   rs=512; co=0;   start=4036; }
    else if (z < 4292) { src=W_h;   dh=w_hh2;  dl=w_hl2;  rs=512; co=0;   start=4164; }
    else if (z < 4420) { src=W_z;   dh=w_zh;   dl=w_zl;   rs=512; co=0;   start=4292; }
    else if (z < 4548) { src=W_att_h; dh=w_atthh; dl=w_atthl; rs=512; co=0; start=4420; }
    else if (z < 4676) { src=W_beta;  dh=w_betah; dl=w_betal; rs=512; co=0; start=4548; }
    else if (z < 4804) { src=W_att_f; dh=w_attfh; dl=w_attfl; rs=512; co=0; start=4676; }
    else if (z < 4932) { src=W_init_h;dh=w_inhh;  dl=w_inhl;  rs=512; co=0; start=4804; }
    else if (z < 5060) { src=W_init_c;dh=w_inch;  dl=w_incl;  rs=512; co=0; start=4932; }
    else if (z < 11332){ src=ann;     dh=s_annh;  dl=s_annl;  rs=512; co=0; start=5060; }
    else {
        const int b = z - 11332;
        for (int f = tid; f < F_; f += 256) {
            const float* p = ann + (size_t)b*L_*F_ + f;
            float s = 0.f;
            #pragma unroll 4
            for (int l = 0; l < L_; l++) s += p[(size_t)l*F_];
            split2(s * (1.f/196.f), s_meanh[b*F_ + f], s_meanl[b*F_ + f]);
        }
        return;
    }
    const int bse = (z - start) * 2048;
    #pragma unroll
    for (int it = 0; it < 8; it++) {
        const int idx = bse + it*256 + tid;
        const int r = idx >> 9, c = idx & 511;
        split2(src[(size_t)r*rs + co + c], dh[idx], dl[idx]);
    }
}

// h0/c0 preact: 16 blocks
__global__ void __launch_bounds__(256, 2) kInitT(
    const float* __restrict__ b_init_h, const float* __restrict__ b_init_c)
{
    GRID_SYNC();
    const int z = blockIdx.x;
    const int which = z >> 3, n0 = (z & 7) * 64;
    float acc[2][4][4]; acc_zero(acc);
    core_cp(s_meanh, s_meanl,
            which ? w_inch : w_inhh, which ? w_incl : w_inhl, n0, 512, acc);
    epi_store(acc, which ? g_c : g_h, 512, n0, which ? b_init_c : b_init_h);
}

__global__ void __launch_bounds__(256) kTanhHC() {
    GRID_SYNC();
    for (int i = blockIdx.x*256 + threadIdx.x; i < B_*H_; i += 64*256) {
        const float h = tanhf(g_h[i]);
        split2(h, s_hh[i], s_hl[i]);
        g_c[i] = tanhf(g_c[i]);
    }
}

// ann_proj: 196 m-tiles x 8 n-tiles = 1568 blocks (PROFILED at idx 3)
__global__ void __launch_bounds__(256, 2) kAnnProj(const float* __restrict__ b_att_f)
{
    GRID_SYNC();
    const int z = blockIdx.x;
    const size_t m0 = (size_t)(z >> 3) * 128;
    const int n0 = (z & 7) * 64;
    float acc[2][4][4]; acc_zero(acc);
    core_cp(s_annh + m0*K_, s_annl + m0*K_, w_attfh, w_attfl, n0, 512, acc);
    epi_store(acc, g_annproj + m0*F_, F_, n0, b_att_f);
}

// ---------------- step kernels (4 launches/step) ----------------

// kA: LSTM(t-1) [0,128)  ∪  prep(t) [128,256)
__global__ void __launch_bounds__(256) kA(int t,
    const int* __restrict__ captions, const float* __restrict__ E_emb,
    const float* __restrict__ b_ih, const float* __restrict__ b_hh,
    const int* __restrict__ lengths)
{
    GRID_SYNC();
    const int z = blockIdx.x, tid = threadIdx.x;
    if (z < 128) {
        if (t == 0) return;
        const int b = z, u = t - 1, su = u & 1;
        int dl = lengths[b] - 1; if (dl < 1) dl = 1;
        const bool act = dl > u;
        const float* gg_ = g_gates[su] + b*2048;
        for (int j = tid; j < 512; j += 256) {
            const float i_ = gg_[j], f_ = gg_[512+j], ggv = gg_[1024+j], o_ = gg_[1536+j];
            const float c_old = g_c[b*H_ + j];
            const float cn = sigf(f_) * c_old + sigf(i_) * tanhf(ggv);
            const float hn = sigf(o_) * tanhf(cn);
            split2(hn, s_hnewh[su][b*H_ + j], s_hnewl[su][b*H_ + j]);
            if (act) {
                g_c[b*H_ + j] = cn;
                split2(hn, s_hh[b*H_ + j], s_hl[b*H_ + j]);
            }
        }
    } else {
        if (t > 30) return;
        const int b = z - 128, s = t & 1;
        const int tok = captions[b*T_ + t];
        for (int j = tid; j < 512; j += 256) {
            split2(E_emb[(size_t)tok*512 + j], s_embh[s][b*512 + j], s_embl[s][b*512 + j]);
            g_pre[s][b*512 + j] = 0.f;
            #pragma unroll
            for (int q = 0; q < 4; q++)
                g_gates[s][b*2048 + q*512 + j] = b_ih[q*512 + j] + b_hh[q*512 + j];
        }
    }
}

// kB: hp/gpre(t) [0,16) direct  ∪  pre-gemm(t-1) [16,40) atomic
__global__ void __launch_bounds__(256, 2) kB(int t,
    const float* __restrict__ b_att_h, const float* __restrict__ b_beta)
{
    GRID_SYNC();
    const int z = blockIdx.x;
    if (z < 16) {
        if (t > 30) return;
        const int which = z >> 3, n0 = (z & 7) * 64;
        float acc[2][4][4]; acc_zero(acc);
        core_cp(s_hh, s_hl,
                which ? w_betah : w_atthh, which ? w_betal : w_atthl,
                n0, 512, acc);
        epi_store(acc, which ? g_gpre : g_hp, 512, n0,
                  which ? b_beta : b_att_h);
    } else {
        if (t == 0) return;
        const int zz = z - 16, seg = zz >> 3, n0 = (zz & 7) * 64;
        const int s = (t-1) & 1;
        const bf16 *Ah, *Al, *Wh, *Wl;
        if      (seg == 0) { Ah=s_embh[s];  Al=s_embl[s];  Wh=w_yh;  Wl=w_yl;  }
        else if (seg == 1) { Ah=s_hnewh[s]; Al=s_hnewl[s]; Wh=w_hh2; Wl=w_hl2; }
        else               { Ah=s_gctxh[s]; Al=s_gctxl[s]; Wh=w_zh;  Wl=w_zl;  }
        float acc[2][4][4]; acc_zero(acc);
        core_cp(Ah, Al, Wh, Wl, n0, 512, acc);
        epi_atomic(acc, g_pre[s], 512, n0);
    }
}

// kattn: attention(t) [0,128) (512 thr)  ∪  tanh+split pre(t-1) [128,144)
__global__ void __launch_bounds__(512) kattn(
    const float* __restrict__ ann,
    const float* __restrict__ w_att_v,
    const float* __restrict__ b_att_v,
    const int*   __restrict__ lengths,
    int t, float* __restrict__ alphas_out)
{
    GRID_SYNC();
    if (blockIdx.x >= 128) {
        if (t == 0) return;
        const int s = (t-1) & 1;
        for (int i = (blockIdx.x - 128)*512 + threadIdx.x; i < B_*F_; i += 16*512) {
            const float v = tanhf(g_pre[s][i]);
            split2(v, s_preh[s][i], s_prel[s][i]);
        }
        return;
    }
    if (t > 30) return;

    __shared__ float hp_s[F_];
    __shared__ float wv_s[F_];
    __shared__ float sc[L_];
    __shared__ float red[16];
    __shared__ float sval[2];

    const int b = blockIdx.x;
    const int tid = threadIdx.x;
    const int w = tid >> 5, lane = tid & 31;
    const int s = t & 1;

    if (tid < F_) {
        hp_s[tid] = g_hp[b*F_ + tid];
        wv_s[tid] = w_att_v[tid];
    }
    __syncthreads();

    const float bv = b_att_v[0];
    const float* ap = g_annproj + (size_t)b*L_*F_;

    for (int l = w; l < L_; l += 16) {
        const float* row = ap + (size_t)l*F_;
        float sacc = 0.f;
        #pragma unroll 4
        for (int a = lane; a < F_; a += 32)
            sacc += fmaxf(row[a] + hp_s[a], 0.f) * wv_s[a];
        #pragma unroll
        for (int o = 16; o; o >>= 1) sacc += __shfl_down_sync(0xffffffffu, sacc, o);
        if (lane == 0) sc[l] = sacc + bv;
    }
    __syncthreads();

    float mx = -1e30f;
    if (tid < L_) mx = sc[tid];
    #pragma unroll
    for (int o = 16; o; o >>= 1) mx = fmaxf(mx, __shfl_xor_sync(0xffffffffu, mx, o));
    if (lane == 0) red[w] = mx;
    __syncthreads();
    if (tid == 0) {
        float m = red[0];
        #pragma unroll
        for (int i = 1; i < 16; i++) m = fmaxf(m, red[i]);
        sval[0] = m;
    }
    __syncthreads();
    mx = sval[0];

    float ss = 0.f;
    if (tid < L_) {
        const float e = expf(sc[tid] - mx);
        sc[tid] = e;
        ss = e;
    }
    #pragma unroll
    for (int o = 16; o; o >>= 1) ss += __shfl_xor_sync(0xffffffffu, ss, o);
    if (lane == 0) red[w] = ss;
    __syncthreads();
    if (tid == 0) {
        float s2 = 0.f;
        #pragma unroll
        for (int i = 0; i < 16; i++) s2 += red[i];
        sval[1] = s2;
    }
    __syncthreads();
    const float inv = 1.f / sval[1];

    int dl = lengths[b] - 1; if (dl < 1) dl = 1;
    const bool act = dl > t;
    if (tid < L_) {
        const float a = sc[tid] * inv;
        sc[tid] = a;
        alphas_out[((size_t)b*TD + t)*L_ + tid] = act ? a : 0.f;
    }
    __syncthreads();

    const float* an = ann + (size_t)b*L_*F_;
    const int f = tid;
    float acc = 0.f;
    #pragma unroll 4
    for (int l = 0; l < L_; l++)
        acc = fmaf(sc[l], an[(size_t)l*F_ + f], acc);
    const float gate = sigf(g_gpre[b*F_ + f]);
    split2(gate * acc, s_gctxh[s][b*F_ + f], s_gctxl[s][b*F_ + f]);
}

// kD: gates(t) atomic [0,96)  ∪  logits(t-1) direct [96,253)
__global__ void __launch_bounds__(256, 2) kD(int t,
    const float* __restrict__ b_out, const int* __restrict__ lengths,
    float* __restrict__ out)
{
    GRID_SYNC();
    const int z = blockIdx.x;
    if (z < 96) {
        if (t > 30) return;
        const int s = t & 1;
        const int seg = z >> 5, n0 = (z & 31) * 64;
        const bf16 *Ah, *Al, *Wh, *Wl;
        if      (seg == 0) { Ah=s_embh[s];  Al=s_embl[s];  Wh=w_ihah; Wl=w_ihal; }
        else if (seg == 1) { Ah=s_gctxh[s]; Al=s_gctxl[s]; Wh=w_ihbh; Wl=w_ihbl; }
        else               { Ah=s_hh;       Al=s_hl;       Wh=w_hhh;  Wl=w_hhl;  }
        float acc[2][4][4]; acc_zero(acc);
        core_cp(Ah, Al, Wh, Wl, n0, 2048, acc);
        epi_atomic(acc, g_gates[s], 2048, n0);
    } else {
        if (t == 0) return;
        const int u = t - 1, s = u & 1;
        const int n0 = (z - 96) * 64;
        float acc[2][4][4]; acc_zero(acc);
        core_cp(s_preh[s], s_prel[s], w_outh, w_outl, n0, V_, acc);

        const int lane = threadIdx.x & 31, wid = threadIdx.x >> 5;
        const int g = lane >> 2, tg = lane & 3;
        const int wm = wid >> 1, wn = wid & 1;
        #pragma unroll
        for (int mt = 0; mt < 2; mt++) {
            const int r0 = wm*32 + mt*16 + g, r1 = r0 + 8;
            int dl0 = lengths[r0] - 1; if (dl0 < 1) dl0 = 1;
            int dl1 = lengths[r1] - 1; if (dl1 < 1) dl1 = 1;
            const bool a0 = dl0 > u, a1 = dl1 > u;
            float* row0 = out + ((size_t)r0*TD + u) * V_;
            float* row1 = out + ((size_t)r1*TD + u) * V_;
            #pragma unroll
            for (int j = 0; j < 4; j++) {
                const int c = n0 + wn*32 + j*8 + 2*tg;
                if (c < V_) {
                    const float b0 = b_out[c], b1 = b_out[c+1];
                    *reinterpret_cast<float2*>(&row0[c]) = a0 ?
                        make_float2(acc[mt][j][0] + b0, acc[mt][j][1] + b1) :
                        make_float2(0.f, 0.f);
                    *reinterpret_cast<float2*>(&row1[c]) = a1 ?
                        make_float2(acc[mt][j][2] + b0, acc[mt][j][3] + b1) :
                        make_float2(0.f, 0.f);
                }
            }
        }
    }
}

__global__ void kdeclen(const int* __restrict__ lengths, float* __restrict__ out)
{
    GRID_SYNC();
    const int b = threadIdx.x;
    if (b < B_) {
        int dl = lengths[b] - 1; if (dl < 1) dl = 1;
        out[(size_t)LOGITS_SZ + ALPHA_SZ + b] = (float)dl;
    }
}

// ---------------- host launcher ----------------

template<typename... EA, typename... AA>
static void pdl(int grid, int block, size_t smem, void (*kern)(EA...), AA... args)
{
    cudaLaunchAttribute at[1];
    at[0].id = cudaLaunchAttributeProgrammaticStreamSerialization;
    at[0].val.programmaticStreamSerializationAllowed = 1;
    cudaLaunchConfig_t cfg;
    cfg.gridDim = dim3(grid);
    cfg.blockDim = dim3(block);
    cfg.dynamicSmemBytes = smem;
    cfg.stream = 0;
    cfg.attrs = at;
    cfg.numAttrs = 1;
    cudaLaunchKernelEx(&cfg, kern, args...);
}

extern "C" void kernel_launch(void* const* d_in, const int* in_sizes, int n_in,
                              void* d_out, int out_size)
{
    const float* ann      = (const float*)d_in[0];
    const int*   captions = (const int*)  d_in[1];
    const int*   lengths  = (const int*)  d_in[2];
    const float* E_emb    = (const float*)d_in[3];
    const float* W_init_h = (const float*)d_in[4];
    const float* b_init_h = (const float*)d_in[5];
    const float* W_init_c = (const float*)d_in[6];
    const float* b_init_c = (const float*)d_in[7];
    const float* W_att_f  = (const float*)d_in[8];
    const float* b_att_f  = (const float*)d_in[9];
    const float* W_att_h  = (const float*)d_in[10];
    const float* b_att_h  = (const float*)d_in[11];
    const float* w_att_v  = (const float*)d_in[12];
    const float* b_att_v  = (const float*)d_in[13];
    const float* W_beta   = (const float*)d_in[14];
    const float* b_beta   = (const float*)d_in[15];
    const float* W_ih     = (const float*)d_in[16];
    const float* W_hh     = (const float*)d_in[17];
    const float* b_ih     = (const float*)d_in[18];
    const float* b_hh     = (const float*)d_in[19];
    const float* W_y      = (const float*)d_in[20];
    const float* W_h      = (const float*)d_in[21];
    const float* W_z      = (const float*)d_in[22];
    const float* W_out    = (const float*)d_in[23];
    const float* b_out    = (const float*)d_in[24];

    float* out = (float*)d_out;

    cudaFuncSetAttribute(kInitT,   cudaFuncAttributeMaxDynamicSharedMemorySize, DSMEM);
    cudaFuncSetAttribute(kAnnProj, cudaFuncAttributeMaxDynamicSharedMemorySize, DSMEM);
    cudaFuncSetAttribute(kB,       cudaFuncAttributeMaxDynamicSharedMemorySize, DSMEM);
    cudaFuncSetAttribute(kD,       cudaFuncAttributeMaxDynamicSharedMemorySize, DSMEM);

    // prologue (kAnnProj at launch index 3 -> profiled)
    kConvAll<<<11460, 256>>>(W_out, W_ih, W_hh, W_y, W_h, W_z,
                             W_att_h, W_beta, W_att_f, W_init_h, W_init_c, ann);
    pdl(16, 256, (size_t)DSMEM, kInitT, b_init_h, b_init_c);
    pdl(64, 256, (size_t)0, kTanhHC);
    pdl(1568, 256, (size_t)DSMEM, kAnnProj, b_att_f);

    // pipelined decode loop (4 launches/step)
    for (int t = 0; t <= TD; t++) {
        pdl(256, 256, (size_t)0, kA, t, captions, E_emb, b_ih, b_hh, lengths);
        pdl(40, 256, (size_t)DSMEM, kB, t, b_att_h, b_beta);
        pdl(144, 512, (size_t)0, kattn, ann, w_att_v, b_att_v, lengths, t,
            out + LOGITS_SZ);
        pdl(253, 256, (size_t)DSMEM, kD, t, b_out, lengths, out);
    }

    pdl(1, 128, (size_t)0, kdeclen, lengths, out);
}